// round 8
// baseline (speedup 1.0000x reference)
#include <cuda_runtime.h>
#include <cuda_bf16.h>
#include <math.h>

#define Bn   2
#define Tn   2048
#define Cn   1024
#define Hn   16
#define HDn  64
#define BTn  (Bn*Tn)
#define QMAXF 127.0f
#define C3   3072
#define QW   36        // padded words per row in attn smem

// ---------------- scratch ----------------
__device__ int   g_qa [BTn*256];
__device__ float g_sa [32*BTn];
__device__ int   g_qw1[3*Cn*256];
__device__ float g_sw1[32*3*Cn];
__device__ int   g_qw2[Cn*256];
__device__ float g_sw2[32*Cn];
__device__ float g_qkv[(size_t)BTn*C3];
__device__ int   g_qy [BTn*256];
__device__ float g_sy [32*BTn];
__device__ float g_proj[(size_t)BTn*Cn];
// precomputed bf16 hi/lo K and transposed V, per (b,h): 65536 words each
__device__ unsigned gKH[Bn*Hn*65536], gKL[Bn*Hn*65536];
__device__ unsigned gVH[Bn*Hn*65536], gVL[Bn*Hn*65536];

__device__ __forceinline__ float warp_sum(float v){
#pragma unroll
    for (int o=16;o;o>>=1) v += __shfl_xor_sync(0xffffffffu, v, o);
    return v;
}
__device__ __forceinline__ float max8(float v){
#pragma unroll
    for (int o=4;o;o>>=1) v = fmaxf(v, __shfl_xor_sync(0xffffffffu, v, o));
    return v;
}
__device__ __forceinline__ int pack4(float a, float b, float c, float d){
    int i0=(int)a, i1=(int)b, i2=(int)c, i3=(int)d;
    return (i0&0xFF) | ((i1&0xFF)<<8) | ((i2&0xFF)<<16) | (i3<<24);
}
__device__ __forceinline__ float qclamp(float h, float inv_s){
    float q = rintf(h * inv_s);
    return fminf(fmaxf(q, -QMAXF), QMAXF);
}
__device__ __forceinline__ float ex2f(float x){
    float y; asm("ex2.approx.f32 %0, %1;" : "=f"(y) : "f"(x)); return y;
}
__device__ __forceinline__ unsigned pbf2(float x, float y){
    __nv_bfloat162 h = __floats2bfloat162_rn(x, y);
    return *(unsigned*)&h;
}
__device__ __forceinline__ void split2(float x, float y, unsigned &hi, unsigned &lo){
    unsigned h = pbf2(x, y);
    __nv_bfloat162 hb = *(__nv_bfloat162*)&h;
    hi = h;
    lo = pbf2(x - __bfloat162float(hb.x), y - __bfloat162float(hb.y));
}
__device__ __forceinline__ void mma16816(float* d, const unsigned* a, unsigned b0, unsigned b1){
    asm volatile("mma.sync.aligned.m16n8k16.row.col.f32.bf16.bf16.f32 "
        "{%0,%1,%2,%3},{%4,%5,%6,%7},{%8,%9},{%0,%1,%2,%3};"
        : "+f"(d[0]),"+f"(d[1]),"+f"(d[2]),"+f"(d[3])
        : "r"(a[0]),"r"(a[1]),"r"(a[2]),"r"(a[3]), "r"(b0),"r"(b1));
}
// IMMA with magic-bias initial accumulator: d comes out pre-biased for f32 reinterpretation
__device__ __forceinline__ void imma16832m(int* d, const unsigned* a, unsigned b0, unsigned b1){
    asm volatile("mma.sync.aligned.m16n8k32.row.col.s32.s8.s8.s32 "
        "{%0,%1,%2,%3},{%4,%5,%6,%7},{%8,%9},{%10,%11,%12,%13};"
        : "=r"(d[0]),"=r"(d[1]),"=r"(d[2]),"=r"(d[3])
        : "r"(a[0]),"r"(a[1]),"r"(a[2]),"r"(a[3]), "r"(b0),"r"(b1),
          "r"(0x4B400000),"r"(0x4B400000),"r"(0x4B400000),"r"(0x4B400000));
}
__device__ __forceinline__ void ldm_x4(unsigned* r, const void* p){
    unsigned ad = (unsigned)__cvta_generic_to_shared(p);
    asm volatile("ldmatrix.sync.aligned.m8n8.x4.shared.b16 {%0,%1,%2,%3}, [%4];"
        : "=r"(r[0]),"=r"(r[1]),"=r"(r[2]),"=r"(r[3]) : "r"(ad));
}
// packed f32x2 helpers
__device__ __forceinline__ unsigned long long packf2(float x, float y){
    unsigned long long r; asm("mov.b64 %0, {%1,%2};" : "=l"(r) : "f"(x),"f"(y)); return r;
}
__device__ __forceinline__ unsigned long long pack2i(int x, int y){
    unsigned long long r; asm("mov.b64 %0, {%1,%2};" : "=l"(r) : "r"(x),"r"(y)); return r;
}
__device__ __forceinline__ void unpackf2(unsigned long long v, float &x, float &y){
    asm("mov.b64 {%0,%1}, %2;" : "=f"(x),"=f"(y) : "l"(v));
}
__device__ __forceinline__ unsigned long long addf2(unsigned long long a, unsigned long long b){
    unsigned long long r; asm("add.rn.f32x2 %0, %1, %2;" : "=l"(r) : "l"(a),"l"(b)); return r;
}
__device__ __forceinline__ unsigned long long mulf2(unsigned long long a, unsigned long long b){
    unsigned long long r; asm("mul.rn.f32x2 %0, %1, %2;" : "=l"(r) : "l"(a),"l"(b)); return r;
}
__device__ __forceinline__ unsigned long long fmaf2(unsigned long long a, unsigned long long b, unsigned long long c){
    unsigned long long r; asm("fma.rn.f32x2 %0, %1, %2, %3;" : "=l"(r) : "l"(a),"l"(b),"l"(c)); return r;
}
// cp.async
__device__ __forceinline__ void cpa16(void* dst, const void* src){
    unsigned d = (unsigned)__cvta_generic_to_shared(dst);
    asm volatile("cp.async.cg.shared.global [%0], [%1], 16;" :: "r"(d), "l"(src));
}
__device__ __forceinline__ void cpa4(void* dst, const void* src){
    unsigned d = (unsigned)__cvta_generic_to_shared(dst);
    asm volatile("cp.async.ca.shared.global [%0], [%1], 4;" :: "r"(d), "l"(src));
}
#define CP_COMMIT() asm volatile("cp.async.commit_group;")
#define CP_WAIT0()  asm volatile("cp.async.wait_group 0;")
#define CP_WAIT1()  asm volatile("cp.async.wait_group 1;")

// ---------------- kernel 1: fused prepass (LN quant + w1 quant + w2 quant) ----------------
__global__ void prepass(const int* __restrict__ qx, const float* __restrict__ sx,
                        const float* __restrict__ meanp, const float* __restrict__ rstdp,
                        const float* __restrict__ lnw,
                        const float* __restrict__ w1, const float* __restrict__ w2){
    int bid = blockIdx.x, t = threadIdx.x;
    int c0 = t << 2;
    if (bid < BTn){
        int r = bid;
        int4 qv = *(const int4*)(qx + r*Cn + c0);
        float sxv = sx[r*32 + (c0 >> 5)];
        float mu = meanp[r], rs = rstdp[r];
        float4 wv = *(const float4*)(lnw + c0);
        float h0 = ((float)qv.x * sxv - mu) * rs * wv.x;
        float h1 = ((float)qv.y * sxv - mu) * rs * wv.y;
        float h2 = ((float)qv.z * sxv - mu) * rs * wv.z;
        float h3 = ((float)qv.w * sxv - mu) * rs * wv.w;
        float m = max8(fmaxf(fmaxf(fabsf(h0),fabsf(h1)), fmaxf(fabsf(h2),fabsf(h3))));
        float s = fmaxf(m * (1.0f/QMAXF), 1e-8f);
        float inv = 1.0f / s;
        g_qa[r*256 + t] = pack4(qclamp(h0,inv), qclamp(h1,inv), qclamp(h2,inv), qclamp(h3,inv));
        if ((t & 7) == 0) g_sa[(t>>3)*BTn + r] = s;
    } else {
        const float* w; int* qo; float* so; int r, nrows;
        if (bid < BTn + C3){ w = w1; qo = g_qw1; so = g_sw1; r = bid - BTn; nrows = C3; }
        else               { w = w2; qo = g_qw2; so = g_sw2; r = bid - BTn - C3; nrows = Cn; }
        float4 wv = *(const float4*)(w + (size_t)r*Cn + c0);
        float m = max8(fmaxf(fmaxf(fabsf(wv.x),fabsf(wv.y)), fmaxf(fabsf(wv.z),fabsf(wv.w))));
        float s = fmaxf(m * (1.0f/QMAXF), 1e-8f);
        float inv = 1.0f / s;
        qo[r*256 + t] = pack4(qclamp(wv.x,inv), qclamp(wv.y,inv), qclamp(wv.z,inv), qclamp(wv.w,inv));
        if ((t & 7) == 0) so[(t>>3)*nrows + r] = s;
    }
}

// ---------------- kernel 3: int8 tensor-core GEMM, 3-stage cp.async pipeline ----------------
__global__ __launch_bounds__(256,2) void gemm_imma(int which){
    const int* Aq; const float* sA; const int* Bq; const float* sB; float* Cm; int N;
    if (which == 0){ Aq=g_qa; sA=g_sa; Bq=g_qw1; sB=g_sw1; Cm=g_qkv;  N=C3; }
    else           { Aq=g_qy; sA=g_sy; Bq=g_qw2; sB=g_sw2; Cm=g_proj; N=Cn; }

    __shared__ __align__(16) int As[3][128][12];
    __shared__ __align__(16) int Bs[3][128][12];
    __shared__ float sAs[3][128];
    __shared__ __align__(8) float sBs[3][128];

    int tid = threadIdx.x, lane = tid & 31, wp = tid >> 5;
    int wM = wp >> 2, wN = wp & 3;
    int bm = blockIdx.y << 7, bn = blockIdx.x << 7;
    int lr = tid >> 1, lw = (tid & 1) << 2;

    #define LOAD_STAGE(st, g) do { \
        cpa16(&As[st][lr][lw], Aq + (bm + lr)*256 + (g)*8 + lw); \
        cpa16(&Bs[st][lr][lw], Bq + (bn + lr)*256 + (g)*8 + lw); \
        if (tid < 128) cpa4(&sAs[st][tid], sA + (g)*BTn + bm + tid); \
        else           cpa4(&sBs[st][tid-128], sB + (g)*N + bn + tid - 128); \
        CP_COMMIT(); \
    } while(0)

    LOAD_STAGE(0, 0);
    LOAD_STAGE(1, 1);

    unsigned long long accp[4][4][2];
#pragma unroll
    for (int i=0;i<4;i++)
#pragma unroll
        for (int j=0;j<4;j++){ accp[i][j][0] = 0ull; accp[i][j][1] = 0ull; }

    const unsigned long long negM = packf2(-12582912.0f, -12582912.0f);
    int a_row = (lane & 15), a_wrd = (lane >> 4) << 2;
    int b_row = ((lane >> 4) << 3) + (lane & 7), b_wrd = ((lane >> 3) & 1) << 2;

    for (int g = 0; g < 32; g++){
        int st = g % 3;
        if (g < 30) CP_WAIT1(); else CP_WAIT0();
        __syncthreads();
        if (g + 2 < 32) LOAD_STAGE((g+2)%3, g+2);

        unsigned a[4][4], bf[2][4];
#pragma unroll
        for (int mc = 0; mc < 4; mc++)
            ldm_x4(a[mc], &As[st][wM*64 + mc*16 + a_row][a_wrd]);
#pragma unroll
        for (int p = 0; p < 2; p++)
            ldm_x4(bf[p], &Bs[st][wN*32 + p*16 + b_row][b_wrd]);

        unsigned long long sa2[8], sb2[4];
#pragma unroll
        for (int mc = 0; mc < 4; mc++){
            float s0 = sAs[st][wM*64 + mc*16 + (lane>>2)];
            float s1 = sAs[st][wM*64 + mc*16 + (lane>>2) + 8];
            sa2[2*mc]   = packf2(s0, s0);
            sa2[2*mc+1] = packf2(s1, s1);
        }
#pragma unroll
        for (int nc = 0; nc < 4; nc++)
            sb2[nc] = *(const unsigned long long*)&sBs[st][wN*32 + nc*8 + ((lane&3)<<1)];

#pragma unroll
        for (int mc = 0; mc < 4; mc++){
#pragma unroll
            for (int nc = 0; nc < 4; nc++){
                int d[4];
                imma16832m(d, a[mc], bf[nc>>1][(nc&1)*2], bf[nc>>1][(nc&1)*2+1]);
                unsigned long long f0 = addf2(pack2i(d[0], d[1]), negM);
                unsigned long long f1 = addf2(pack2i(d[2], d[3]), negM);
                accp[mc][nc][0] = fmaf2(mulf2(f0, sa2[2*mc  ]), sb2[nc], accp[mc][nc][0]);
                accp[mc][nc][1] = fmaf2(mulf2(f1, sa2[2*mc+1]), sb2[nc], accp[mc][nc][1]);
            }
        }
    }
#pragma unroll
    for (int mc = 0; mc < 4; mc++){
#pragma unroll
        for (int nc = 0; nc < 4; nc++){
            int row0 = bm + wM*64 + mc*16 + (lane>>2);
            int col  = bn + wN*32 + nc*8 + ((lane&3)<<1);
            float x0,y0,x1,y1;
            unpackf2(accp[mc][nc][0], x0, y0);
            unpackf2(accp[mc][nc][1], x1, y1);
            *(float2*)(Cm + (size_t)row0*N + col)     = make_float2(x0, y0);
            *(float2*)(Cm + (size_t)(row0+8)*N + col) = make_float2(x1, y1);
        }
    }
    #undef LOAD_STAGE
}

// ---------------- kernel 3.5: K/V -> bf16 hi/lo precompute (V transposed) ----------------
__global__ __launch_bounds__(256) void qkv_convert(){
    __shared__ float Vs[64][65];
    int kt = blockIdx.x, hh = blockIdx.y, b = blockIdx.z;
    int tid = threadIdx.x;
    int ks = kt << 6;
    int bh = b*Hn + hh;
    const float* base = g_qkv + (size_t)(b*Tn)*C3 + hh*HDn;
    unsigned kbase = bh*65536;

    // K: rows ks..ks+63, 64 d -> hi/lo words [row][32]
#pragma unroll
    for (int it = 0; it < 4; it++){
        int idx = tid + it*256;
        int row = idx >> 4, d4 = (idx & 15) << 2;
        float4 v = *(const float4*)(base + (size_t)(ks+row)*C3 + Cn + d4);
        unsigned h0,l0,h1,l1;
        split2(v.x, v.y, h0, l0);
        split2(v.z, v.w, h1, l1);
        unsigned wd = kbase + (ks+row)*32 + (d4>>1);
        gKH[wd] = h0; gKH[wd+1] = h1;
        gKL[wd] = l0; gKL[wd+1] = l1;
    }
    // V: stage tile [64 k][64 d] in smem, then write transposed hi/lo [d][kw]
#pragma unroll
    for (int it = 0; it < 4; it++){
        int idx = tid + it*256;
        int row = idx >> 4, d4 = (idx & 15) << 2;
        float4 v = *(const float4*)(base + (size_t)(ks+row)*C3 + 2*Cn + d4);
        Vs[row][d4] = v.x; Vs[row][d4+1] = v.y; Vs[row][d4+2] = v.z; Vs[row][d4+3] = v.w;
    }
    __syncthreads();
#pragma unroll
    for (int it = 0; it < 8; it++){
        int idx = tid + it*256;
        int d = idx >> 5, kwl = idx & 31;
        float v0 = Vs[2*kwl  ][d];
        float v1 = Vs[2*kwl+1][d];
        unsigned h, l;
        split2(v0, v1, h, l);
        unsigned wd = kbase + d*1024 + (ks>>1) + kwl;
        gVH[wd] = h; gVL[wd] = l;
    }
}

// ---------------- kernel 4: flash attention, bf16 mma (K/V precomputed) ----------------
__global__ __launch_bounds__(256) void attn_kernel(){
    __shared__ unsigned KH[64*QW], KL[64*QW], VH[64*QW], VL[64*QW];   // 36 KB

    int qt = blockIdx.x, hh = blockIdx.y, b = blockIdx.z;
    int tid = threadIdx.x, w = tid >> 5, lane = tid & 31;
    int g = lane >> 2, tig = lane & 3;
    int qs = qt << 7, qb = w << 4;
    const float* base = g_qkv + (size_t)(b*Tn)*C3 + hh*HDn;
    int bh = b*Hn + hh;
    unsigned kbase = bh*65536;
    const float SCALE = 0.125f * 1.44269504088896f;
    int r0 = qs + qb + g, r1 = r0 + 8;

    unsigned aqh[4][4], aql[4][4];
#pragma unroll
    for (int dk=0; dk<4; dk++){
        const float* p0 = base + (size_t)r0*C3 + 16*dk + 2*tig;
        const float* p1 = base + (size_t)r1*C3 + 16*dk + 2*tig;
        float2 v00 = *(const float2*)(p0);
        float2 v01 = *(const float2*)(p0 + 8);
        float2 v10 = *(const float2*)(p1);
        float2 v11 = *(const float2*)(p1 + 8);
        split2(v00.x*SCALE, v00.y*SCALE, aqh[dk][0], aql[dk][0]);
        split2(v10.x*SCALE, v10.y*SCALE, aqh[dk][1], aql[dk][1]);
        split2(v01.x*SCALE, v01.y*SCALE, aqh[dk][2], aql[dk][2]);
        split2(v11.x*SCALE, v11.y*SCALE, aqh[dk][3], aql[dk][3]);
    }

    float o[8][4];
#pragma unroll
    for (int n=0;n<8;n++){ o[n][0]=0.f; o[n][1]=0.f; o[n][2]=0.f; o[n][3]=0.f; }
    float m0 = -INFINITY, m1 = -INFINITY, l0s = 0.f, l1s = 0.f;

    int ntiles = (qs + 128) >> 6;
    for (int kt = 0; kt < ntiles; kt++){
        int ks = kt << 6;
        __syncthreads();
        // bulk cp.async copy of precomputed tiles: 512 chunks of 16B per array
#pragma unroll
        for (int it = 0; it < 2; it++){
            int idx = tid + it*256;
            int row = idx >> 3, ch = (idx & 7) << 2;
            cpa16(&KH[row*QW + ch], &gKH[kbase + (ks+row)*32 + ch]);
            cpa16(&KL[row*QW + ch], &gKL[kbase + (ks+row)*32 + ch]);
            cpa16(&VH[row*QW + ch], &gVH[kbase + row*1024 + (ks>>1) + ch]);
            cpa16(&VL[row*QW + ch], &gVL[kbase + row*1024 + (ks>>1) + ch]);
        }
        CP_COMMIT();
        CP_WAIT0();
        __syncthreads();

        float s[8][4];
#pragma unroll
        for (int n=0;n<8;n++){ s[n][0]=0.f; s[n][1]=0.f; s[n][2]=0.f; s[n][3]=0.f; }
#pragma unroll
        for (int dk = 0; dk < 4; dk++){
#pragma unroll
            for (int n = 0; n < 8; n++){
                int kb = (8*n+g)*QW + 8*dk + tig;
                unsigned bh0 = KH[kb], bh1 = KH[kb+4];
                unsigned bl0 = KL[kb], bl1 = KL[kb+4];
                mma16816(s[n], aqh[dk], bh0, bh1);
                mma16816(s[n], aql[dk], bh0, bh1);
                mma16816(s[n], aqh[dk], bl0, bl1);
            }
        }
        float mx0 = -INFINITY, mx1 = -INFINITY;
#pragma unroll
        for (int n = 0; n < 8; n++){
            int c0 = ks + 8*n + 2*tig, c1 = c0 + 1;
            if (c0 > r0) s[n][0] = -1e30f;
            if (c1 > r0) s[n][1] = -1e30f;
            if (c0 > r1) s[n][2] = -1e30f;
            if (c1 > r1) s[n][3] = -1e30f;
            mx0 = fmaxf(mx0, fmaxf(s[n][0], s[n][1]));
            mx1 = fmaxf(mx1, fmaxf(s[n][2], s[n][3]));
        }
        mx0 = fmaxf(mx0, __shfl_xor_sync(0xffffffffu, mx0, 1));
        mx0 = fmaxf(mx0, __shfl_xor_sync(0xffffffffu, mx0, 2));
        mx1 = fmaxf(mx1, __shfl_xor_sync(0xffffffffu, mx1, 1));
        mx1 = fmaxf(mx1, __shfl_xor_sync(0xffffffffu, mx1, 2));
        float mn0 = fmaxf(m0, mx0), mn1 = fmaxf(m1, mx1);
        float al0 = ex2f(m0 - mn0), al1 = ex2f(m1 - mn1);
        m0 = mn0; m1 = mn1;
        float rs0 = 0.f, rs1 = 0.f;
#pragma unroll
        for (int n = 0; n < 8; n++){
            s[n][0] = ex2f(s[n][0] - m0);
            s[n][1] = ex2f(s[n][1] - m0);
            s[n][2] = ex2f(s[n][2] - m1);
            s[n][3] = ex2f(s[n][3] - m1);
            rs0 += s[n][0] + s[n][1];
            rs1 += s[n][2] + s[n][3];
        }
        rs0 += __shfl_xor_sync(0xffffffffu, rs0, 1);
        rs0 += __shfl_xor_sync(0xffffffffu, rs0, 2);
        rs1 += __shfl_xor_sync(0xffffffffu, rs1, 1);
        rs1 += __shfl_xor_sync(0xffffffffu, rs1, 2);
        l0s = l0s*al0 + rs0;
        l1s = l1s*al1 + rs1;
#pragma unroll
        for (int n = 0; n < 8; n++){
            o[n][0] *= al0; o[n][1] *= al0;
            o[n][2] *= al1; o[n][3] *= al1;
        }
#pragma unroll
        for (int kc = 0; kc < 4; kc++){
            unsigned ph[4], pl[4];
            split2(s[2*kc  ][0], s[2*kc  ][1], ph[0], pl[0]);
            split2(s[2*kc  ][2], s[2*kc  ][3], ph[1], pl[1]);
            split2(s[2*kc+1][0], s[2*kc+1][1], ph[2], pl[2]);
            split2(s[2*kc+1][2], s[2*kc+1][3], ph[3], pl[3]);
#pragma unroll
            for (int nd = 0; nd < 8; nd++){
                int kb = (8*nd+g)*QW + 8*kc + tig;
                unsigned bh0 = VH[kb], bh1 = VH[kb+4];
                unsigned bl0 = VL[kb], bl1 = VL[kb+4];
                mma16816(o[nd], ph, bh0, bh1);
                mma16816(o[nd], pl, bh0, bh1);
                mma16816(o[nd], ph, bl0, bl1);
            }
        }
    }

    float inv0 = 1.0f / l0s, inv1 = 1.0f / l1s;
    float gm00=0.f, gm01=0.f, gm10=0.f, gm11=0.f;
#pragma unroll
    for (int nd = 0; nd < 8; nd++){
        float a0 = fabsf(o[nd][0]*inv0), a1 = fabsf(o[nd][1]*inv0);
        float b0 = fabsf(o[nd][2]*inv1), b1 = fabsf(o[nd][3]*inv1);
        if (nd < 4){ gm00 = fmaxf(gm00, fmaxf(a0,a1)); gm10 = fmaxf(gm10, fmaxf(b0,b1)); }
        else       { gm01 = fmaxf(gm01, fmaxf(a0,a1)); gm11 = fmaxf(gm11, fmaxf(b0,b1)); }
    }
#pragma unroll
    for (int off = 1; off <= 2; off <<= 1){
        gm00 = fmaxf(gm00, __shfl_xor_sync(0xffffffffu, gm00, off));
        gm01 = fmaxf(gm01, __shfl_xor_sync(0xffffffffu, gm01, off));
        gm10 = fmaxf(gm10, __shfl_xor_sync(0xffffffffu, gm10, off));
        gm11 = fmaxf(gm11, __shfl_xor_sync(0xffffffffu, gm11, off));
    }
    float sq00 = fmaxf(gm00*(1.0f/QMAXF), 1e-8f), sq01 = fmaxf(gm01*(1.0f/QMAXF), 1e-8f);
    float sq10 = fmaxf(gm10*(1.0f/QMAXF), 1e-8f), sq11 = fmaxf(gm11*(1.0f/QMAXF), 1e-8f);
    int row0 = b*Tn + r0, row1 = b*Tn + r1;
#pragma unroll
    for (int nd = 0; nd < 8; nd++){
        float is0 = (nd<4) ? 1.0f/sq00 : 1.0f/sq01;
        float is1 = (nd<4) ? 1.0f/sq10 : 1.0f/sq11;
        int q0 = (int)qclamp(o[nd][0]*inv0, is0), q1 = (int)qclamp(o[nd][1]*inv0, is0);
        int q2 = (int)qclamp(o[nd][2]*inv1, is1), q3 = (int)qclamp(o[nd][3]*inv1, is1);
        int sh0 = (q0&0xFF) | ((q1&0xFF)<<8);
        int sh1 = (q2&0xFF) | ((q3&0xFF)<<8);
        int ot0 = __shfl_down_sync(0xffffffffu, sh0, 1);
        int ot1 = __shfl_down_sync(0xffffffffu, sh1, 1);
        if (!(tig & 1)){
            int wi = hh*16 + nd*2 + (tig>>1);
            g_qy[row0*256 + wi] = (sh0&0xFFFF) | (ot0<<16);
            g_qy[row1*256 + wi] = (sh1&0xFFFF) | (ot1<<16);
        }
    }
    if (tig == 0){
        g_sy[(hh*2  )*BTn + row0] = sq00;
        g_sy[(hh*2  )*BTn + row1] = sq10;
    }
    if (tig == 1){
        g_sy[(hh*2+1)*BTn + row0] = sq01;
        g_sy[(hh*2+1)*BTn + row1] = sq11;
    }
}

// ---------------- kernel 5: residual + stats + quant, single-pass ----------------
__global__ void final_kernel(const float* __restrict__ x, float* __restrict__ out, long long osz){
    __shared__ float red[8], redq[8], bc[2];
    int r = blockIdx.x, t = threadIdx.x;
    int c0 = t << 2;
    float4 xv = *(const float4*)(x + (size_t)r*Cn + c0);
    float4 pv = *(const float4*)(g_proj + (size_t)r*Cn + c0);
    float v0 = xv.x + pv.x, v1 = xv.y + pv.y, v2 = xv.z + pv.z, v3 = xv.w + pv.w;

    float sum = (v0 + v1) + (v2 + v3);
    float sq  = v0*v0 + v1*v1 + v2*v2 + v3*v3;
    sum = warp_sum(sum);
    sq  = warp_sum(sq);
    if ((t & 31) == 0){ red[t>>5] = sum; redq[t>>5] = sq; }
    __syncthreads();
    if (t < 32){
        float a = (t < 8) ? red[t]  : 0.f;
        float b = (t < 8) ? redq[t] : 0.f;
#pragma unroll
        for (int o=4;o;o>>=1){ a += __shfl_xor_sync(0xffffffffu, a, o); b += __shfl_xor_sync(0xffffffffu, b, o); }
        if (t == 0){
            float mu = a * (1.0f/Cn);
            float var = b * (1.0f/Cn) - mu*mu;
            bc[0] = mu;
            bc[1] = 1.0f / sqrtf(var + 1e-5f);
        }
    }
    __syncthreads();
    float mu = bc[0], rst = bc[1];

    *(float4*)(out + (size_t)r*Cn + c0) = make_float4(v0, v1, v2, v3);
    float m = max8(fmaxf(fmaxf(fabsf(v0),fabsf(v1)), fmaxf(fabsf(v2),fabsf(v3))));
    float s = fmaxf(m * (1.0f/QMAXF), 1e-8f);
    float inv = 1.0f / s;
    long long oq = (long long)BTn*Cn + (long long)r*Cn + c0;
    if (oq + 3 < osz)
        *(float4*)(out + oq) = make_float4(qclamp(v0,inv), qclamp(v1,inv), qclamp(v2,inv), qclamp(v3,inv));
    if ((t & 7) == 0){
        long long os = 2LL*BTn*Cn + (long long)r*32 + (t>>3);
        if (os < osz) out[os] = s;
    }
    if (t == 0){
        long long om = 2LL*BTn*Cn + 32LL*BTn + r;
        if (om < osz)        out[om]       = mu;
        if (om + BTn < osz)  out[om + BTn] = rst;
    }
}

// ---------------- launch ----------------
extern "C" void kernel_launch(void* const* d_in, const int* in_sizes, int n_in,
                              void* d_out, int out_size){
    const float* x     = (const float*)d_in[0];
    const int*   qx    = (const int*)  d_in[1];
    const float* sx    = (const float*)d_in[2];
    const float* meanp = (const float*)d_in[3];
    const float* rstdp = (const float*)d_in[4];
    const float* lnw   = (const float*)d_in[5];
    const float* w1    = (const float*)d_in[6];
    const float* w2    = (const float*)d_in[7];
    float* out = (float*)d_out;

    prepass<<<BTn + C3 + Cn, 256>>>(qx, sx, meanp, rstdp, lnw, w1, w2);
    gemm_imma<<<dim3(C3/128, BTn/128), 256>>>(0);
    qkv_convert<<<dim3(Tn/64, Hn, Bn), 256>>>();
    attn_kernel<<<dim3(Tn/128, Hn, Bn), 256>>>();
    gemm_imma<<<dim3(Cn/128, BTn/128), 256>>>(1);
    final_kernel<<<BTn, 256>>>(x, out, (long long)out_size);
}

// round 9
// speedup vs baseline: 1.0482x; 1.0482x over previous
#include <cuda_runtime.h>
#include <cuda_bf16.h>
#include <math.h>

#define Bn   2
#define Tn   2048
#define Cn   1024
#define Hn   16
#define HDn  64
#define BTn  (Bn*Tn)
#define QMAXF 127.0f
#define C3   3072
#define QW   36        // padded words per row in attn smem
#define STAGEW (4*64*QW)   // words per attn smem stage (4 arrays)

// ---------------- scratch ----------------
__device__ int   g_qa [BTn*256];
__device__ float g_sa [32*BTn];
__device__ int   g_qw1[3*Cn*256];
__device__ float g_sw1[32*3*Cn];
__device__ int   g_qw2[Cn*256];
__device__ float g_sw2[32*Cn];
__device__ float g_qkv[(size_t)BTn*C3];
__device__ int   g_qy [BTn*256];
__device__ float g_sy [32*BTn];
__device__ float g_proj[(size_t)BTn*Cn];
__device__ unsigned gKH[Bn*Hn*65536], gKL[Bn*Hn*65536];
__device__ unsigned gVH[Bn*Hn*65536], gVL[Bn*Hn*65536];

__device__ __forceinline__ float warp_sum(float v){
#pragma unroll
    for (int o=16;o;o>>=1) v += __shfl_xor_sync(0xffffffffu, v, o);
    return v;
}
__device__ __forceinline__ float max8(float v){
#pragma unroll
    for (int o=4;o;o>>=1) v = fmaxf(v, __shfl_xor_sync(0xffffffffu, v, o));
    return v;
}
__device__ __forceinline__ int pack4(float a, float b, float c, float d){
    int i0=(int)a, i1=(int)b, i2=(int)c, i3=(int)d;
    return (i0&0xFF) | ((i1&0xFF)<<8) | ((i2&0xFF)<<16) | (i3<<24);
}
__device__ __forceinline__ float qclamp(float h, float inv_s){
    float q = rintf(h * inv_s);
    return fminf(fmaxf(q, -QMAXF), QMAXF);
}
__device__ __forceinline__ float ex2f(float x){
    float y; asm("ex2.approx.f32 %0, %1;" : "=f"(y) : "f"(x)); return y;
}
__device__ __forceinline__ unsigned pbf2(float x, float y){
    __nv_bfloat162 h = __floats2bfloat162_rn(x, y);
    return *(unsigned*)&h;
}
__device__ __forceinline__ void split2(float x, float y, unsigned &hi, unsigned &lo){
    unsigned h = pbf2(x, y);
    __nv_bfloat162 hb = *(__nv_bfloat162*)&h;
    hi = h;
    lo = pbf2(x - __bfloat162float(hb.x), y - __bfloat162float(hb.y));
}
__device__ __forceinline__ void mma16816(float* d, const unsigned* a, unsigned b0, unsigned b1){
    asm volatile("mma.sync.aligned.m16n8k16.row.col.f32.bf16.bf16.f32 "
        "{%0,%1,%2,%3},{%4,%5,%6,%7},{%8,%9},{%0,%1,%2,%3};"
        : "+f"(d[0]),"+f"(d[1]),"+f"(d[2]),"+f"(d[3])
        : "r"(a[0]),"r"(a[1]),"r"(a[2]),"r"(a[3]), "r"(b0),"r"(b1));
}
__device__ __forceinline__ void imma16832m(int* d, const unsigned* a, unsigned b0, unsigned b1){
    asm volatile("mma.sync.aligned.m16n8k32.row.col.s32.s8.s8.s32 "
        "{%0,%1,%2,%3},{%4,%5,%6,%7},{%8,%9},{%10,%11,%12,%13};"
        : "=r"(d[0]),"=r"(d[1]),"=r"(d[2]),"=r"(d[3])
        : "r"(a[0]),"r"(a[1]),"r"(a[2]),"r"(a[3]), "r"(b0),"r"(b1),
          "r"(0x4B400000),"r"(0x4B400000),"r"(0x4B400000),"r"(0x4B400000));
}
__device__ __forceinline__ void ldm_x4(unsigned* r, const void* p){
    unsigned ad = (unsigned)__cvta_generic_to_shared(p);
    asm volatile("ldmatrix.sync.aligned.m8n8.x4.shared.b16 {%0,%1,%2,%3}, [%4];"
        : "=r"(r[0]),"=r"(r[1]),"=r"(r[2]),"=r"(r[3]) : "r"(ad));
}
__device__ __forceinline__ unsigned long long packf2(float x, float y){
    unsigned long long r; asm("mov.b64 %0, {%1,%2};" : "=l"(r) : "f"(x),"f"(y)); return r;
}
__device__ __forceinline__ unsigned long long pack2i(int x, int y){
    unsigned long long r; asm("mov.b64 %0, {%1,%2};" : "=l"(r) : "r"(x),"r"(y)); return r;
}
__device__ __forceinline__ void unpackf2(unsigned long long v, float &x, float &y){
    asm("mov.b64 {%0,%1}, %2;" : "=f"(x),"=f"(y) : "l"(v));
}
__device__ __forceinline__ unsigned long long addf2(unsigned long long a, unsigned long long b){
    unsigned long long r; asm("add.rn.f32x2 %0, %1, %2;" : "=l"(r) : "l"(a),"l"(b)); return r;
}
__device__ __forceinline__ unsigned long long mulf2(unsigned long long a, unsigned long long b){
    unsigned long long r; asm("mul.rn.f32x2 %0, %1, %2;" : "=l"(r) : "l"(a),"l"(b)); return r;
}
__device__ __forceinline__ unsigned long long fmaf2(unsigned long long a, unsigned long long b, unsigned long long c){
    unsigned long long r; asm("fma.rn.f32x2 %0, %1, %2, %3;" : "=l"(r) : "l"(a),"l"(b),"l"(c)); return r;
}
__device__ __forceinline__ void cpa16(void* dst, const void* src){
    unsigned d = (unsigned)__cvta_generic_to_shared(dst);
    asm volatile("cp.async.cg.shared.global [%0], [%1], 16;" :: "r"(d), "l"(src));
}
__device__ __forceinline__ void cpa4(void* dst, const void* src){
    unsigned d = (unsigned)__cvta_generic_to_shared(dst);
    asm volatile("cp.async.ca.shared.global [%0], [%1], 4;" :: "r"(d), "l"(src));
}
#define CP_COMMIT() asm volatile("cp.async.commit_group;")
#define CP_WAIT0()  asm volatile("cp.async.wait_group 0;")
#define CP_WAIT1()  asm volatile("cp.async.wait_group 1;")

// ---------------- kernel 1: fused prepass ----------------
__global__ void prepass(const int* __restrict__ qx, const float* __restrict__ sx,
                        const float* __restrict__ meanp, const float* __restrict__ rstdp,
                        const float* __restrict__ lnw,
                        const float* __restrict__ w1, const float* __restrict__ w2){
    int bid = blockIdx.x, t = threadIdx.x;
    int c0 = t << 2;
    if (bid < BTn){
        int r = bid;
        int4 qv = *(const int4*)(qx + r*Cn + c0);
        float sxv = sx[r*32 + (c0 >> 5)];
        float mu = meanp[r], rs = rstdp[r];
        float4 wv = *(const float4*)(lnw + c0);
        float h0 = ((float)qv.x * sxv - mu) * rs * wv.x;
        float h1 = ((float)qv.y * sxv - mu) * rs * wv.y;
        float h2 = ((float)qv.z * sxv - mu) * rs * wv.z;
        float h3 = ((float)qv.w * sxv - mu) * rs * wv.w;
        float m = max8(fmaxf(fmaxf(fabsf(h0),fabsf(h1)), fmaxf(fabsf(h2),fabsf(h3))));
        float s = fmaxf(m * (1.0f/QMAXF), 1e-8f);
        float inv = 1.0f / s;
        g_qa[r*256 + t] = pack4(qclamp(h0,inv), qclamp(h1,inv), qclamp(h2,inv), qclamp(h3,inv));
        if ((t & 7) == 0) g_sa[(t>>3)*BTn + r] = s;
    } else {
        const float* w; int* qo; float* so; int r, nrows;
        if (bid < BTn + C3){ w = w1; qo = g_qw1; so = g_sw1; r = bid - BTn; nrows = C3; }
        else               { w = w2; qo = g_qw2; so = g_sw2; r = bid - BTn - C3; nrows = Cn; }
        float4 wv = *(const float4*)(w + (size_t)r*Cn + c0);
        float m = max8(fmaxf(fmaxf(fabsf(wv.x),fabsf(wv.y)), fmaxf(fabsf(wv.z),fabsf(wv.w))));
        float s = fmaxf(m * (1.0f/QMAXF), 1e-8f);
        float inv = 1.0f / s;
        qo[r*256 + t] = pack4(qclamp(wv.x,inv), qclamp(wv.y,inv), qclamp(wv.z,inv), qclamp(wv.w,inv));
        if ((t & 7) == 0) so[(t>>3)*nrows + r] = s;
    }
}

// ---------------- kernel 3: int8 tensor-core GEMM, 3-stage cp.async pipeline ----------------
__global__ __launch_bounds__(256,2) void gemm_imma(int which){
    const int* Aq; const float* sA; const int* Bq; const float* sB; float* Cm; int N;
    if (which == 0){ Aq=g_qa; sA=g_sa; Bq=g_qw1; sB=g_sw1; Cm=g_qkv;  N=C3; }
    else           { Aq=g_qy; sA=g_sy; Bq=g_qw2; sB=g_sw2; Cm=g_proj; N=Cn; }

    __shared__ __align__(16) int As[3][128][12];
    __shared__ __align__(16) int Bs[3][128][12];
    __shared__ float sAs[3][128];
    __shared__ __align__(8) float sBs[3][128];

    int tid = threadIdx.x, lane = tid & 31, wp = tid >> 5;
    int wM = wp >> 2, wN = wp & 3;
    int bm = blockIdx.y << 7, bn = blockIdx.x << 7;
    int lr = tid >> 1, lw = (tid & 1) << 2;

    #define LOAD_STAGE(st, g) do { \
        cpa16(&As[st][lr][lw], Aq + (bm + lr)*256 + (g)*8 + lw); \
        cpa16(&Bs[st][lr][lw], Bq + (bn + lr)*256 + (g)*8 + lw); \
        if (tid < 128) cpa4(&sAs[st][tid], sA + (g)*BTn + bm + tid); \
        else           cpa4(&sBs[st][tid-128], sB + (g)*N + bn + tid - 128); \
        CP_COMMIT(); \
    } while(0)

    LOAD_STAGE(0, 0);
    LOAD_STAGE(1, 1);

    unsigned long long accp[4][4][2];
#pragma unroll
    for (int i=0;i<4;i++)
#pragma unroll
        for (int j=0;j<4;j++){ accp[i][j][0] = 0ull; accp[i][j][1] = 0ull; }

    const unsigned long long negM = packf2(-12582912.0f, -12582912.0f);
    int a_row = (lane & 15), a_wrd = (lane >> 4) << 2;
    int b_row = ((lane >> 4) << 3) + (lane & 7), b_wrd = ((lane >> 3) & 1) << 2;

    for (int g = 0; g < 32; g++){
        int st = g % 3;
        if (g < 30) CP_WAIT1(); else CP_WAIT0();
        __syncthreads();
        if (g + 2 < 32) LOAD_STAGE((g+2)%3, g+2);

        unsigned a[4][4], bf[2][4];
#pragma unroll
        for (int mc = 0; mc < 4; mc++)
            ldm_x4(a[mc], &As[st][wM*64 + mc*16 + a_row][a_wrd]);
#pragma unroll
        for (int p = 0; p < 2; p++)
            ldm_x4(bf[p], &Bs[st][wN*32 + p*16 + b_row][b_wrd]);

        unsigned long long sa2[8], sb2[4];
#pragma unroll
        for (int mc = 0; mc < 4; mc++){
            float s0 = sAs[st][wM*64 + mc*16 + (lane>>2)];
            float s1 = sAs[st][wM*64 + mc*16 + (lane>>2) + 8];
            sa2[2*mc]   = packf2(s0, s0);
            sa2[2*mc+1] = packf2(s1, s1);
        }
#pragma unroll
        for (int nc = 0; nc < 4; nc++)
            sb2[nc] = *(const unsigned long long*)&sBs[st][wN*32 + nc*8 + ((lane&3)<<1)];

#pragma unroll
        for (int mc = 0; mc < 4; mc++){
#pragma unroll
            for (int nc = 0; nc < 4; nc++){
                int d[4];
                imma16832m(d, a[mc], bf[nc>>1][(nc&1)*2], bf[nc>>1][(nc&1)*2+1]);
                unsigned long long f0 = addf2(pack2i(d[0], d[1]), negM);
                unsigned long long f1 = addf2(pack2i(d[2], d[3]), negM);
                accp[mc][nc][0] = fmaf2(mulf2(f0, sa2[2*mc  ]), sb2[nc], accp[mc][nc][0]);
                accp[mc][nc][1] = fmaf2(mulf2(f1, sa2[2*mc+1]), sb2[nc], accp[mc][nc][1]);
            }
        }
    }
#pragma unroll
    for (int mc = 0; mc < 4; mc++){
#pragma unroll
        for (int nc = 0; nc < 4; nc++){
            int row0 = bm + wM*64 + mc*16 + (lane>>2);
            int col  = bn + wN*32 + nc*8 + ((lane&3)<<1);
            float x0,y0,x1,y1;
            unpackf2(accp[mc][nc][0], x0, y0);
            unpackf2(accp[mc][nc][1], x1, y1);
            *(float2*)(Cm + (size_t)row0*N + col)     = make_float2(x0, y0);
            *(float2*)(Cm + (size_t)(row0+8)*N + col) = make_float2(x1, y1);
        }
    }
    #undef LOAD_STAGE
}

// ---------------- kernel 3.5: K/V -> bf16 hi/lo precompute (V transposed) ----------------
__global__ __launch_bounds__(256) void qkv_convert(){
    __shared__ float Vs[64][65];
    int kt = blockIdx.x, hh = blockIdx.y, b = blockIdx.z;
    int tid = threadIdx.x;
    int ks = kt << 6;
    int bh = b*Hn + hh;
    const float* base = g_qkv + (size_t)(b*Tn)*C3 + hh*HDn;
    unsigned kbase = bh*65536;

#pragma unroll
    for (int it = 0; it < 4; it++){
        int idx = tid + it*256;
        int row = idx >> 4, d4 = (idx & 15) << 2;
        float4 v = *(const float4*)(base + (size_t)(ks+row)*C3 + Cn + d4);
        unsigned h0,l0,h1,l1;
        split2(v.x, v.y, h0, l0);
        split2(v.z, v.w, h1, l1);
        unsigned wd = kbase + (ks+row)*32 + (d4>>1);
        gKH[wd] = h0; gKH[wd+1] = h1;
        gKL[wd] = l0; gKL[wd+1] = l1;
    }
#pragma unroll
    for (int it = 0; it < 4; it++){
        int idx = tid + it*256;
        int row = idx >> 4, d4 = (idx & 15) << 2;
        float4 v = *(const float4*)(base + (size_t)(ks+row)*C3 + 2*Cn + d4);
        Vs[row][d4] = v.x; Vs[row][d4+1] = v.y; Vs[row][d4+2] = v.z; Vs[row][d4+3] = v.w;
    }
    __syncthreads();
#pragma unroll
    for (int it = 0; it < 8; it++){
        int idx = tid + it*256;
        int d = idx >> 5, kwl = idx & 31;
        float v0 = Vs[2*kwl  ][d];
        float v1 = Vs[2*kwl+1][d];
        unsigned h, l;
        split2(v0, v1, h, l);
        unsigned wd = kbase + d*1024 + (ks>>1) + kwl;
        gVH[wd] = h; gVL[wd] = l;
    }
}

// ---------------- kernel 4: flash attention, double-buffered cp.async ----------------
__global__ __launch_bounds__(256) void attn_kernel(){
    extern __shared__ unsigned sm[];   // 2 stages x (KH|KL|VH|VL), 73728 B

    int qt = (gridDim.x - 1) - blockIdx.x;      // heavy blocks first
    int hh = blockIdx.y, b = blockIdx.z;
    int tid = threadIdx.x, w = tid >> 5, lane = tid & 31;
    int g = lane >> 2, tig = lane & 3;
    int qs = qt << 7, qb = w << 4;
    const float* base = g_qkv + (size_t)(b*Tn)*C3 + hh*HDn;
    int bh = b*Hn + hh;
    unsigned kbase = bh*65536;
    const float SCALE = 0.125f * 1.44269504088896f;
    int r0 = qs + qb + g, r1 = r0 + 8;

    unsigned aqh[4][4], aql[4][4];
#pragma unroll
    for (int dk=0; dk<4; dk++){
        const float* p0 = base + (size_t)r0*C3 + 16*dk + 2*tig;
        const float* p1 = base + (size_t)r1*C3 + 16*dk + 2*tig;
        float2 v00 = *(const float2*)(p0);
        float2 v01 = *(const float2*)(p0 + 8);
        float2 v10 = *(const float2*)(p1);
        float2 v11 = *(const float2*)(p1 + 8);
        split2(v00.x*SCALE, v00.y*SCALE, aqh[dk][0], aql[dk][0]);
        split2(v10.x*SCALE, v10.y*SCALE, aqh[dk][1], aql[dk][1]);
        split2(v01.x*SCALE, v01.y*SCALE, aqh[dk][2], aql[dk][2]);
        split2(v11.x*SCALE, v11.y*SCALE, aqh[dk][3], aql[dk][3]);
    }

    float o[8][4];
#pragma unroll
    for (int n=0;n<8;n++){ o[n][0]=0.f; o[n][1]=0.f; o[n][2]=0.f; o[n][3]=0.f; }
    float m0 = -INFINITY, m1 = -INFINITY, l0s = 0.f, l1s = 0.f;

    int ntiles = (qs + 128) >> 6;

    #define TILE_LOAD(stg, kss) do { \
        unsigned* KHp = sm + (stg)*STAGEW;          \
        unsigned* KLp = KHp + 64*QW;                \
        unsigned* VHp = KLp + 64*QW;                \
        unsigned* VLp = VHp + 64*QW;                \
        _Pragma("unroll") \
        for (int it = 0; it < 2; it++){ \
            int idx = tid + it*256; \
            int row = idx >> 3, ch = (idx & 7) << 2; \
            cpa16(&KHp[row*QW + ch], &gKH[kbase + ((kss)+row)*32 + ch]); \
            cpa16(&KLp[row*QW + ch], &gKL[kbase + ((kss)+row)*32 + ch]); \
            cpa16(&VHp[row*QW + ch], &gVH[kbase + row*1024 + ((kss)>>1) + ch]); \
            cpa16(&VLp[row*QW + ch], &gVL[kbase + row*1024 + ((kss)>>1) + ch]); \
        } \
        CP_COMMIT(); \
    } while(0)

    TILE_LOAD(0, 0);

    for (int kt = 0; kt < ntiles; kt++){
        int ks = kt << 6;
        int st = kt & 1;
        if (kt + 1 < ntiles){ TILE_LOAD(st^1, ks + 64); CP_WAIT1(); }
        else                { CP_WAIT0(); }
        __syncthreads();

        const unsigned* KH = sm + st*STAGEW;
        const unsigned* KL = KH + 64*QW;
        const unsigned* VH = KL + 64*QW;
        const unsigned* VL = VH + 64*QW;

        float s[8][4];
#pragma unroll
        for (int n=0;n<8;n++){ s[n][0]=0.f; s[n][1]=0.f; s[n][2]=0.f; s[n][3]=0.f; }
#pragma unroll
        for (int dk = 0; dk < 4; dk++){
#pragma unroll
            for (int n = 0; n < 8; n++){
                int kb = (8*n+g)*QW + 8*dk + tig;
                unsigned bh0 = KH[kb], bh1 = KH[kb+4];
                unsigned bl0 = KL[kb], bl1 = KL[kb+4];
                mma16816(s[n], aqh[dk], bh0, bh1);
                mma16816(s[n], aql[dk], bh0, bh1);
                mma16816(s[n], aqh[dk], bl0, bl1);
            }
        }
        float mx0 = -INFINITY, mx1 = -INFINITY;
#pragma unroll
        for (int n = 0; n < 8; n++){
            int c0 = ks + 8*n + 2*tig, c1 = c0 + 1;
            if (c0 > r0) s[n][0] = -1e30f;
            if (c1 > r0) s[n][1] = -1e30f;
            if (c0 > r1) s[n][2] = -1e30f;
            if (c1 > r1) s[n][3] = -1e30f;
            mx0 = fmaxf(mx0, fmaxf(s[n][0], s[n][1]));
            mx1 = fmaxf(mx1, fmaxf(s[n][2], s[n][3]));
        }
        mx0 = fmaxf(mx0, __shfl_xor_sync(0xffffffffu, mx0, 1));
        mx0 = fmaxf(mx0, __shfl_xor_sync(0xffffffffu, mx0, 2));
        mx1 = fmaxf(mx1, __shfl_xor_sync(0xffffffffu, mx1, 1));
        mx1 = fmaxf(mx1, __shfl_xor_sync(0xffffffffu, mx1, 2));
        float mn0 = fmaxf(m0, mx0), mn1 = fmaxf(m1, mx1);
        float al0 = ex2f(m0 - mn0), al1 = ex2f(m1 - mn1);
        m0 = mn0; m1 = mn1;
        float rs0 = 0.f, rs1 = 0.f;
#pragma unroll
        for (int n = 0; n < 8; n++){
            s[n][0] = ex2f(s[n][0] - m0);
            s[n][1] = ex2f(s[n][1] - m0);
            s[n][2] = ex2f(s[n][2] - m1);
            s[n][3] = ex2f(s[n][3] - m1);
            rs0 += s[n][0] + s[n][1];
            rs1 += s[n][2] + s[n][3];
        }
        rs0 += __shfl_xor_sync(0xffffffffu, rs0, 1);
        rs0 += __shfl_xor_sync(0xffffffffu, rs0, 2);
        rs1 += __shfl_xor_sync(0xffffffffu, rs1, 1);
        rs1 += __shfl_xor_sync(0xffffffffu, rs1, 2);
        l0s = l0s*al0 + rs0;
        l1s = l1s*al1 + rs1;
#pragma unroll
        for (int n = 0; n < 8; n++){
            o[n][0] *= al0; o[n][1] *= al0;
            o[n][2] *= al1; o[n][3] *= al1;
        }
#pragma unroll
        for (int kc = 0; kc < 4; kc++){
            unsigned ph[4], pl[4];
            split2(s[2*kc  ][0], s[2*kc  ][1], ph[0], pl[0]);
            split2(s[2*kc  ][2], s[2*kc  ][3], ph[1], pl[1]);
            split2(s[2*kc+1][0], s[2*kc+1][1], ph[2], pl[2]);
            split2(s[2*kc+1][2], s[2*kc+1][3], ph[3], pl[3]);
#pragma unroll
            for (int nd = 0; nd < 8; nd++){
                int kb = (8*nd+g)*QW + 8*kc + tig;
                unsigned bh0 = VH[kb], bh1 = VH[kb+4];
                unsigned bl0 = VL[kb], bl1 = VL[kb+4];
                mma16816(o[nd], ph, bh0, bh1);
                mma16816(o[nd], pl, bh0, bh1);
                mma16816(o[nd], ph, bl0, bl1);
            }
        }
        __syncthreads();   // stage st free for tile kt+2's load next iteration
    }
    #undef TILE_LOAD

    float inv0 = 1.0f / l0s, inv1 = 1.0f / l1s;
    float gm00=0.f, gm01=0.f, gm10=0.f, gm11=0.f;
#pragma unroll
    for (int nd = 0; nd < 8; nd++){
        float a0 = fabsf(o[nd][0]*inv0), a1 = fabsf(o[nd][1]*inv0);
        float b0 = fabsf(o[nd][2]*inv1), b1 = fabsf(o[nd][3]*inv1);
        if (nd < 4){ gm00 = fmaxf(gm00, fmaxf(a0,a1)); gm10 = fmaxf(gm10, fmaxf(b0,b1)); }
        else       { gm01 = fmaxf(gm01, fmaxf(a0,a1)); gm11 = fmaxf(gm11, fmaxf(b0,b1)); }
    }
#pragma unroll
    for (int off = 1; off <= 2; off <<= 1){
        gm00 = fmaxf(gm00, __shfl_xor_sync(0xffffffffu, gm00, off));
        gm01 = fmaxf(gm01, __shfl_xor_sync(0xffffffffu, gm01, off));
        gm10 = fmaxf(gm10, __shfl_xor_sync(0xffffffffu, gm10, off));
        gm11 = fmaxf(gm11, __shfl_xor_sync(0xffffffffu, gm11, off));
    }
    float sq00 = fmaxf(gm00*(1.0f/QMAXF), 1e-8f), sq01 = fmaxf(gm01*(1.0f/QMAXF), 1e-8f);
    float sq10 = fmaxf(gm10*(1.0f/QMAXF), 1e-8f), sq11 = fmaxf(gm11*(1.0f/QMAXF), 1e-8f);
    int row0 = b*Tn + r0, row1 = b*Tn + r1;
#pragma unroll
    for (int nd = 0; nd < 8; nd++){
        float is0 = (nd<4) ? 1.0f/sq00 : 1.0f/sq01;
        float is1 = (nd<4) ? 1.0f/sq10 : 1.0f/sq11;
        int q0 = (int)qclamp(o[nd][0]*inv0, is0), q1 = (int)qclamp(o[nd][1]*inv0, is0);
        int q2 = (int)qclamp(o[nd][2]*inv1, is1), q3 = (int)qclamp(o[nd][3]*inv1, is1);
        int sh0 = (q0&0xFF) | ((q1&0xFF)<<8);
        int sh1 = (q2&0xFF) | ((q3&0xFF)<<8);
        int ot0 = __shfl_down_sync(0xffffffffu, sh0, 1);
        int ot1 = __shfl_down_sync(0xffffffffu, sh1, 1);
        if (!(tig & 1)){
            int wi = hh*16 + nd*2 + (tig>>1);
            g_qy[row0*256 + wi] = (sh0&0xFFFF) | (ot0<<16);
            g_qy[row1*256 + wi] = (sh1&0xFFFF) | (ot1<<16);
        }
    }
    if (tig == 0){
        g_sy[(hh*2  )*BTn + row0] = sq00;
        g_sy[(hh*2  )*BTn + row1] = sq10;
    }
    if (tig == 1){
        g_sy[(hh*2+1)*BTn + row0] = sq01;
        g_sy[(hh*2+1)*BTn + row1] = sq11;
    }
}

// ---------------- kernel 5: residual + stats + quant, single-pass ----------------
__global__ void final_kernel(const float* __restrict__ x, float* __restrict__ out, long long osz){
    __shared__ float red[8], redq[8], bc[2];
    int r = blockIdx.x, t = threadIdx.x;
    int c0 = t << 2;
    float4 xv = *(const float4*)(x + (size_t)r*Cn + c0);
    float4 pv = *(const float4*)(g_proj + (size_t)r*Cn + c0);
    float v0 = xv.x + pv.x, v1 = xv.y + pv.y, v2 = xv.z + pv.z, v3 = xv.w + pv.w;

    float sum = (v0 + v1) + (v2 + v3);
    float sq  = v0*v0 + v1*v1 + v2*v2 + v3*v3;
    sum = warp_sum(sum);
    sq  = warp_sum(sq);
    if ((t & 31) == 0){ red[t>>5] = sum; redq[t>>5] = sq; }
    __syncthreads();
    if (t < 32){
        float a = (t < 8) ? red[t]  : 0.f;
        float b = (t < 8) ? redq[t] : 0.f;
#pragma unroll
        for (int o=4;o;o>>=1){ a += __shfl_xor_sync(0xffffffffu, a, o); b += __shfl_xor_sync(0xffffffffu, b, o); }
        if (t == 0){
            float mu = a * (1.0f/Cn);
            float var = b * (1.0f/Cn) - mu*mu;
            bc[0] = mu;
            bc[1] = 1.0f / sqrtf(var + 1e-5f);
        }
    }
    __syncthreads();
    float mu = bc[0], rst = bc[1];

    *(float4*)(out + (size_t)r*Cn + c0) = make_float4(v0, v1, v2, v3);
    float m = max8(fmaxf(fmaxf(fabsf(v0),fabsf(v1)), fmaxf(fabsf(v2),fabsf(v3))));
    float s = fmaxf(m * (1.0f/QMAXF), 1e-8f);
    float inv = 1.0f / s;
    long long oq = (long long)BTn*Cn + (long long)r*Cn + c0;
    if (oq + 3 < osz)
        *(float4*)(out + oq) = make_float4(qclamp(v0,inv), qclamp(v1,inv), qclamp(v2,inv), qclamp(v3,inv));
    if ((t & 7) == 0){
        long long os = 2LL*BTn*Cn + (long long)r*32 + (t>>3);
        if (os < osz) out[os] = s;
    }
    if (t == 0){
        long long om = 2LL*BTn*Cn + 32LL*BTn + r;
        if (om < osz)        out[om]       = mu;
        if (om + BTn < osz)  out[om + BTn] = rst;
    }
}

// ---------------- launch ----------------
extern "C" void kernel_launch(void* const* d_in, const int* in_sizes, int n_in,
                              void* d_out, int out_size){
    const float* x     = (const float*)d_in[0];
    const int*   qx    = (const int*)  d_in[1];
    const float* sx    = (const float*)d_in[2];
    const float* meanp = (const float*)d_in[3];
    const float* rstdp = (const float*)d_in[4];
    const float* lnw   = (const float*)d_in[5];
    const float* w1    = (const float*)d_in[6];
    const float* w2    = (const float*)d_in[7];
    float* out = (float*)d_out;

    const int ATTN_SMEM = 2 * STAGEW * 4;   // 73728 bytes
    cudaFuncSetAttribute(attn_kernel, cudaFuncAttributeMaxDynamicSharedMemorySize, ATTN_SMEM);

    prepass<<<BTn + C3 + Cn, 256>>>(qx, sx, meanp, rstdp, lnw, w1, w2);
    gemm_imma<<<dim3(C3/128, BTn/128), 256>>>(0);
    qkv_convert<<<dim3(Tn/64, Hn, Bn), 256>>>();
    attn_kernel<<<dim3(Tn/128, Hn, Bn), 256, ATTN_SMEM>>>();
    gemm_imma<<<dim3(Cn/128, BTn/128), 256>>>(1);
    final_kernel<<<BTn, 256>>>(x, out, (long long)out_size);
}

// round 10
// speedup vs baseline: 1.0506x; 1.0023x over previous
#include <cuda_runtime.h>
#include <cuda_bf16.h>
#include <math.h>

#define Bn   2
#define Tn   2048
#define Cn   1024
#define Hn   16
#define HDn  64
#define BTn  (Bn*Tn)
#define QMAXF 127.0f
#define C3   3072
#define QW   36        // padded words per row in attn smem
#define STAGEW (4*64*QW)   // words per attn smem stage (4 arrays)

// ---------------- scratch ----------------
__device__ int   g_qa [BTn*256];
__device__ float g_sa [32*BTn];
__device__ int   g_qw1[3*Cn*256];
__device__ float g_sw1[32*3*Cn];
__device__ int   g_qw2[Cn*256];
__device__ float g_sw2[32*Cn];
__device__ float g_qkv[(size_t)BTn*C3];
__device__ int   g_qy [BTn*256];
__device__ float g_sy [32*BTn];
__device__ float g_proj[(size_t)BTn*Cn];
__device__ unsigned gKH[Bn*Hn*65536], gKL[Bn*Hn*65536];
__device__ unsigned gVH[Bn*Hn*65536], gVL[Bn*Hn*65536];

__device__ __forceinline__ float warp_sum(float v){
#pragma unroll
    for (int o=16;o;o>>=1) v += __shfl_xor_sync(0xffffffffu, v, o);
    return v;
}
__device__ __forceinline__ float max8(float v){
#pragma unroll
    for (int o=4;o;o>>=1) v = fmaxf(v, __shfl_xor_sync(0xffffffffu, v, o));
    return v;
}
__device__ __forceinline__ int pack4(float a, float b, float c, float d){
    int i0=(int)a, i1=(int)b, i2=(int)c, i3=(int)d;
    return (i0&0xFF) | ((i1&0xFF)<<8) | ((i2&0xFF)<<16) | (i3<<24);
}
__device__ __forceinline__ float qclamp(float h, float inv_s){
    float q = rintf(h * inv_s);
    return fminf(fmaxf(q, -QMAXF), QMAXF);
}
__device__ __forceinline__ float ex2f(float x){
    float y; asm("ex2.approx.f32 %0, %1;" : "=f"(y) : "f"(x)); return y;
}
__device__ __forceinline__ unsigned pbf2(float x, float y){
    __nv_bfloat162 h = __floats2bfloat162_rn(x, y);
    return *(unsigned*)&h;
}
__device__ __forceinline__ void split2(float x, float y, unsigned &hi, unsigned &lo){
    unsigned h = pbf2(x, y);
    __nv_bfloat162 hb = *(__nv_bfloat162*)&h;
    hi = h;
    lo = pbf2(x - __bfloat162float(hb.x), y - __bfloat162float(hb.y));
}
__device__ __forceinline__ void mma16816(float* d, const unsigned* a, unsigned b0, unsigned b1){
    asm volatile("mma.sync.aligned.m16n8k16.row.col.f32.bf16.bf16.f32 "
        "{%0,%1,%2,%3},{%4,%5,%6,%7},{%8,%9},{%0,%1,%2,%3};"
        : "+f"(d[0]),"+f"(d[1]),"+f"(d[2]),"+f"(d[3])
        : "r"(a[0]),"r"(a[1]),"r"(a[2]),"r"(a[3]), "r"(b0),"r"(b1));
}
__device__ __forceinline__ void imma16832m(int* d, const unsigned* a, unsigned b0, unsigned b1){
    asm volatile("mma.sync.aligned.m16n8k32.row.col.s32.s8.s8.s32 "
        "{%0,%1,%2,%3},{%4,%5,%6,%7},{%8,%9},{%10,%11,%12,%13};"
        : "=r"(d[0]),"=r"(d[1]),"=r"(d[2]),"=r"(d[3])
        : "r"(a[0]),"r"(a[1]),"r"(a[2]),"r"(a[3]), "r"(b0),"r"(b1),
          "r"(0x4B400000),"r"(0x4B400000),"r"(0x4B400000),"r"(0x4B400000));
}
__device__ __forceinline__ void ldm_x4(unsigned* r, const void* p){
    unsigned ad = (unsigned)__cvta_generic_to_shared(p);
    asm volatile("ldmatrix.sync.aligned.m8n8.x4.shared.b16 {%0,%1,%2,%3}, [%4];"
        : "=r"(r[0]),"=r"(r[1]),"=r"(r[2]),"=r"(r[3]) : "r"(ad));
}
__device__ __forceinline__ unsigned long long packf2(float x, float y){
    unsigned long long r; asm("mov.b64 %0, {%1,%2};" : "=l"(r) : "f"(x),"f"(y)); return r;
}
__device__ __forceinline__ unsigned long long pack2i(int x, int y){
    unsigned long long r; asm("mov.b64 %0, {%1,%2};" : "=l"(r) : "r"(x),"r"(y)); return r;
}
__device__ __forceinline__ void unpackf2(unsigned long long v, float &x, float &y){
    asm("mov.b64 {%0,%1}, %2;" : "=f"(x),"=f"(y) : "l"(v));
}
__device__ __forceinline__ unsigned long long addf2(unsigned long long a, unsigned long long b){
    unsigned long long r; asm("add.rn.f32x2 %0, %1, %2;" : "=l"(r) : "l"(a),"l"(b)); return r;
}
__device__ __forceinline__ unsigned long long mulf2(unsigned long long a, unsigned long long b){
    unsigned long long r; asm("mul.rn.f32x2 %0, %1, %2;" : "=l"(r) : "l"(a),"l"(b)); return r;
}
__device__ __forceinline__ unsigned long long fmaf2(unsigned long long a, unsigned long long b, unsigned long long c){
    unsigned long long r; asm("fma.rn.f32x2 %0, %1, %2, %3;" : "=l"(r) : "l"(a),"l"(b),"l"(c)); return r;
}
__device__ __forceinline__ void cpa16(void* dst, const void* src){
    unsigned d = (unsigned)__cvta_generic_to_shared(dst);
    asm volatile("cp.async.cg.shared.global [%0], [%1], 16;" :: "r"(d), "l"(src));
}
__device__ __forceinline__ void cpa4(void* dst, const void* src){
    unsigned d = (unsigned)__cvta_generic_to_shared(dst);
    asm volatile("cp.async.ca.shared.global [%0], [%1], 4;" :: "r"(d), "l"(src));
}
#define CP_COMMIT() asm volatile("cp.async.commit_group;")
#define CP_WAIT0()  asm volatile("cp.async.wait_group 0;")
#define CP_WAIT1()  asm volatile("cp.async.wait_group 1;")

// ---------------- kernel 1: fused prepass ----------------
__global__ void prepass(const int* __restrict__ qx, const float* __restrict__ sx,
                        const float* __restrict__ meanp, const float* __restrict__ rstdp,
                        const float* __restrict__ lnw,
                        const float* __restrict__ w1, const float* __restrict__ w2){
    int bid = blockIdx.x, t = threadIdx.x;
    int c0 = t << 2;
    if (bid < BTn){
        int r = bid;
        int4 qv = *(const int4*)(qx + r*Cn + c0);
        float sxv = sx[r*32 + (c0 >> 5)];
        float mu = meanp[r], rs = rstdp[r];
        float4 wv = *(const float4*)(lnw + c0);
        float h0 = ((float)qv.x * sxv - mu) * rs * wv.x;
        float h1 = ((float)qv.y * sxv - mu) * rs * wv.y;
        float h2 = ((float)qv.z * sxv - mu) * rs * wv.z;
        float h3 = ((float)qv.w * sxv - mu) * rs * wv.w;
        float m = max8(fmaxf(fmaxf(fabsf(h0),fabsf(h1)), fmaxf(fabsf(h2),fabsf(h3))));
        float s = fmaxf(m * (1.0f/QMAXF), 1e-8f);
        float inv = 1.0f / s;
        g_qa[r*256 + t] = pack4(qclamp(h0,inv), qclamp(h1,inv), qclamp(h2,inv), qclamp(h3,inv));
        if ((t & 7) == 0) g_sa[(t>>3)*BTn + r] = s;
    } else {
        const float* w; int* qo; float* so; int r, nrows;
        if (bid < BTn + C3){ w = w1; qo = g_qw1; so = g_sw1; r = bid - BTn; nrows = C3; }
        else               { w = w2; qo = g_qw2; so = g_sw2; r = bid - BTn - C3; nrows = Cn; }
        float4 wv = *(const float4*)(w + (size_t)r*Cn + c0);
        float m = max8(fmaxf(fmaxf(fabsf(wv.x),fabsf(wv.y)), fmaxf(fabsf(wv.z),fabsf(wv.w))));
        float s = fmaxf(m * (1.0f/QMAXF), 1e-8f);
        float inv = 1.0f / s;
        qo[r*256 + t] = pack4(qclamp(wv.x,inv), qclamp(wv.y,inv), qclamp(wv.z,inv), qclamp(wv.w,inv));
        if ((t & 7) == 0) so[(t>>3)*nrows + r] = s;
    }
}

// ---------------- kernel 3: int8 tensor-core GEMM, 3-stage cp.async pipeline ----------------
__global__ __launch_bounds__(256,2) void gemm_imma(int which){
    const int* Aq; const float* sA; const int* Bq; const float* sB; float* Cm; int N;
    if (which == 0){ Aq=g_qa; sA=g_sa; Bq=g_qw1; sB=g_sw1; Cm=g_qkv;  N=C3; }
    else           { Aq=g_qy; sA=g_sy; Bq=g_qw2; sB=g_sw2; Cm=g_proj; N=Cn; }

    __shared__ __align__(16) int As[3][128][12];
    __shared__ __align__(16) int Bs[3][128][12];
    __shared__ float sAs[3][128];
    __shared__ __align__(8) float sBs[3][128];

    int tid = threadIdx.x, lane = tid & 31, wp = tid >> 5;
    int wM = wp >> 2, wN = wp & 3;
    int bm = blockIdx.y << 7, bn = blockIdx.x << 7;
    int lr = tid >> 1, lw = (tid & 1) << 2;

    #define LOAD_STAGE(st, g) do { \
        cpa16(&As[st][lr][lw], Aq + (bm + lr)*256 + (g)*8 + lw); \
        cpa16(&Bs[st][lr][lw], Bq + (bn + lr)*256 + (g)*8 + lw); \
        if (tid < 128) cpa4(&sAs[st][tid], sA + (g)*BTn + bm + tid); \
        else           cpa4(&sBs[st][tid-128], sB + (g)*N + bn + tid - 128); \
        CP_COMMIT(); \
    } while(0)

    LOAD_STAGE(0, 0);
    LOAD_STAGE(1, 1);

    unsigned long long accp[4][4][2];
#pragma unroll
    for (int i=0;i<4;i++)
#pragma unroll
        for (int j=0;j<4;j++){ accp[i][j][0] = 0ull; accp[i][j][1] = 0ull; }

    const unsigned long long negM = packf2(-12582912.0f, -12582912.0f);
    int a_row = (lane & 15), a_wrd = (lane >> 4) << 2;
    int b_row = ((lane >> 4) << 3) + (lane & 7), b_wrd = ((lane >> 3) & 1) << 2;

    for (int g = 0; g < 32; g++){
        int st = g % 3;
        if (g < 30) CP_WAIT1(); else CP_WAIT0();
        __syncthreads();
        if (g + 2 < 32) LOAD_STAGE((g+2)%3, g+2);

        unsigned a[4][4], bf[2][4];
#pragma unroll
        for (int mc = 0; mc < 4; mc++)
            ldm_x4(a[mc], &As[st][wM*64 + mc*16 + a_row][a_wrd]);
#pragma unroll
        for (int p = 0; p < 2; p++)
            ldm_x4(bf[p], &Bs[st][wN*32 + p*16 + b_row][b_wrd]);

        unsigned long long sa2[8], sb2[4];
#pragma unroll
        for (int mc = 0; mc < 4; mc++){
            float s0 = sAs[st][wM*64 + mc*16 + (lane>>2)];
            float s1 = sAs[st][wM*64 + mc*16 + (lane>>2) + 8];
            sa2[2*mc]   = packf2(s0, s0);
            sa2[2*mc+1] = packf2(s1, s1);
        }
#pragma unroll
        for (int nc = 0; nc < 4; nc++)
            sb2[nc] = *(const unsigned long long*)&sBs[st][wN*32 + nc*8 + ((lane&3)<<1)];

#pragma unroll
        for (int mc = 0; mc < 4; mc++){
#pragma unroll
            for (int nc = 0; nc < 4; nc++){
                int d[4];
                imma16832m(d, a[mc], bf[nc>>1][(nc&1)*2], bf[nc>>1][(nc&1)*2+1]);
                unsigned long long f0 = addf2(pack2i(d[0], d[1]), negM);
                unsigned long long f1 = addf2(pack2i(d[2], d[3]), negM);
                accp[mc][nc][0] = fmaf2(mulf2(f0, sa2[2*mc  ]), sb2[nc], accp[mc][nc][0]);
                accp[mc][nc][1] = fmaf2(mulf2(f1, sa2[2*mc+1]), sb2[nc], accp[mc][nc][1]);
            }
        }
    }
#pragma unroll
    for (int mc = 0; mc < 4; mc++){
#pragma unroll
        for (int nc = 0; nc < 4; nc++){
            int row0 = bm + wM*64 + mc*16 + (lane>>2);
            int col  = bn + wN*32 + nc*8 + ((lane&3)<<1);
            float x0,y0,x1,y1;
            unpackf2(accp[mc][nc][0], x0, y0);
            unpackf2(accp[mc][nc][1], x1, y1);
            *(float2*)(Cm + (size_t)row0*N + col)     = make_float2(x0, y0);
            *(float2*)(Cm + (size_t)(row0+8)*N + col) = make_float2(x1, y1);
        }
    }
    #undef LOAD_STAGE
}

// ---------------- kernel 3.5: K/V -> bf16 hi/lo precompute (V transposed) ----------------
__global__ __launch_bounds__(256) void qkv_convert(){
    __shared__ float Vs[64][65];
    int kt = blockIdx.x, hh = blockIdx.y, b = blockIdx.z;
    int tid = threadIdx.x;
    int ks = kt << 6;
    int bh = b*Hn + hh;
    const float* base = g_qkv + (size_t)(b*Tn)*C3 + hh*HDn;
    unsigned kbase = bh*65536;

#pragma unroll
    for (int it = 0; it < 4; it++){
        int idx = tid + it*256;
        int row = idx >> 4, d4 = (idx & 15) << 2;
        float4 v = *(const float4*)(base + (size_t)(ks+row)*C3 + Cn + d4);
        unsigned h0,l0,h1,l1;
        split2(v.x, v.y, h0, l0);
        split2(v.z, v.w, h1, l1);
        unsigned wd = kbase + (ks+row)*32 + (d4>>1);
        gKH[wd] = h0; gKH[wd+1] = h1;
        gKL[wd] = l0; gKL[wd+1] = l1;
    }
#pragma unroll
    for (int it = 0; it < 4; it++){
        int idx = tid + it*256;
        int row = idx >> 4, d4 = (idx & 15) << 2;
        float4 v = *(const float4*)(base + (size_t)(ks+row)*C3 + 2*Cn + d4);
        Vs[row][d4] = v.x; Vs[row][d4+1] = v.y; Vs[row][d4+2] = v.z; Vs[row][d4+3] = v.w;
    }
    __syncthreads();
#pragma unroll
    for (int it = 0; it < 8; it++){
        int idx = tid + it*256;
        int d = idx >> 5, kwl = idx & 31;
        float v0 = Vs[2*kwl  ][d];
        float v1 = Vs[2*kwl+1][d];
        unsigned h, l;
        split2(v0, v1, h, l);
        unsigned wd = kbase + d*1024 + (ks>>1) + kwl;
        gVH[wd] = h; gVL[wd] = l;
    }
}

// ---------------- kernel 4: flash attention, double-buffered, 2 blocks/SM ----------------
__global__ __launch_bounds__(256,2) void attn_kernel(){
    extern __shared__ unsigned sm[];   // 2 stages x (KH|KL|VH|VL), 73728 B

    int qt = (gridDim.x - 1) - blockIdx.x;      // heavy blocks first
    int hh = blockIdx.y, b = blockIdx.z;
    int tid = threadIdx.x, w = tid >> 5, lane = tid & 31;
    int g = lane >> 2, tig = lane & 3;
    int qs = qt << 7, qb = w << 4;
    const float* base = g_qkv + (size_t)(b*Tn)*C3 + hh*HDn;
    int bh = b*Hn + hh;
    unsigned kbase = bh*65536;
    const float SCALE = 0.125f * 1.44269504088896f;
    int r0 = qs + qb + g, r1 = r0 + 8;

    unsigned aqh[4][4], aql[4][4];
#pragma unroll
    for (int dk=0; dk<4; dk++){
        const float* p0 = base + (size_t)r0*C3 + 16*dk + 2*tig;
        const float* p1 = base + (size_t)r1*C3 + 16*dk + 2*tig;
        float2 v00 = *(const float2*)(p0);
        float2 v01 = *(const float2*)(p0 + 8);
        float2 v10 = *(const float2*)(p1);
        float2 v11 = *(const float2*)(p1 + 8);
        split2(v00.x*SCALE, v00.y*SCALE, aqh[dk][0], aql[dk][0]);
        split2(v10.x*SCALE, v10.y*SCALE, aqh[dk][1], aql[dk][1]);
        split2(v01.x*SCALE, v01.y*SCALE, aqh[dk][2], aql[dk][2]);
        split2(v11.x*SCALE, v11.y*SCALE, aqh[dk][3], aql[dk][3]);
    }

    float o[8][4];
#pragma unroll
    for (int n=0;n<8;n++){ o[n][0]=0.f; o[n][1]=0.f; o[n][2]=0.f; o[n][3]=0.f; }
    float m0 = -INFINITY, m1 = -INFINITY, l0s = 0.f, l1s = 0.f;

    int ntiles = (qs + 128) >> 6;

    #define TILE_LOAD(stg, kss) do { \
        unsigned* KHp = sm + (stg)*STAGEW;          \
        unsigned* KLp = KHp + 64*QW;                \
        unsigned* VHp = KLp + 64*QW;                \
        unsigned* VLp = VHp + 64*QW;                \
        _Pragma("unroll") \
        for (int it = 0; it < 2; it++){ \
            int idx = tid + it*256; \
            int row = idx >> 3, ch = (idx & 7) << 2; \
            cpa16(&KHp[row*QW + ch], &gKH[kbase + ((kss)+row)*32 + ch]); \
            cpa16(&KLp[row*QW + ch], &gKL[kbase + ((kss)+row)*32 + ch]); \
            cpa16(&VHp[row*QW + ch], &gVH[kbase + row*1024 + ((kss)>>1) + ch]); \
            cpa16(&VLp[row*QW + ch], &gVL[kbase + row*1024 + ((kss)>>1) + ch]); \
        } \
        CP_COMMIT(); \
    } while(0)

    TILE_LOAD(0, 0);

    for (int kt = 0; kt < ntiles; kt++){
        int ks = kt << 6;
        int st = kt & 1;
        if (kt + 1 < ntiles){ TILE_LOAD(st^1, ks + 64); CP_WAIT1(); }
        else                { CP_WAIT0(); }
        __syncthreads();

        const unsigned* KH = sm + st*STAGEW;
        const unsigned* KL = KH + 64*QW;
        const unsigned* VH = KL + 64*QW;
        const unsigned* VL = VH + 64*QW;

        float s[8][4];
#pragma unroll
        for (int n=0;n<8;n++){ s[n][0]=0.f; s[n][1]=0.f; s[n][2]=0.f; s[n][3]=0.f; }
#pragma unroll
        for (int dk = 0; dk < 4; dk++){
#pragma unroll
            for (int n = 0; n < 8; n++){
                int kb = (8*n+g)*QW + 8*dk + tig;
                unsigned bh0 = KH[kb], bh1 = KH[kb+4];
                unsigned bl0 = KL[kb], bl1 = KL[kb+4];
                mma16816(s[n], aqh[dk], bh0, bh1);
                mma16816(s[n], aql[dk], bh0, bh1);
                mma16816(s[n], aqh[dk], bl0, bl1);
            }
        }
        float mx0 = -INFINITY, mx1 = -INFINITY;
#pragma unroll
        for (int n = 0; n < 8; n++){
            int c0 = ks + 8*n + 2*tig, c1 = c0 + 1;
            if (c0 > r0) s[n][0] = -1e30f;
            if (c1 > r0) s[n][1] = -1e30f;
            if (c0 > r1) s[n][2] = -1e30f;
            if (c1 > r1) s[n][3] = -1e30f;
            mx0 = fmaxf(mx0, fmaxf(s[n][0], s[n][1]));
            mx1 = fmaxf(mx1, fmaxf(s[n][2], s[n][3]));
        }
        mx0 = fmaxf(mx0, __shfl_xor_sync(0xffffffffu, mx0, 1));
        mx0 = fmaxf(mx0, __shfl_xor_sync(0xffffffffu, mx0, 2));
        mx1 = fmaxf(mx1, __shfl_xor_sync(0xffffffffu, mx1, 1));
        mx1 = fmaxf(mx1, __shfl_xor_sync(0xffffffffu, mx1, 2));
        float mn0 = fmaxf(m0, mx0), mn1 = fmaxf(m1, mx1);
        float al0 = ex2f(m0 - mn0), al1 = ex2f(m1 - mn1);
        m0 = mn0; m1 = mn1;
        float rs0 = 0.f, rs1 = 0.f;
#pragma unroll
        for (int n = 0; n < 8; n++){
            s[n][0] = ex2f(s[n][0] - m0);
            s[n][1] = ex2f(s[n][1] - m0);
            s[n][2] = ex2f(s[n][2] - m1);
            s[n][3] = ex2f(s[n][3] - m1);
            rs0 += s[n][0] + s[n][1];
            rs1 += s[n][2] + s[n][3];
        }
        rs0 += __shfl_xor_sync(0xffffffffu, rs0, 1);
        rs0 += __shfl_xor_sync(0xffffffffu, rs0, 2);
        rs1 += __shfl_xor_sync(0xffffffffu, rs1, 1);
        rs1 += __shfl_xor_sync(0xffffffffu, rs1, 2);
        l0s = l0s*al0 + rs0;
        l1s = l1s*al1 + rs1;
#pragma unroll
        for (int n = 0; n < 8; n++){
            o[n][0] *= al0; o[n][1] *= al0;
            o[n][2] *= al1; o[n][3] *= al1;
        }
#pragma unroll
        for (int kc = 0; kc < 4; kc++){
            unsigned ph[4], pl[4];
            split2(s[2*kc  ][0], s[2*kc  ][1], ph[0], pl[0]);
            split2(s[2*kc  ][2], s[2*kc  ][3], ph[1], pl[1]);
            split2(s[2*kc+1][0], s[2*kc+1][1], ph[2], pl[2]);
            split2(s[2*kc+1][2], s[2*kc+1][3], ph[3], pl[3]);
#pragma unroll
            for (int nd = 0; nd < 8; nd++){
                int kb = (8*nd+g)*QW + 8*kc + tig;
                unsigned bh0 = VH[kb], bh1 = VH[kb+4];
                unsigned bl0 = VL[kb], bl1 = VL[kb+4];
                mma16816(o[nd], ph, bh0, bh1);
                mma16816(o[nd], pl, bh0, bh1);
                mma16816(o[nd], ph, bl0, bl1);
            }
        }
        __syncthreads();
    }
    #undef TILE_LOAD

    float inv0 = 1.0f / l0s, inv1 = 1.0f / l1s;
    float gm00=0.f, gm01=0.f, gm10=0.f, gm11=0.f;
#pragma unroll
    for (int nd = 0; nd < 8; nd++){
        float a0 = fabsf(o[nd][0]*inv0), a1 = fabsf(o[nd][1]*inv0);
        float b0 = fabsf(o[nd][2]*inv1), b1 = fabsf(o[nd][3]*inv1);
        if (nd < 4){ gm00 = fmaxf(gm00, fmaxf(a0,a1)); gm10 = fmaxf(gm10, fmaxf(b0,b1)); }
        else       { gm01 = fmaxf(gm01, fmaxf(a0,a1)); gm11 = fmaxf(gm11, fmaxf(b0,b1)); }
    }
#pragma unroll
    for (int off = 1; off <= 2; off <<= 1){
        gm00 = fmaxf(gm00, __shfl_xor_sync(0xffffffffu, gm00, off));
        gm01 = fmaxf(gm01, __shfl_xor_sync(0xffffffffu, gm01, off));
        gm10 = fmaxf(gm10, __shfl_xor_sync(0xffffffffu, gm10, off));
        gm11 = fmaxf(gm11, __shfl_xor_sync(0xffffffffu, gm11, off));
    }
    float sq00 = fmaxf(gm00*(1.0f/QMAXF), 1e-8f), sq01 = fmaxf(gm01*(1.0f/QMAXF), 1e-8f);
    float sq10 = fmaxf(gm10*(1.0f/QMAXF), 1e-8f), sq11 = fmaxf(gm11*(1.0f/QMAXF), 1e-8f);
    int row0 = b*Tn + r0, row1 = b*Tn + r1;
#pragma unroll
    for (int nd = 0; nd < 8; nd++){
        float is0 = (nd<4) ? 1.0f/sq00 : 1.0f/sq01;
        float is1 = (nd<4) ? 1.0f/sq10 : 1.0f/sq11;
        int q0 = (int)qclamp(o[nd][0]*inv0, is0), q1 = (int)qclamp(o[nd][1]*inv0, is0);
        int q2 = (int)qclamp(o[nd][2]*inv1, is1), q3 = (int)qclamp(o[nd][3]*inv1, is1);
        int sh0 = (q0&0xFF) | ((q1&0xFF)<<8);
        int sh1 = (q2&0xFF) | ((q3&0xFF)<<8);
        int ot0 = __shfl_down_sync(0xffffffffu, sh0, 1);
        int ot1 = __shfl_down_sync(0xffffffffu, sh1, 1);
        if (!(tig & 1)){
            int wi = hh*16 + nd*2 + (tig>>1);
            g_qy[row0*256 + wi] = (sh0&0xFFFF) | (ot0<<16);
            g_qy[row1*256 + wi] = (sh1&0xFFFF) | (ot1<<16);
        }
    }
    if (tig == 0){
        g_sy[(hh*2  )*BTn + row0] = sq00;
        g_sy[(hh*2  )*BTn + row1] = sq10;
    }
    if (tig == 1){
        g_sy[(hh*2+1)*BTn + row0] = sq01;
        g_sy[(hh*2+1)*BTn + row1] = sq11;
    }
}

// ---------------- kernel 5: residual + stats + quant, single-pass ----------------
__global__ void final_kernel(const float* __restrict__ x, float* __restrict__ out, long long osz){
    __shared__ float red[8], redq[8], bc[2];
    int r = blockIdx.x, t = threadIdx.x;
    int c0 = t << 2;
    float4 xv = *(const float4*)(x + (size_t)r*Cn + c0);
    float4 pv = *(const float4*)(g_proj + (size_t)r*Cn + c0);
    float v0 = xv.x + pv.x, v1 = xv.y + pv.y, v2 = xv.z + pv.z, v3 = xv.w + pv.w;

    float sum = (v0 + v1) + (v2 + v3);
    float sq  = v0*v0 + v1*v1 + v2*v2 + v3*v3;
    sum = warp_sum(sum);
    sq  = warp_sum(sq);
    if ((t & 31) == 0){ red[t>>5] = sum; redq[t>>5] = sq; }
    __syncthreads();
    if (t < 32){
        float a = (t < 8) ? red[t]  : 0.f;
        float b = (t < 8) ? redq[t] : 0.f;
#pragma unroll
        for (int o=4;o;o>>=1){ a += __shfl_xor_sync(0xffffffffu, a, o); b += __shfl_xor_sync(0xffffffffu, b, o); }
        if (t == 0){
            float mu = a * (1.0f/Cn);
            float var = b * (1.0f/Cn) - mu*mu;
            bc[0] = mu;
            bc[1] = 1.0f / sqrtf(var + 1e-5f);
        }
    }
    __syncthreads();
    float mu = bc[0], rst = bc[1];

    *(float4*)(out + (size_t)r*Cn + c0) = make_float4(v0, v1, v2, v3);
    float m = max8(fmaxf(fmaxf(fabsf(v0),fabsf(v1)), fmaxf(fabsf(v2),fabsf(v3))));
    float s = fmaxf(m * (1.0f/QMAXF), 1e-8f);
    float inv = 1.0f / s;
    long long oq = (long long)BTn*Cn + (long long)r*Cn + c0;
    if (oq + 3 < osz)
        *(float4*)(out + oq) = make_float4(qclamp(v0,inv), qclamp(v1,inv), qclamp(v2,inv), qclamp(v3,inv));
    if ((t & 7) == 0){
        long long os = 2LL*BTn*Cn + (long long)r*32 + (t>>3);
        if (os < osz) out[os] = s;
    }
    if (t == 0){
        long long om = 2LL*BTn*Cn + 32LL*BTn + r;
        if (om < osz)        out[om]       = mu;
        if (om + BTn < osz)  out[om + BTn] = rst;
    }
}

// ---------------- launch ----------------
extern "C" void kernel_launch(void* const* d_in, const int* in_sizes, int n_in,
                              void* d_out, int out_size){
    const float* x     = (const float*)d_in[0];
    const int*   qx    = (const int*)  d_in[1];
    const float* sx    = (const float*)d_in[2];
    const float* meanp = (const float*)d_in[3];
    const float* rstdp = (const float*)d_in[4];
    const float* lnw   = (const float*)d_in[5];
    const float* w1    = (const float*)d_in[6];
    const float* w2    = (const float*)d_in[7];
    float* out = (float*)d_out;

    const int ATTN_SMEM = 2 * STAGEW * 4;   // 73728 bytes
    cudaFuncSetAttribute(attn_kernel, cudaFuncAttributeMaxDynamicSharedMemorySize, ATTN_SMEM);

    prepass<<<BTn + C3 + Cn, 256>>>(qx, sx, meanp, rstdp, lnw, w1, w2);
    gemm_imma<<<dim3(C3/128, BTn/128), 256>>>(0);
    qkv_convert<<<dim3(Tn/64, Hn, Bn), 256>>>();
    attn_kernel<<<dim3(Tn/128, Hn, Bn), 256, ATTN_SMEM>>>();
    gemm_imma<<<dim3(Cn/128, BTn/128), 256>>>(1);
    final_kernel<<<BTn, 256>>>(x, out, (long long)out_size);
}

// round 11
// speedup vs baseline: 1.0861x; 1.0338x over previous
#include <cuda_runtime.h>
#include <cuda_bf16.h>
#include <math.h>

#define Bn   2
#define Tn   2048
#define Cn   1024
#define Hn   16
#define HDn  64
#define BTn  (Bn*Tn)
#define QMAXF 127.0f
#define C3   3072
#define QW   36
// attn 32-key stage: KH(32*QW) KL(32*QW) VH(64*QW) VL(64*QW)
#define KH_OFF 0
#define KL_OFF (32*QW)
#define VH_OFF (64*QW)
#define VL_OFF (128*QW)
#define STAGEW (192*QW)     // 6912 words = 27648 B

// ---------------- scratch ----------------
__device__ int   g_qa [BTn*256];
__device__ float g_sa [32*BTn];
__device__ int   g_qw1[3*Cn*256];
__device__ float g_sw1[32*3*Cn];
__device__ int   g_qw2[Cn*256];
__device__ float g_sw2[32*Cn];
__device__ float g_qkv[(size_t)BTn*C3];
__device__ int   g_qy [BTn*256];
__device__ float g_sy [32*BTn];
__device__ float g_proj[(size_t)BTn*Cn];
__device__ unsigned gKH[Bn*Hn*65536], gKL[Bn*Hn*65536];
__device__ unsigned gVH[Bn*Hn*65536], gVL[Bn*Hn*65536];

__device__ __forceinline__ float warp_sum(float v){
#pragma unroll
    for (int o=16;o;o>>=1) v += __shfl_xor_sync(0xffffffffu, v, o);
    return v;
}
__device__ __forceinline__ float max8(float v){
#pragma unroll
    for (int o=4;o;o>>=1) v = fmaxf(v, __shfl_xor_sync(0xffffffffu, v, o));
    return v;
}
__device__ __forceinline__ int pack4(float a, float b, float c, float d){
    int i0=(int)a, i1=(int)b, i2=(int)c, i3=(int)d;
    return (i0&0xFF) | ((i1&0xFF)<<8) | ((i2&0xFF)<<16) | (i3<<24);
}
__device__ __forceinline__ float qclamp(float h, float inv_s){
    float q = rintf(h * inv_s);
    return fminf(fmaxf(q, -QMAXF), QMAXF);
}
__device__ __forceinline__ float ex2f(float x){
    float y; asm("ex2.approx.f32 %0, %1;" : "=f"(y) : "f"(x)); return y;
}
__device__ __forceinline__ unsigned pbf2(float x, float y){
    __nv_bfloat162 h = __floats2bfloat162_rn(x, y);
    return *(unsigned*)&h;
}
__device__ __forceinline__ void split2(float x, float y, unsigned &hi, unsigned &lo){
    unsigned h = pbf2(x, y);
    __nv_bfloat162 hb = *(__nv_bfloat162*)&h;
    hi = h;
    lo = pbf2(x - __bfloat162float(hb.x), y - __bfloat162float(hb.y));
}
__device__ __forceinline__ void mma16816(float* d, const unsigned* a, unsigned b0, unsigned b1){
    asm volatile("mma.sync.aligned.m16n8k16.row.col.f32.bf16.bf16.f32 "
        "{%0,%1,%2,%3},{%4,%5,%6,%7},{%8,%9},{%0,%1,%2,%3};"
        : "+f"(d[0]),"+f"(d[1]),"+f"(d[2]),"+f"(d[3])
        : "r"(a[0]),"r"(a[1]),"r"(a[2]),"r"(a[3]), "r"(b0),"r"(b1));
}
__device__ __forceinline__ void imma16832m(int* d, const unsigned* a, unsigned b0, unsigned b1){
    asm volatile("mma.sync.aligned.m16n8k32.row.col.s32.s8.s8.s32 "
        "{%0,%1,%2,%3},{%4,%5,%6,%7},{%8,%9},{%10,%11,%12,%13};"
        : "=r"(d[0]),"=r"(d[1]),"=r"(d[2]),"=r"(d[3])
        : "r"(a[0]),"r"(a[1]),"r"(a[2]),"r"(a[3]), "r"(b0),"r"(b1),
          "r"(0x4B400000),"r"(0x4B400000),"r"(0x4B400000),"r"(0x4B400000));
}
__device__ __forceinline__ void ldm_x4(unsigned* r, const void* p){
    unsigned ad = (unsigned)__cvta_generic_to_shared(p);
    asm volatile("ldmatrix.sync.aligned.m8n8.x4.shared.b16 {%0,%1,%2,%3}, [%4];"
        : "=r"(r[0]),"=r"(r[1]),"=r"(r[2]),"=r"(r[3]) : "r"(ad));
}
__device__ __forceinline__ unsigned long long packf2(float x, float y){
    unsigned long long r; asm("mov.b64 %0, {%1,%2};" : "=l"(r) : "f"(x),"f"(y)); return r;
}
__device__ __forceinline__ unsigned long long pack2i(int x, int y){
    unsigned long long r; asm("mov.b64 %0, {%1,%2};" : "=l"(r) : "r"(x),"r"(y)); return r;
}
__device__ __forceinline__ void unpackf2(unsigned long long v, float &x, float &y){
    asm("mov.b64 {%0,%1}, %2;" : "=f"(x),"=f"(y) : "l"(v));
}
__device__ __forceinline__ unsigned long long addf2(unsigned long long a, unsigned long long b){
    unsigned long long r; asm("add.rn.f32x2 %0, %1, %2;" : "=l"(r) : "l"(a),"l"(b)); return r;
}
__device__ __forceinline__ unsigned long long mulf2(unsigned long long a, unsigned long long b){
    unsigned long long r; asm("mul.rn.f32x2 %0, %1, %2;" : "=l"(r) : "l"(a),"l"(b)); return r;
}
__device__ __forceinline__ unsigned long long fmaf2(unsigned long long a, unsigned long long b, unsigned long long c){
    unsigned long long r; asm("fma.rn.f32x2 %0, %1, %2, %3;" : "=l"(r) : "l"(a),"l"(b),"l"(c)); return r;
}
__device__ __forceinline__ void cpa16(void* dst, const void* src){
    unsigned d = (unsigned)__cvta_generic_to_shared(dst);
    asm volatile("cp.async.cg.shared.global [%0], [%1], 16;" :: "r"(d), "l"(src));
}
__device__ __forceinline__ void cpa4(void* dst, const void* src){
    unsigned d = (unsigned)__cvta_generic_to_shared(dst);
    asm volatile("cp.async.ca.shared.global [%0], [%1], 4;" :: "r"(d), "l"(src));
}
#define CP_COMMIT() asm volatile("cp.async.commit_group;")
#define CP_WAIT0()  asm volatile("cp.async.wait_group 0;")
#define CP_WAIT1()  asm volatile("cp.async.wait_group 1;")

// ---------------- kernel 1: fused prepass ----------------
__global__ void prepass(const int* __restrict__ qx, const float* __restrict__ sx,
                        const float* __restrict__ meanp, const float* __restrict__ rstdp,
                        const float* __restrict__ lnw,
                        const float* __restrict__ w1, const float* __restrict__ w2){
    int bid = blockIdx.x, t = threadIdx.x;
    int c0 = t << 2;
    if (bid < BTn){
        int r = bid;
        int4 qv = *(const int4*)(qx + r*Cn + c0);
        float sxv = sx[r*32 + (c0 >> 5)];
        float mu = meanp[r], rs = rstdp[r];
        float4 wv = *(const float4*)(lnw + c0);
        float h0 = ((float)qv.x * sxv - mu) * rs * wv.x;
        float h1 = ((float)qv.y * sxv - mu) * rs * wv.y;
        float h2 = ((float)qv.z * sxv - mu) * rs * wv.z;
        float h3 = ((float)qv.w * sxv - mu) * rs * wv.w;
        float m = max8(fmaxf(fmaxf(fabsf(h0),fabsf(h1)), fmaxf(fabsf(h2),fabsf(h3))));
        float s = fmaxf(m * (1.0f/QMAXF), 1e-8f);
        float inv = 1.0f / s;
        g_qa[r*256 + t] = pack4(qclamp(h0,inv), qclamp(h1,inv), qclamp(h2,inv), qclamp(h3,inv));
        if ((t & 7) == 0) g_sa[(t>>3)*BTn + r] = s;
    } else {
        const float* w; int* qo; float* so; int r, nrows;
        if (bid < BTn + C3){ w = w1; qo = g_qw1; so = g_sw1; r = bid - BTn; nrows = C3; }
        else               { w = w2; qo = g_qw2; so = g_sw2; r = bid - BTn - C3; nrows = Cn; }
        float4 wv = *(const float4*)(w + (size_t)r*Cn + c0);
        float m = max8(fmaxf(fmaxf(fabsf(wv.x),fabsf(wv.y)), fmaxf(fabsf(wv.z),fabsf(wv.w))));
        float s = fmaxf(m * (1.0f/QMAXF), 1e-8f);
        float inv = 1.0f / s;
        qo[r*256 + t] = pack4(qclamp(wv.x,inv), qclamp(wv.y,inv), qclamp(wv.z,inv), qclamp(wv.w,inv));
        if ((t & 7) == 0) so[(t>>3)*nrows + r] = s;
    }
}

// ---------------- kernel 3: int8 tensor-core GEMM, 3-stage cp.async pipeline ----------------
__global__ __launch_bounds__(256,2) void gemm_imma(int which){
    const int* Aq; const float* sA; const int* Bq; const float* sB; float* Cm; int N;
    if (which == 0){ Aq=g_qa; sA=g_sa; Bq=g_qw1; sB=g_sw1; Cm=g_qkv;  N=C3; }
    else           { Aq=g_qy; sA=g_sy; Bq=g_qw2; sB=g_sw2; Cm=g_proj; N=Cn; }

    __shared__ __align__(16) int As[3][128][12];
    __shared__ __align__(16) int Bs[3][128][12];
    __shared__ float sAs[3][128];
    __shared__ __align__(8) float sBs[3][128];

    int tid = threadIdx.x, lane = tid & 31, wp = tid >> 5;
    int wM = wp >> 2, wN = wp & 3;
    int bm = blockIdx.y << 7, bn = blockIdx.x << 7;
    int lr = tid >> 1, lw = (tid & 1) << 2;

    #define LOAD_STAGE(st, g) do { \
        cpa16(&As[st][lr][lw], Aq + (bm + lr)*256 + (g)*8 + lw); \
        cpa16(&Bs[st][lr][lw], Bq + (bn + lr)*256 + (g)*8 + lw); \
        if (tid < 128) cpa4(&sAs[st][tid], sA + (g)*BTn + bm + tid); \
        else           cpa4(&sBs[st][tid-128], sB + (g)*N + bn + tid - 128); \
        CP_COMMIT(); \
    } while(0)

    LOAD_STAGE(0, 0);
    LOAD_STAGE(1, 1);

    unsigned long long accp[4][4][2];
#pragma unroll
    for (int i=0;i<4;i++)
#pragma unroll
        for (int j=0;j<4;j++){ accp[i][j][0] = 0ull; accp[i][j][1] = 0ull; }

    const unsigned long long negM = packf2(-12582912.0f, -12582912.0f);
    int a_row = (lane & 15), a_wrd = (lane >> 4) << 2;
    int b_row = ((lane >> 4) << 3) + (lane & 7), b_wrd = ((lane >> 3) & 1) << 2;

    for (int g = 0; g < 32; g++){
        int st = g % 3;
        if (g < 30) CP_WAIT1(); else CP_WAIT0();
        __syncthreads();
        if (g + 2 < 32) LOAD_STAGE((g+2)%3, g+2);

        unsigned a[4][4], bf[2][4];
#pragma unroll
        for (int mc = 0; mc < 4; mc++)
            ldm_x4(a[mc], &As[st][wM*64 + mc*16 + a_row][a_wrd]);
#pragma unroll
        for (int p = 0; p < 2; p++)
            ldm_x4(bf[p], &Bs[st][wN*32 + p*16 + b_row][b_wrd]);

        unsigned long long sa2[8], sb2[4];
#pragma unroll
        for (int mc = 0; mc < 4; mc++){
            float s0 = sAs[st][wM*64 + mc*16 + (lane>>2)];
            float s1 = sAs[st][wM*64 + mc*16 + (lane>>2) + 8];
            sa2[2*mc]   = packf2(s0, s0);
            sa2[2*mc+1] = packf2(s1, s1);
        }
#pragma unroll
        for (int nc = 0; nc < 4; nc++)
            sb2[nc] = *(const unsigned long long*)&sBs[st][wN*32 + nc*8 + ((lane&3)<<1)];

#pragma unroll
        for (int mc = 0; mc < 4; mc++){
#pragma unroll
            for (int nc = 0; nc < 4; nc++){
                int d[4];
                imma16832m(d, a[mc], bf[nc>>1][(nc&1)*2], bf[nc>>1][(nc&1)*2+1]);
                unsigned long long f0 = addf2(pack2i(d[0], d[1]), negM);
                unsigned long long f1 = addf2(pack2i(d[2], d[3]), negM);
                accp[mc][nc][0] = fmaf2(mulf2(f0, sa2[2*mc  ]), sb2[nc], accp[mc][nc][0]);
                accp[mc][nc][1] = fmaf2(mulf2(f1, sa2[2*mc+1]), sb2[nc], accp[mc][nc][1]);
            }
        }
    }
#pragma unroll
    for (int mc = 0; mc < 4; mc++){
#pragma unroll
        for (int nc = 0; nc < 4; nc++){
            int row0 = bm + wM*64 + mc*16 + (lane>>2);
            int col  = bn + wN*32 + nc*8 + ((lane&3)<<1);
            float x0,y0,x1,y1;
            unpackf2(accp[mc][nc][0], x0, y0);
            unpackf2(accp[mc][nc][1], x1, y1);
            *(float2*)(Cm + (size_t)row0*N + col)     = make_float2(x0, y0);
            *(float2*)(Cm + (size_t)(row0+8)*N + col) = make_float2(x1, y1);
        }
    }
    #undef LOAD_STAGE
}

// ---------------- kernel 3.5: K/V -> bf16 hi/lo precompute (V transposed) ----------------
__global__ __launch_bounds__(256) void qkv_convert(){
    __shared__ float Vs[64][65];
    int kt = blockIdx.x, hh = blockIdx.y, b = blockIdx.z;
    int tid = threadIdx.x;
    int ks = kt << 6;
    int bh = b*Hn + hh;
    const float* base = g_qkv + (size_t)(b*Tn)*C3 + hh*HDn;
    unsigned kbase = bh*65536;

#pragma unroll
    for (int it = 0; it < 4; it++){
        int idx = tid + it*256;
        int row = idx >> 4, d4 = (idx & 15) << 2;
        float4 v = *(const float4*)(base + (size_t)(ks+row)*C3 + Cn + d4);
        unsigned h0,l0,h1,l1;
        split2(v.x, v.y, h0, l0);
        split2(v.z, v.w, h1, l1);
        unsigned wd = kbase + (ks+row)*32 + (d4>>1);
        gKH[wd] = h0; gKH[wd+1] = h1;
        gKL[wd] = l0; gKL[wd+1] = l1;
    }
#pragma unroll
    for (int it = 0; it < 4; it++){
        int idx = tid + it*256;
        int row = idx >> 4, d4 = (idx & 15) << 2;
        float4 v = *(const float4*)(base + (size_t)(ks+row)*C3 + 2*Cn + d4);
        Vs[row][d4] = v.x; Vs[row][d4+1] = v.y; Vs[row][d4+2] = v.z; Vs[row][d4+3] = v.w;
    }
    __syncthreads();
#pragma unroll
    for (int it = 0; it < 8; it++){
        int idx = tid + it*256;
        int d = idx >> 5, kwl = idx & 31;
        float v0 = Vs[2*kwl  ][d];
        float v1 = Vs[2*kwl+1][d];
        unsigned h, l;
        split2(v0, v1, h, l);
        unsigned wd = kbase + d*1024 + (ks>>1) + kwl;
        gVH[wd] = h; gVL[wd] = l;
    }
}

// ---------------- kernel 4: flash attention, 32-key tiles, no spills ----------------
__global__ __launch_bounds__(256,2) void attn_kernel(){
    extern __shared__ unsigned sm[];   // 2 stages x STAGEW words

    int qt = (gridDim.x - 1) - blockIdx.x;
    int hh = blockIdx.y, b = blockIdx.z;
    int tid = threadIdx.x, w = tid >> 5, lane = tid & 31;
    int g = lane >> 2, tig = lane & 3;
    int qs = qt << 7, qb = w << 4;
    const float* base = g_qkv + (size_t)(b*Tn)*C3 + hh*HDn;
    int bh = b*Hn + hh;
    unsigned kbase = bh*65536;
    const float SCALE = 0.125f * 1.44269504088896f;
    int r0 = qs + qb + g, r1 = r0 + 8;

    unsigned aqh[4][4], aql[4][4];
#pragma unroll
    for (int dk=0; dk<4; dk++){
        const float* p0 = base + (size_t)r0*C3 + 16*dk + 2*tig;
        const float* p1 = base + (size_t)r1*C3 + 16*dk + 2*tig;
        float2 v00 = *(const float2*)(p0);
        float2 v01 = *(const float2*)(p0 + 8);
        float2 v10 = *(const float2*)(p1);
        float2 v11 = *(const float2*)(p1 + 8);
        split2(v00.x*SCALE, v00.y*SCALE, aqh[dk][0], aql[dk][0]);
        split2(v10.x*SCALE, v10.y*SCALE, aqh[dk][1], aql[dk][1]);
        split2(v01.x*SCALE, v01.y*SCALE, aqh[dk][2], aql[dk][2]);
        split2(v11.x*SCALE, v11.y*SCALE, aqh[dk][3], aql[dk][3]);
    }

    float o[8][4];
#pragma unroll
    for (int n=0;n<8;n++){ o[n][0]=0.f; o[n][1]=0.f; o[n][2]=0.f; o[n][3]=0.f; }
    float m0 = -INFINITY, m1 = -INFINITY, l0s = 0.f, l1s = 0.f;

    int ntiles = (qs + 128) >> 5;      // 32-key tiles

    // K: 32 rows x 32 words (8 chunks); V: 64 rows x 16 words (4 chunks)
    #define TILE_LOAD(stg, kss) do { \
        unsigned* S = sm + (stg)*STAGEW; \
        { int row = tid >> 3, ch = (tid & 7) << 2; \
          cpa16(&S[KH_OFF + row*QW + ch], &gKH[kbase + ((kss)+row)*32 + ch]); \
          cpa16(&S[KL_OFF + row*QW + ch], &gKL[kbase + ((kss)+row)*32 + ch]); } \
        { int row = tid >> 2, ch = (tid & 3) << 2; \
          cpa16(&S[VH_OFF + row*QW + ch], &gVH[kbase + row*1024 + ((kss)>>1) + ch]); \
          cpa16(&S[VL_OFF + row*QW + ch], &gVL[kbase + row*1024 + ((kss)>>1) + ch]); } \
        CP_COMMIT(); \
    } while(0)

    TILE_LOAD(0, 0);

    for (int kt = 0; kt < ntiles; kt++){
        int ks = kt << 5;
        int st = kt & 1;
        if (kt + 1 < ntiles){ TILE_LOAD(st^1, ks + 32); CP_WAIT1(); }
        else                { CP_WAIT0(); }
        __syncthreads();

        const unsigned* KH = sm + st*STAGEW + KH_OFF;
        const unsigned* KL = sm + st*STAGEW + KL_OFF;
        const unsigned* VH = sm + st*STAGEW + VH_OFF;
        const unsigned* VL = sm + st*STAGEW + VL_OFF;

        float s[4][4];
#pragma unroll
        for (int n=0;n<4;n++){ s[n][0]=0.f; s[n][1]=0.f; s[n][2]=0.f; s[n][3]=0.f; }
#pragma unroll
        for (int dk = 0; dk < 4; dk++){
#pragma unroll
            for (int n = 0; n < 4; n++){
                int kb = (8*n+g)*QW + 8*dk + tig;
                unsigned bh0 = KH[kb], bh1 = KH[kb+4];
                unsigned bl0 = KL[kb], bl1 = KL[kb+4];
                mma16816(s[n], aqh[dk], bh0, bh1);
                mma16816(s[n], aql[dk], bh0, bh1);
                mma16816(s[n], aqh[dk], bl0, bl1);
            }
        }
        float mx0 = -INFINITY, mx1 = -INFINITY;
#pragma unroll
        for (int n = 0; n < 4; n++){
            int c0 = ks + 8*n + 2*tig, c1 = c0 + 1;
            if (c0 > r0) s[n][0] = -1e30f;
            if (c1 > r0) s[n][1] = -1e30f;
            if (c0 > r1) s[n][2] = -1e30f;
            if (c1 > r1) s[n][3] = -1e30f;
            mx0 = fmaxf(mx0, fmaxf(s[n][0], s[n][1]));
            mx1 = fmaxf(mx1, fmaxf(s[n][2], s[n][3]));
        }
        mx0 = fmaxf(mx0, __shfl_xor_sync(0xffffffffu, mx0, 1));
        mx0 = fmaxf(mx0, __shfl_xor_sync(0xffffffffu, mx0, 2));
        mx1 = fmaxf(mx1, __shfl_xor_sync(0xffffffffu, mx1, 1));
        mx1 = fmaxf(mx1, __shfl_xor_sync(0xffffffffu, mx1, 2));
        float mn0 = fmaxf(m0, mx0), mn1 = fmaxf(m1, mx1);
        float al0 = ex2f(m0 - mn0), al1 = ex2f(m1 - mn1);
        m0 = mn0; m1 = mn1;
        float rs0 = 0.f, rs1 = 0.f;
#pragma unroll
        for (int n = 0; n < 4; n++){
            s[n][0] = ex2f(s[n][0] - m0);
            s[n][1] = ex2f(s[n][1] - m0);
            s[n][2] = ex2f(s[n][2] - m1);
            s[n][3] = ex2f(s[n][3] - m1);
            rs0 += s[n][0] + s[n][1];
            rs1 += s[n][2] + s[n][3];
        }
        rs0 += __shfl_xor_sync(0xffffffffu, rs0, 1);
        rs0 += __shfl_xor_sync(0xffffffffu, rs0, 2);
        rs1 += __shfl_xor_sync(0xffffffffu, rs1, 1);
        rs1 += __shfl_xor_sync(0xffffffffu, rs1, 2);
        l0s = l0s*al0 + rs0;
        l1s = l1s*al1 + rs1;
#pragma unroll
        for (int n = 0; n < 8; n++){
            o[n][0] *= al0; o[n][1] *= al0;
            o[n][2] *= al1; o[n][3] *= al1;
        }
#pragma unroll
        for (int kc = 0; kc < 2; kc++){
            unsigned ph[4], pl[4];
            split2(s[2*kc  ][0], s[2*kc  ][1], ph[0], pl[0]);
            split2(s[2*kc  ][2], s[2*kc  ][3], ph[1], pl[1]);
            split2(s[2*kc+1][0], s[2*kc+1][1], ph[2], pl[2]);
            split2(s[2*kc+1][2], s[2*kc+1][3], ph[3], pl[3]);
#pragma unroll
            for (int nd = 0; nd < 8; nd++){
                int kb = (8*nd+g)*QW + 8*kc + tig;
                unsigned bh0 = VH[kb], bh1 = VH[kb+4];
                unsigned bl0 = VL[kb], bl1 = VL[kb+4];
                mma16816(o[nd], ph, bh0, bh1);
                mma16816(o[nd], pl, bh0, bh1);
                mma16816(o[nd], ph, bl0, bl1);
            }
        }
        __syncthreads();
    }
    #undef TILE_LOAD

    float inv0 = 1.0f / l0s, inv1 = 1.0f / l1s;
    float gm00=0.f, gm01=0.f, gm10=0.f, gm11=0.f;
#pragma unroll
    for (int nd = 0; nd < 8; nd++){
        float a0 = fabsf(o[nd][0]*inv0), a1 = fabsf(o[nd][1]*inv0);
        float b0 = fabsf(o[nd][2]*inv1), b1 = fabsf(o[nd][3]*inv1);
        if (nd < 4){ gm00 = fmaxf(gm00, fmaxf(a0,a1)); gm10 = fmaxf(gm10, fmaxf(b0,b1)); }
        else       { gm01 = fmaxf(gm01, fmaxf(a0,a1)); gm11 = fmaxf(gm11, fmaxf(b0,b1)); }
    }
#pragma unroll
    for (int off = 1; off <= 2; off <<= 1){
        gm00 = fmaxf(gm00, __shfl_xor_sync(0xffffffffu, gm00, off));
        gm01 = fmaxf(gm01, __shfl_xor_sync(0xffffffffu, gm01, off));
        gm10 = fmaxf(gm10, __shfl_xor_sync(0xffffffffu, gm10, off));
        gm11 = fmaxf(gm11, __shfl_xor_sync(0xffffffffu, gm11, off));
    }
    float sq00 = fmaxf(gm00*(1.0f/QMAXF), 1e-8f), sq01 = fmaxf(gm01*(1.0f/QMAXF), 1e-8f);
    float sq10 = fmaxf(gm10*(1.0f/QMAXF), 1e-8f), sq11 = fmaxf(gm11*(1.0f/QMAXF), 1e-8f);
    int row0 = b*Tn + r0, row1 = b*Tn + r1;
#pragma unroll
    for (int nd = 0; nd < 8; nd++){
        float is0 = (nd<4) ? 1.0f/sq00 : 1.0f/sq01;
        float is1 = (nd<4) ? 1.0f/sq10 : 1.0f/sq11;
        int q0 = (int)qclamp(o[nd][0]*inv0, is0), q1 = (int)qclamp(o[nd][1]*inv0, is0);
        int q2 = (int)qclamp(o[nd][2]*inv1, is1), q3 = (int)qclamp(o[nd][3]*inv1, is1);
        int sh0 = (q0&0xFF) | ((q1&0xFF)<<8);
        int sh1 = (q2&0xFF) | ((q3&0xFF)<<8);
        int ot0 = __shfl_down_sync(0xffffffffu, sh0, 1);
        int ot1 = __shfl_down_sync(0xffffffffu, sh1, 1);
        if (!(tig & 1)){
            int wi = hh*16 + nd*2 + (tig>>1);
            g_qy[row0*256 + wi] = (sh0&0xFFFF) | (ot0<<16);
            g_qy[row1*256 + wi] = (sh1&0xFFFF) | (ot1<<16);
        }
    }
    if (tig == 0){
        g_sy[(hh*2  )*BTn + row0] = sq00;
        g_sy[(hh*2  )*BTn + row1] = sq10;
    }
    if (tig == 1){
        g_sy[(hh*2+1)*BTn + row0] = sq01;
        g_sy[(hh*2+1)*BTn + row1] = sq11;
    }
}

// ---------------- kernel 5: residual + stats + quant, single-pass ----------------
__global__ void final_kernel(const float* __restrict__ x, float* __restrict__ out, long long osz){
    __shared__ float red[8], redq[8], bc[2];
    int r = blockIdx.x, t = threadIdx.x;
    int c0 = t << 2;
    float4 xv = *(const float4*)(x + (size_t)r*Cn + c0);
    float4 pv = *(const float4*)(g_proj + (size_t)r*Cn + c0);
    float v0 = xv.x + pv.x, v1 = xv.y + pv.y, v2 = xv.z + pv.z, v3 = xv.w + pv.w;

    float sum = (v0 + v1) + (v2 + v3);
    float sq  = v0*v0 + v1*v1 + v2*v2 + v3*v3;
    sum = warp_sum(sum);
    sq  = warp_sum(sq);
    if ((t & 31) == 0){ red[t>>5] = sum; redq[t>>5] = sq; }
    __syncthreads();
    if (t < 32){
        float a = (t < 8) ? red[t]  : 0.f;
        float b = (t < 8) ? redq[t] : 0.f;
#pragma unroll
        for (int o=4;o;o>>=1){ a += __shfl_xor_sync(0xffffffffu, a, o); b += __shfl_xor_sync(0xffffffffu, b, o); }
        if (t == 0){
            float mu = a * (1.0f/Cn);
            float var = b * (1.0f/Cn) - mu*mu;
            bc[0] = mu;
            bc[1] = 1.0f / sqrtf(var + 1e-5f);
        }
    }
    __syncthreads();
    float mu = bc[0], rst = bc[1];

    *(float4*)(out + (size_t)r*Cn + c0) = make_float4(v0, v1, v2, v3);
    float m = max8(fmaxf(fmaxf(fabsf(v0),fabsf(v1)), fmaxf(fabsf(v2),fabsf(v3))));
    float s = fmaxf(m * (1.0f/QMAXF), 1e-8f);
    float inv = 1.0f / s;
    long long oq = (long long)BTn*Cn + (long long)r*Cn + c0;
    if (oq + 3 < osz)
        *(float4*)(out + oq) = make_float4(qclamp(v0,inv), qclamp(v1,inv), qclamp(v2,inv), qclamp(v3,inv));
    if ((t & 7) == 0){
        long long os = 2LL*BTn*Cn + (long long)r*32 + (t>>3);
        if (os < osz) out[os] = s;
    }
    if (t == 0){
        long long om = 2LL*BTn*Cn + 32LL*BTn + r;
        if (om < osz)        out[om]       = mu;
        if (om + BTn < osz)  out[om + BTn] = rst;
    }
}

// ---------------- launch ----------------
extern "C" void kernel_launch(void* const* d_in, const int* in_sizes, int n_in,
                              void* d_out, int out_size){
    const float* x     = (const float*)d_in[0];
    const int*   qx    = (const int*)  d_in[1];
    const float* sx    = (const float*)d_in[2];
    const float* meanp = (const float*)d_in[3];
    const float* rstdp = (const float*)d_in[4];
    const float* lnw   = (const float*)d_in[5];
    const float* w1    = (const float*)d_in[6];
    const float* w2    = (const float*)d_in[7];
    float* out = (float*)d_out;

    const int ATTN_SMEM = 2 * STAGEW * 4;   // 55296 bytes
    cudaFuncSetAttribute(attn_kernel, cudaFuncAttributeMaxDynamicSharedMemorySize, ATTN_SMEM);

    prepass<<<BTn + C3 + Cn, 256>>>(qx, sx, meanp, rstdp, lnw, w1, w2);
    gemm_imma<<<dim3(C3/128, BTn/128), 256>>>(0);
    qkv_convert<<<dim3(Tn/64, Hn, Bn), 256>>>();
    attn_kernel<<<dim3(Tn/128, Hn, Bn), 256, ATTN_SMEM>>>();
    gemm_imma<<<dim3(Cn/128, BTn/128), 256>>>(1);
    final_kernel<<<BTn, 256>>>(x, out, (long long)out_size);
}

// round 13
// speedup vs baseline: 1.1332x; 1.0434x over previous
#include <cuda_runtime.h>
#include <cuda_bf16.h>
#include <math.h>

#define Bn   2
#define Tn   2048
#define Cn   1024
#define Hn   16
#define HDn  64
#define BTn  (Bn*Tn)
#define QMAXF 127.0f
#define C3   3072
#define QW   36
#define KH_OFF 0
#define KL_OFF (32*QW)
#define VH_OFF (64*QW)
#define VL_OFF (128*QW)
#define STAGEW (192*QW)     // 6912 words = 27648 B

// ---------------- scratch ----------------
__device__ int   g_qa [BTn*256];
__device__ float g_sa [32*BTn];
__device__ int   g_qw1[3*Cn*256];
__device__ float g_sw1[32*3*Cn];
__device__ int   g_qw2[Cn*256];
__device__ float g_sw2[32*Cn];
__device__ float g_qkv[(size_t)BTn*C3];
__device__ int   g_qy [BTn*256];
__device__ float g_sy [32*BTn];
__device__ float g_proj[(size_t)BTn*Cn];
__device__ unsigned gKH[Bn*Hn*65536], gKL[Bn*Hn*65536];
__device__ unsigned gVH[Bn*Hn*65536], gVL[Bn*Hn*65536];

__device__ __forceinline__ float warp_sum(float v){
#pragma unroll
    for (int o=16;o;o>>=1) v += __shfl_xor_sync(0xffffffffu, v, o);
    return v;
}
__device__ __forceinline__ float max8(float v){
#pragma unroll
    for (int o=4;o;o>>=1) v = fmaxf(v, __shfl_xor_sync(0xffffffffu, v, o));
    return v;
}
__device__ __forceinline__ int pack4(float a, float b, float c, float d){
    int i0=(int)a, i1=(int)b, i2=(int)c, i3=(int)d;
    return (i0&0xFF) | ((i1&0xFF)<<8) | ((i2&0xFF)<<16) | (i3<<24);
}
__device__ __forceinline__ float qclamp(float h, float inv_s){
    float q = rintf(h * inv_s);
    return fminf(fmaxf(q, -QMAXF), QMAXF);
}
__device__ __forceinline__ float ex2f(float x){
    float y; asm("ex2.approx.f32 %0, %1;" : "=f"(y) : "f"(x)); return y;
}
__device__ __forceinline__ unsigned pbf2(float x, float y){
    __nv_bfloat162 h = __floats2bfloat162_rn(x, y);
    return *(unsigned*)&h;
}
__device__ __forceinline__ void split2(float x, float y, unsigned &hi, unsigned &lo){
    unsigned h = pbf2(x, y);
    __nv_bfloat162 hb = *(__nv_bfloat162*)&h;
    hi = h;
    lo = pbf2(x - __bfloat162float(hb.x), y - __bfloat162float(hb.y));
}
__device__ __forceinline__ void mma16816(float* d, const unsigned* a, unsigned b0, unsigned b1){
    asm volatile("mma.sync.aligned.m16n8k16.row.col.f32.bf16.bf16.f32 "
        "{%0,%1,%2,%3},{%4,%5,%6,%7},{%8,%9},{%0,%1,%2,%3};"
        : "+f"(d[0]),"+f"(d[1]),"+f"(d[2]),"+f"(d[3])
        : "r"(a[0]),"r"(a[1]),"r"(a[2]),"r"(a[3]), "r"(b0),"r"(b1));
}
__device__ __forceinline__ void imma16832m(int* d, const unsigned* a, unsigned b0, unsigned b1){
    asm volatile("mma.sync.aligned.m16n8k32.row.col.s32.s8.s8.s32 "
        "{%0,%1,%2,%3},{%4,%5,%6,%7},{%8,%9},{%10,%11,%12,%13};"
        : "=r"(d[0]),"=r"(d[1]),"=r"(d[2]),"=r"(d[3])
        : "r"(a[0]),"r"(a[1]),"r"(a[2]),"r"(a[3]), "r"(b0),"r"(b1),
          "r"(0x4B400000),"r"(0x4B400000),"r"(0x4B400000),"r"(0x4B400000));
}
__device__ __forceinline__ void ldm_x4(unsigned* r, const void* p){
    unsigned ad = (unsigned)__cvta_generic_to_shared(p);
    asm volatile("ldmatrix.sync.aligned.m8n8.x4.shared.b16 {%0,%1,%2,%3}, [%4];"
        : "=r"(r[0]),"=r"(r[1]),"=r"(r[2]),"=r"(r[3]) : "r"(ad));
}
__device__ __forceinline__ void ldm_x4u(unsigned* r, unsigned ad){
    asm volatile("ldmatrix.sync.aligned.m8n8.x4.shared.b16 {%0,%1,%2,%3}, [%4];"
        : "=r"(r[0]),"=r"(r[1]),"=r"(r[2]),"=r"(r[3]) : "r"(ad));
}
__device__ __forceinline__ unsigned long long packf2(float x, float y){
    unsigned long long r; asm("mov.b64 %0, {%1,%2};" : "=l"(r) : "f"(x),"f"(y)); return r;
}
__device__ __forceinline__ unsigned long long pack2i(int x, int y){
    unsigned long long r; asm("mov.b64 %0, {%1,%2};" : "=l"(r) : "r"(x),"r"(y)); return r;
}
__device__ __forceinline__ void unpackf2(unsigned long long v, float &x, float &y){
    asm("mov.b64 {%0,%1}, %2;" : "=f"(x),"=f"(y) : "l"(v));
}
__device__ __forceinline__ unsigned long long addf2(unsigned long long a, unsigned long long b){
    unsigned long long r; asm("add.rn.f32x2 %0, %1, %2;" : "=l"(r) : "l"(a),"l"(b)); return r;
}
__device__ __forceinline__ unsigned long long mulf2(unsigned long long a, unsigned long long b){
    unsigned long long r; asm("mul.rn.f32x2 %0, %1, %2;" : "=l"(r) : "l"(a),"l"(b)); return r;
}
__device__ __forceinline__ unsigned long long fmaf2(unsigned long long a, unsigned long long b, unsigned long long c){
    unsigned long long r; asm("fma.rn.f32x2 %0, %1, %2, %3;" : "=l"(r) : "l"(a),"l"(b),"l"(c)); return r;
}
__device__ __forceinline__ void cpa16(void* dst, const void* src){
    unsigned d = (unsigned)__cvta_generic_to_shared(dst);
    asm volatile("cp.async.cg.shared.global [%0], [%1], 16;" :: "r"(d), "l"(src));
}
__device__ __forceinline__ void cpa4(void* dst, const void* src){
    unsigned d = (unsigned)__cvta_generic_to_shared(dst);
    asm volatile("cp.async.ca.shared.global [%0], [%1], 4;" :: "r"(d), "l"(src));
}
#define CP_COMMIT() asm volatile("cp.async.commit_group;")
#define CP_WAIT0()  asm volatile("cp.async.wait_group 0;")
#define CP_WAIT1()  asm volatile("cp.async.wait_group 1;")

// ---------------- kernel 1: fused prepass ----------------
__global__ void prepass(const int* __restrict__ qx, const float* __restrict__ sx,
                        const float* __restrict__ meanp, const float* __restrict__ rstdp,
                        const float* __restrict__ lnw,
                        const float* __restrict__ w1, const float* __restrict__ w2){
    int bid = blockIdx.x, t = threadIdx.x;
    int c0 = t << 2;
    if (bid < BTn){
        int r = bid;
        int4 qv = *(const int4*)(qx + r*Cn + c0);
        float sxv = sx[r*32 + (c0 >> 5)];
        float mu = meanp[r], rs = rstdp[r];
        float4 wv = *(const float4*)(lnw + c0);
        float h0 = ((float)qv.x * sxv - mu) * rs * wv.x;
        float h1 = ((float)qv.y * sxv - mu) * rs * wv.y;
        float h2 = ((float)qv.z * sxv - mu) * rs * wv.z;
        float h3 = ((float)qv.w * sxv - mu) * rs * wv.w;
        float m = max8(fmaxf(fmaxf(fabsf(h0),fabsf(h1)), fmaxf(fabsf(h2),fabsf(h3))));
        float s = fmaxf(m * (1.0f/QMAXF), 1e-8f);
        float inv = 1.0f / s;
        g_qa[r*256 + t] = pack4(qclamp(h0,inv), qclamp(h1,inv), qclamp(h2,inv), qclamp(h3,inv));
        if ((t & 7) == 0) g_sa[(t>>3)*BTn + r] = s;
    } else {
        const float* w; int* qo; float* so; int r, nrows;
        if (bid < BTn + C3){ w = w1; qo = g_qw1; so = g_sw1; r = bid - BTn; nrows = C3; }
        else               { w = w2; qo = g_qw2; so = g_sw2; r = bid - BTn - C3; nrows = Cn; }
        float4 wv = *(const float4*)(w + (size_t)r*Cn + c0);
        float m = max8(fmaxf(fmaxf(fabsf(wv.x),fabsf(wv.y)), fmaxf(fabsf(wv.z),fabsf(wv.w))));
        float s = fmaxf(m * (1.0f/QMAXF), 1e-8f);
        float inv = 1.0f / s;
        qo[r*256 + t] = pack4(qclamp(wv.x,inv), qclamp(wv.y,inv), qclamp(wv.z,inv), qclamp(wv.w,inv));
        if ((t & 7) == 0) so[(t>>3)*nrows + r] = s;
    }
}

// ---------------- kernel 3: int8 tensor-core GEMM, 3-stage cp.async pipeline ----------------
__global__ __launch_bounds__(256,2) void gemm_imma(int which){
    const int* Aq; const float* sA; const int* Bq; const float* sB; float* Cm; int N;
    if (which == 0){ Aq=g_qa; sA=g_sa; Bq=g_qw1; sB=g_sw1; Cm=g_qkv;  N=C3; }
    else           { Aq=g_qy; sA=g_sy; Bq=g_qw2; sB=g_sw2; Cm=g_proj; N=Cn; }

    __shared__ __align__(16) int As[3][128][12];
    __shared__ __align__(16) int Bs[3][128][12];
    __shared__ float sAs[3][128];
    __shared__ __align__(8) float sBs[3][128];

    int tid = threadIdx.x, lane = tid & 31, wp = tid >> 5;
    int wM = wp >> 2, wN = wp & 3;
    int bm = blockIdx.y << 7, bn = blockIdx.x << 7;
    int lr = tid >> 1, lw = (tid & 1) << 2;

    #define LOAD_STAGE(st, g) do { \
        cpa16(&As[st][lr][lw], Aq + (bm + lr)*256 + (g)*8 + lw); \
        cpa16(&Bs[st][lr][lw], Bq + (bn + lr)*256 + (g)*8 + lw); \
        if (tid < 128) cpa4(&sAs[st][tid], sA + (g)*BTn + bm + tid); \
        else           cpa4(&sBs[st][tid-128], sB + (g)*N + bn + tid - 128); \
        CP_COMMIT(); \
    } while(0)

    LOAD_STAGE(0, 0);
    LOAD_STAGE(1, 1);

    unsigned long long accp[4][4][2];
#pragma unroll
    for (int i=0;i<4;i++)
#pragma unroll
        for (int j=0;j<4;j++){ accp[i][j][0] = 0ull; accp[i][j][1] = 0ull; }

    const unsigned long long negM = packf2(-12582912.0f, -12582912.0f);
    int a_row = (lane & 15), a_wrd = (lane >> 4) << 2;
    int b_row = ((lane >> 4) << 3) + (lane & 7), b_wrd = ((lane >> 3) & 1) << 2;

    for (int g = 0; g < 32; g++){
        int st = g % 3;
        if (g < 30) CP_WAIT1(); else CP_WAIT0();
        __syncthreads();
        if (g + 2 < 32) LOAD_STAGE((g+2)%3, g+2);

        unsigned a[4][4], bf[2][4];
#pragma unroll
        for (int mc = 0; mc < 4; mc++)
            ldm_x4(a[mc], &As[st][wM*64 + mc*16 + a_row][a_wrd]);
#pragma unroll
        for (int p = 0; p < 2; p++)
            ldm_x4(bf[p], &Bs[st][wN*32 + p*16 + b_row][b_wrd]);

        unsigned long long sa2[8], sb2[4];
#pragma unroll
        for (int mc = 0; mc < 4; mc++){
            float s0 = sAs[st][wM*64 + mc*16 + (lane>>2)];
            float s1 = sAs[st][wM*64 + mc*16 + (lane>>2) + 8];
            sa2[2*mc]   = packf2(s0, s0);
            sa2[2*mc+1] = packf2(s1, s1);
        }
#pragma unroll
        for (int nc = 0; nc < 4; nc++)
            sb2[nc] = *(const unsigned long long*)&sBs[st][wN*32 + nc*8 + ((lane&3)<<1)];

#pragma unroll
        for (int mc = 0; mc < 4; mc++){
#pragma unroll
            for (int nc = 0; nc < 4; nc++){
                int d[4];
                imma16832m(d, a[mc], bf[nc>>1][(nc&1)*2], bf[nc>>1][(nc&1)*2+1]);
                unsigned long long f0 = addf2(pack2i(d[0], d[1]), negM);
                unsigned long long f1 = addf2(pack2i(d[2], d[3]), negM);
                accp[mc][nc][0] = fmaf2(mulf2(f0, sa2[2*mc  ]), sb2[nc], accp[mc][nc][0]);
                accp[mc][nc][1] = fmaf2(mulf2(f1, sa2[2*mc+1]), sb2[nc], accp[mc][nc][1]);
            }
        }
    }
#pragma unroll
    for (int mc = 0; mc < 4; mc++){
#pragma unroll
        for (int nc = 0; nc < 4; nc++){
            int row0 = bm + wM*64 + mc*16 + (lane>>2);
            int col  = bn + wN*32 + nc*8 + ((lane&3)<<1);
            float x0,y0,x1,y1;
            unpackf2(accp[mc][nc][0], x0, y0);
            unpackf2(accp[mc][nc][1], x1, y1);
            *(float2*)(Cm + (size_t)row0*N + col)     = make_float2(x0, y0);
            *(float2*)(Cm + (size_t)(row0+8)*N + col) = make_float2(x1, y1);
        }
    }
    #undef LOAD_STAGE
}

// ---------------- kernel 3.5: K/V -> bf16 hi/lo precompute (V transposed) ----------------
__global__ __launch_bounds__(256) void qkv_convert(){
    __shared__ float Vs[64][65];
    int kt = blockIdx.x, hh = blockIdx.y, b = blockIdx.z;
    int tid = threadIdx.x;
    int ks = kt << 6;
    int bh = b*Hn + hh;
    const float* base = g_qkv + (size_t)(b*Tn)*C3 + hh*HDn;
    unsigned kbase = bh*65536;

#pragma unroll
    for (int it = 0; it < 4; it++){
        int idx = tid + it*256;
        int row = idx >> 4, d4 = (idx & 15) << 2;
        float4 v = *(const float4*)(base + (size_t)(ks+row)*C3 + Cn + d4);
        unsigned h0,l0,h1,l1;
        split2(v.x, v.y, h0, l0);
        split2(v.z, v.w, h1, l1);
        unsigned wd = kbase + (ks+row)*32 + (d4>>1);
        gKH[wd] = h0; gKH[wd+1] = h1;
        gKL[wd] = l0; gKL[wd+1] = l1;
    }
#pragma unroll
    for (int it = 0; it < 4; it++){
        int idx = tid + it*256;
        int row = idx >> 4, d4 = (idx & 15) << 2;
        float4 v = *(const float4*)(base + (size_t)(ks+row)*C3 + 2*Cn + d4);
        Vs[row][d4] = v.x; Vs[row][d4+1] = v.y; Vs[row][d4+2] = v.z; Vs[row][d4+3] = v.w;
    }
    __syncthreads();
#pragma unroll
    for (int it = 0; it < 8; it++){
        int idx = tid + it*256;
        int d = idx >> 5, kwl = idx & 31;
        float v0 = Vs[2*kwl  ][d];
        float v1 = Vs[2*kwl+1][d];
        unsigned h, l;
        split2(v0, v1, h, l);
        unsigned wd = kbase + d*1024 + (ks>>1) + kwl;
        gVH[wd] = h; gVL[wd] = l;
    }
}

// ---------------- kernel 4: flash attention, ldmatrix fragments ----------------
__global__ __launch_bounds__(256,2) void attn_kernel(){
    extern __shared__ unsigned sm[];   // 2 stages x STAGEW words

    int qt = (gridDim.x - 1) - blockIdx.x;
    int hh = blockIdx.y, b = blockIdx.z;
    int tid = threadIdx.x, w = tid >> 5, lane = tid & 31;
    int g = lane >> 2, tig = lane & 3;
    int qs = qt << 7, qb = w << 4;
    const float* base = g_qkv + (size_t)(b*Tn)*C3 + hh*HDn;
    int bh = b*Hn + hh;
    unsigned kbase = bh*65536;
    const float SCALE = 0.125f * 1.44269504088896f;
    int r0 = qs + qb + g, r1 = r0 + 8;

    unsigned smem_base = (unsigned)__cvta_generic_to_shared(sm);
    int lm_m = lane >> 3, lm_r = lane & 7;
    unsigned laneB = (unsigned)(((8*(lm_m>>1) + lm_r)*QW + 4*(lm_m&1)) * 4);

    unsigned aqh[4][4], aql[4][4];
#pragma unroll
    for (int dk=0; dk<4; dk++){
        const float* p0 = base + (size_t)r0*C3 + 16*dk + 2*tig;
        const float* p1 = base + (size_t)r1*C3 + 16*dk + 2*tig;
        float2 v00 = *(const float2*)(p0);
        float2 v01 = *(const float2*)(p0 + 8);
        float2 v10 = *(const float2*)(p1);
        float2 v11 = *(const float2*)(p1 + 8);
        split2(v00.x*SCALE, v00.y*SCALE, aqh[dk][0], aql[dk][0]);
        split2(v10.x*SCALE, v10.y*SCALE, aqh[dk][1], aql[dk][1]);
        split2(v01.x*SCALE, v01.y*SCALE, aqh[dk][2], aql[dk][2]);
        split2(v11.x*SCALE, v11.y*SCALE, aqh[dk][3], aql[dk][3]);
    }

    float o[8][4];
#pragma unroll
    for (int n=0;n<8;n++){ o[n][0]=0.f; o[n][1]=0.f; o[n][2]=0.f; o[n][3]=0.f; }
    float m0 = -INFINITY, m1 = -INFINITY, l0s = 0.f, l1s = 0.f;

    int ntiles = (qs + 128) >> 5;

    #define TILE_LOAD(stg, kss) do { \
        unsigned* S = sm + (stg)*STAGEW; \
        { int row = tid >> 3, ch = (tid & 7) << 2; \
          cpa16(&S[KH_OFF + row*QW + ch], &gKH[kbase + ((kss)+row)*32 + ch]); \
          cpa16(&S[KL_OFF + row*QW + ch], &gKL[kbase + ((kss)+row)*32 + ch]); } \
        { int row = tid >> 2, ch = (tid & 3) << 2; \
          cpa16(&S[VH_OFF + row*QW + ch], &gVH[kbase + row*1024 + ((kss)>>1) + ch]); \
          cpa16(&S[VL_OFF + row*QW + ch], &gVL[kbase + row*1024 + ((kss)>>1) + ch]); } \
        CP_COMMIT(); \
    } while(0)

    TILE_LOAD(0, 0);

    for (int kt = 0; kt < ntiles; kt++){
        int ks = kt << 5;
        int st = kt & 1;
        if (kt + 1 < ntiles){ TILE_LOAD(st^1, ks + 32); CP_WAIT1(); }
        else                { CP_WAIT0(); }
        __syncthreads();

        unsigned stB = smem_base + (unsigned)(st*STAGEW*4);
        unsigned sKH = stB + KH_OFF*4 + laneB;
        unsigned sKL = stB + KL_OFF*4 + laneB;
        unsigned sVH = stB + VH_OFF*4 + laneB;
        unsigned sVL = stB + VL_OFF*4 + laneB;

        float s[4][4];
#pragma unroll
        for (int n=0;n<4;n++){ s[n][0]=0.f; s[n][1]=0.f; s[n][2]=0.f; s[n][3]=0.f; }
#pragma unroll
        for (int dk = 0; dk < 4; dk++){
#pragma unroll
            for (int np = 0; np < 2; np++){
                unsigned off = (unsigned)(((np<<4)*QW + (dk<<3)) * 4);
                unsigned kh[4], kl[4];
                ldm_x4u(kh, sKH + off);
                ldm_x4u(kl, sKL + off);
                mma16816(s[2*np  ], aqh[dk], kh[0], kh[1]);
                mma16816(s[2*np  ], aql[dk], kh[0], kh[1]);
                mma16816(s[2*np  ], aqh[dk], kl[0], kl[1]);
                mma16816(s[2*np+1], aqh[dk], kh[2], kh[3]);
                mma16816(s[2*np+1], aql[dk], kh[2], kh[3]);
                mma16816(s[2*np+1], aqh[dk], kl[2], kl[3]);
            }
        }
        float mx0 = -INFINITY, mx1 = -INFINITY;
#pragma unroll
        for (int n = 0; n < 4; n++){
            int c0 = ks + 8*n + 2*tig, c1 = c0 + 1;
            if (c0 > r0) s[n][0] = -1e30f;
            if (c1 > r0) s[n][1] = -1e30f;
            if (c0 > r1) s[n][2] = -1e30f;
            if (c1 > r1) s[n][3] = -1e30f;
            mx0 = fmaxf(mx0, fmaxf(s[n][0], s[n][1]));
            mx1 = fmaxf(mx1, fmaxf(s[n][2], s[n][3]));
        }
        mx0 = fmaxf(mx0, __shfl_xor_sync(0xffffffffu, mx0, 1));
        mx0 = fmaxf(mx0, __shfl_xor_sync(0xffffffffu, mx0, 2));
        mx1 = fmaxf(mx1, __shfl_xor_sync(0xffffffffu, mx1, 1));
        mx1 = fmaxf(mx1, __shfl_xor_sync(0xffffffffu, mx1, 2));
        float mn0 = fmaxf(m0, mx0), mn1 = fmaxf(m1, mx1);
        float al0 = ex2f(m0 - mn0), al1 = ex2f(m1 - mn1);
        m0 = mn0; m1 = mn1;
        float rs0 = 0.f, rs1 = 0.f;
#pragma unroll
        for (int n = 0; n < 4; n++){
            s[n][0] = ex2f(s[n][0] - m0);
            s[n][1] = ex2f(s[n][1] - m0);
            s[n][2] = ex2f(s[n][2] - m1);
            s[n][3] = ex2f(s[n][3] - m1);
            rs0 += s[n][0] + s[n][1];
            rs1 += s[n][2] + s[n][3];
        }
        rs0 += __shfl_xor_sync(0xffffffffu, rs0, 1);
        rs0 += __shfl_xor_sync(0xffffffffu, rs0, 2);
        rs1 += __shfl_xor_sync(0xffffffffu, rs1, 1);
        rs1 += __shfl_xor_sync(0xffffffffu, rs1, 2);
        l0s = l0s*al0 + rs0;
        l1s = l1s*al1 + rs1;
#pragma unroll
        for (int n = 0; n < 8; n++){
            o[n][0] *= al0; o[n][1] *= al0;
            o[n][2] *= al1; o[n][3] *= al1;
        }
#pragma unroll
        for (int kc = 0; kc < 2; kc++){
            unsigned ph[4], pl[4];
            split2(s[2*kc  ][0], s[2*kc  ][1], ph[0], pl[0]);
            split2(s[2*kc  ][2], s[2*kc  ][3], ph[1], pl[1]);
            split2(s[2*kc+1][0], s[2*kc+1][1], ph[2], pl[2]);
            split2(s[2*kc+1][2], s[2*kc+1][3], ph[3], pl[3]);
#pragma unroll
            for (int ndp = 0; ndp < 4; ndp++){
                unsigned off = (unsigned)(((ndp<<4)*QW + (kc<<3)) * 4);
                unsigned vh[4], vl[4];
                ldm_x4u(vh, sVH + off);
                ldm_x4u(vl, sVL + off);
                mma16816(o[2*ndp  ], ph, vh[0], vh[1]);
                mma16816(o[2*ndp  ], pl, vh[0], vh[1]);
                mma16816(o[2*ndp  ], ph, vl[0], vl[1]);
                mma16816(o[2*ndp+1], ph, vh[2], vh[3]);
                mma16816(o[2*ndp+1], pl, vh[2], vh[3]);
                mma16816(o[2*ndp+1], ph, vl[2], vl[3]);
            }
        }
        __syncthreads();
    }
    #undef TILE_LOAD

    float inv0 = 1.0f / l0s, inv1 = 1.0f / l1s;
    float gm00=0.f, gm01=0.f, gm10=0.f, gm11=0.f;
#pragma unroll
    for (int nd = 0; nd < 8; nd++){
        float a0 = fabsf(o[nd][0]*inv0), a1 = fabsf(o[nd][1]*inv0);
        float b0 = fabsf(o[nd][2]*inv1), b1 = fabsf(o[nd][3]*inv1);
        if (nd < 4){ gm00 = fmaxf(gm00, fmaxf(a0,a1)); gm10 = fmaxf(gm10, fmaxf(b0,b1)); }
        else       { gm01 = fmaxf(gm01, fmaxf(a0,a1)); gm11 = fmaxf(gm11, fmaxf(b0,b1)); }
    }
#pragma unroll
    for (int off = 1; off <= 2; off <<= 1){
        gm00 = fmaxf(gm00, __shfl_xor_sync(0xffffffffu, gm00, off));
        gm01 = fmaxf(gm01, __shfl_xor_sync(0xffffffffu, gm01, off));
        gm10 = fmaxf(gm10, __shfl_xor_sync(0xffffffffu, gm10, off));
        gm11 = fmaxf(gm11, __shfl_xor_sync(0xffffffffu, gm11, off));
    }
    float sq00 = fmaxf(gm00*(1.0f/QMAXF), 1e-8f), sq01 = fmaxf(gm01*(1.0f/QMAXF), 1e-8f);
    float sq10 = fmaxf(gm10*(1.0f/QMAXF), 1e-8f), sq11 = fmaxf(gm11*(1.0f/QMAXF), 1e-8f);
    int row0 = b*Tn + r0, row1 = b*Tn + r1;
#pragma unroll
    for (int nd = 0; nd < 8; nd++){
        float is0 = (nd<4) ? 1.0f/sq00 : 1.0f/sq01;
        float is1 = (nd<4) ? 1.0f/sq10 : 1.0f/sq11;
        int q0 = (int)qclamp(o[nd][0]*inv0, is0), q1 = (int)qclamp(o[nd][1]*inv0, is0);
        int q2 = (int)qclamp(o[nd][2]*inv1, is1), q3 = (int)qclamp(o[nd][3]*inv1, is1);
        int sh0 = (q0&0xFF) | ((q1&0xFF)<<8);
        int sh1 = (q2&0xFF) | ((q3&0xFF)<<8);
        int ot0 = __shfl_down_sync(0xffffffffu, sh0, 1);
        int ot1 = __shfl_down_sync(0xffffffffu, sh1, 1);
        if (!(tig & 1)){
            int wi = hh*16 + nd*2 + (tig>>1);
            g_qy[row0*256 + wi] = (sh0&0xFFFF) | (ot0<<16);
            g_qy[row1*256 + wi] = (sh1&0xFFFF) | (ot1<<16);
        }
    }
    if (tig == 0){
        g_sy[(hh*2  )*BTn + row0] = sq00;
        g_sy[(hh*2  )*BTn + row1] = sq10;
    }
    if (tig == 1){
        g_sy[(hh*2+1)*BTn + row0] = sq01;
        g_sy[(hh*2+1)*BTn + row1] = sq11;
    }
}

// ---------------- kernel 5: residual + stats + quant, single-pass ----------------
__global__ void final_kernel(const float* __restrict__ x, float* __restrict__ out, long long osz){
    __shared__ float red[8], redq[8], bc[2];
    int r = blockIdx.x, t = threadIdx.x;
    int c0 = t << 2;
    float4 xv = *(const float4*)(x + (size_t)r*Cn + c0);
    float4 pv = *(const float4*)(g_proj + (size_t)r*Cn + c0);
    float v0 = xv.x + pv.x, v1 = xv.y + pv.y, v2 = xv.z + pv.z, v3 = xv.w + pv.w;

    float sum = (v0 + v1) + (v2 + v3);
    float sq  = v0*v0 + v1*v1 + v2*v2 + v3*v3;
    sum = warp_sum(sum);
    sq  = warp_sum(sq);
    if ((t & 31) == 0){ red[t>>5] = sum; redq[t>>5] = sq; }
    __syncthreads();
    if (t < 32){
        float a = (t < 8) ? red[t]  : 0.f;
        float b = (t < 8) ? redq[t] : 0.f;
#pragma unroll
        for (int o=4;o;o>>=1){ a += __shfl_xor_sync(0xffffffffu, a, o); b += __shfl_xor_sync(0xffffffffu, b, o); }
        if (t == 0){
            float mu = a * (1.0f/Cn);
            float var = b * (1.0f/Cn) - mu*mu;
            bc[0] = mu;
            bc[1] = 1.0f / sqrtf(var + 1e-5f);
        }
    }
    __syncthreads();
    float mu = bc[0], rst = bc[1];

    *(float4*)(out + (size_t)r*Cn + c0) = make_float4(v0, v1, v2, v3);
    float m = max8(fmaxf(fmaxf(fabsf(v0),fabsf(v1)), fmaxf(fabsf(v2),fabsf(v3))));
    float s = fmaxf(m * (1.0f/QMAXF), 1e-8f);
    float inv = 1.0f / s;
    long long oq = (long long)BTn*Cn + (long long)r*Cn + c0;
    if (oq + 3 < osz)
        *(float4*)(out + oq) = make_float4(qclamp(v0,inv), qclamp(v1,inv), qclamp(v2,inv), qclamp(v3,inv));
    if ((t & 7) == 0){
        long long os = 2LL*BTn*Cn + (long long)r*32 + (t>>3);
        if (os < osz) out[os] = s;
    }
    if (t == 0){
        long long om = 2LL*BTn*Cn + 32LL*BTn + r;
        if (om < osz)        out[om]       = mu;
        if (om + BTn < osz)  out[om + BTn] = rst;
    }
}

// ---------------- launch ----------------
extern "C" void kernel_launch(void* const* d_in, const int* in_sizes, int n_in,
                              void* d_out, int out_size){
    const float* x     = (const float*)d_in[0];
    const int*   qx    = (const int*)  d_in[1];
    const float* sx    = (const float*)d_in[2];
    const float* meanp = (const float*)d_in[3];
    const float* rstdp = (const float*)d_in[4];
    const float* lnw   = (const float*)d_in[5];
    const float* w1    = (const float*)d_in[6];
    const float* w2    = (const float*)d_in[7];
    float* out = (float*)d_out;

    const int ATTN_SMEM = 2 * STAGEW * 4;   // 55296 bytes
    cudaFuncSetAttribute(attn_kernel, cudaFuncAttributeMaxDynamicSharedMemorySize, ATTN_SMEM);

    prepass<<<BTn + C3 + Cn, 256>>>(qx, sx, meanp, rstdp, lnw, w1, w2);
    gemm_imma<<<dim3(C3/128, BTn/128), 256>>>(0);
    qkv_convert<<<dim3(Tn/64, Hn, Bn), 256>>>();
    attn_kernel<<<dim3(Tn/128, Hn, Bn), 256, ATTN_SMEM>>>();
    gemm_imma<<<dim3(Cn/128, BTn/128), 256>>>(1);
    final_kernel<<<BTn, 256>>>(x, out, (long long)out_size);
}

// round 15
// speedup vs baseline: 1.1563x; 1.0203x over previous
#include <cuda_runtime.h>
#include <cuda_bf16.h>
#include <math.h>

#define Bn   2
#define Tn   2048
#define Cn   1024
#define Hn   16
#define HDn  64
#define BTn  (Bn*Tn)
#define QMAXF 127.0f
#define C3   3072
#define QW   36
#define KH_OFF 0
#define KL_OFF (32*QW)
#define VH_OFF (64*QW)
#define VL_OFF (128*QW)
#define STAGEW (192*QW)     // 6912 words = 27648 B

// ---------------- scratch ----------------
__device__ int   g_qa [BTn*256];
__device__ float g_sa [32*BTn];
__device__ int   g_qw1[3*Cn*256];
__device__ float g_sw1[32*3*Cn];
__device__ int   g_qw2[Cn*256];
__device__ float g_sw2[32*Cn];
__device__ float g_qkv[(size_t)BTn*C3];
__device__ int   g_qy [BTn*256];
__device__ float g_sy [32*BTn];
__device__ float g_proj[(size_t)BTn*Cn];
__device__ unsigned gKH[Bn*Hn*65536], gKL[Bn*Hn*65536];
__device__ unsigned gVH[Bn*Hn*65536], gVL[Bn*Hn*65536];

__device__ __forceinline__ float warp_sum(float v){
#pragma unroll
    for (int o=16;o;o>>=1) v += __shfl_xor_sync(0xffffffffu, v, o);
    return v;
}
__device__ __forceinline__ float max8(float v){
#pragma unroll
    for (int o=4;o;o>>=1) v = fmaxf(v, __shfl_xor_sync(0xffffffffu, v, o));
    return v;
}
__device__ __forceinline__ int pack4(float a, float b, float c, float d){
    int i0=(int)a, i1=(int)b, i2=(int)c, i3=(int)d;
    return (i0&0xFF) | ((i1&0xFF)<<8) | ((i2&0xFF)<<16) | (i3<<24);
}
__device__ __forceinline__ float qclamp(float h, float inv_s){
    float q = rintf(h * inv_s);
    return fminf(fmaxf(q, -QMAXF), QMAXF);
}
__device__ __forceinline__ float ex2f(float x){
    float y; asm("ex2.approx.f32 %0, %1;" : "=f"(y) : "f"(x)); return y;
}
__device__ __forceinline__ unsigned pbf2(float x, float y){
    __nv_bfloat162 h = __floats2bfloat162_rn(x, y);
    return *(unsigned*)&h;
}
__device__ __forceinline__ void split2(float x, float y, unsigned &hi, unsigned &lo){
    unsigned h = pbf2(x, y);
    __nv_bfloat162 hb = *(__nv_bfloat162*)&h;
    hi = h;
    lo = pbf2(x - __bfloat162float(hb.x), y - __bfloat162float(hb.y));
}
__device__ __forceinline__ void mma16816(float* d, const unsigned* a, unsigned b0, unsigned b1){
    asm volatile("mma.sync.aligned.m16n8k16.row.col.f32.bf16.bf16.f32 "
        "{%0,%1,%2,%3},{%4,%5,%6,%7},{%8,%9},{%0,%1,%2,%3};"
        : "+f"(d[0]),"+f"(d[1]),"+f"(d[2]),"+f"(d[3])
        : "r"(a[0]),"r"(a[1]),"r"(a[2]),"r"(a[3]), "r"(b0),"r"(b1));
}
__device__ __forceinline__ void imma16832m(int* d, const unsigned* a, unsigned b0, unsigned b1){
    asm volatile("mma.sync.aligned.m16n8k32.row.col.s32.s8.s8.s32 "
        "{%0,%1,%2,%3},{%4,%5,%6,%7},{%8,%9},{%10,%11,%12,%13};"
        : "=r"(d[0]),"=r"(d[1]),"=r"(d[2]),"=r"(d[3])
        : "r"(a[0]),"r"(a[1]),"r"(a[2]),"r"(a[3]), "r"(b0),"r"(b1),
          "r"(0x4B400000),"r"(0x4B400000),"r"(0x4B400000),"r"(0x4B400000));
}
__device__ __forceinline__ void ldm_x4(unsigned* r, const void* p){
    unsigned ad = (unsigned)__cvta_generic_to_shared(p);
    asm volatile("ldmatrix.sync.aligned.m8n8.x4.shared.b16 {%0,%1,%2,%3}, [%4];"
        : "=r"(r[0]),"=r"(r[1]),"=r"(r[2]),"=r"(r[3]) : "r"(ad));
}
__device__ __forceinline__ void ldm_x4u(unsigned* r, unsigned ad){
    asm volatile("ldmatrix.sync.aligned.m8n8.x4.shared.b16 {%0,%1,%2,%3}, [%4];"
        : "=r"(r[0]),"=r"(r[1]),"=r"(r[2]),"=r"(r[3]) : "r"(ad));
}
__device__ __forceinline__ unsigned long long packf2(float x, float y){
    unsigned long long r; asm("mov.b64 %0, {%1,%2};" : "=l"(r) : "f"(x),"f"(y)); return r;
}
__device__ __forceinline__ unsigned long long pack2i(int x, int y){
    unsigned long long r; asm("mov.b64 %0, {%1,%2};" : "=l"(r) : "r"(x),"r"(y)); return r;
}
__device__ __forceinline__ void unpackf2(unsigned long long v, float &x, float &y){
    asm("mov.b64 {%0,%1}, %2;" : "=f"(x),"=f"(y) : "l"(v));
}
__device__ __forceinline__ unsigned long long addf2(unsigned long long a, unsigned long long b){
    unsigned long long r; asm("add.rn.f32x2 %0, %1, %2;" : "=l"(r) : "l"(a),"l"(b)); return r;
}
__device__ __forceinline__ unsigned long long mulf2(unsigned long long a, unsigned long long b){
    unsigned long long r; asm("mul.rn.f32x2 %0, %1, %2;" : "=l"(r) : "l"(a),"l"(b)); return r;
}
__device__ __forceinline__ unsigned long long fmaf2(unsigned long long a, unsigned long long b, unsigned long long c){
    unsigned long long r; asm("fma.rn.f32x2 %0, %1, %2, %3;" : "=l"(r) : "l"(a),"l"(b),"l"(c)); return r;
}
__device__ __forceinline__ void cpa16(void* dst, const void* src){
    unsigned d = (unsigned)__cvta_generic_to_shared(dst);
    asm volatile("cp.async.cg.shared.global [%0], [%1], 16;" :: "r"(d), "l"(src));
}
__device__ __forceinline__ void cpa4(void* dst, const void* src){
    unsigned d = (unsigned)__cvta_generic_to_shared(dst);
    asm volatile("cp.async.ca.shared.global [%0], [%1], 4;" :: "r"(d), "l"(src));
}
#define CP_COMMIT() asm volatile("cp.async.commit_group;")
#define CP_WAIT0()  asm volatile("cp.async.wait_group 0;")
#define CP_WAIT1()  asm volatile("cp.async.wait_group 1;")

// ---------------- kernel 1: fused prepass ----------------
__global__ void prepass(const int* __restrict__ qx, const float* __restrict__ sx,
                        const float* __restrict__ meanp, const float* __restrict__ rstdp,
                        const float* __restrict__ lnw,
                        const float* __restrict__ w1, const float* __restrict__ w2){
    int bid = blockIdx.x, t = threadIdx.x;
    int c0 = t << 2;
    if (bid < BTn){
        int r = bid;
        int4 qv = *(const int4*)(qx + r*Cn + c0);
        float sxv = sx[r*32 + (c0 >> 5)];
        float mu = meanp[r], rs = rstdp[r];
        float4 wv = *(const float4*)(lnw + c0);
        float h0 = ((float)qv.x * sxv - mu) * rs * wv.x;
        float h1 = ((float)qv.y * sxv - mu) * rs * wv.y;
        float h2 = ((float)qv.z * sxv - mu) * rs * wv.z;
        float h3 = ((float)qv.w * sxv - mu) * rs * wv.w;
        float m = max8(fmaxf(fmaxf(fabsf(h0),fabsf(h1)), fmaxf(fabsf(h2),fabsf(h3))));
        float s = fmaxf(m * (1.0f/QMAXF), 1e-8f);
        float inv = 1.0f / s;
        g_qa[r*256 + t] = pack4(qclamp(h0,inv), qclamp(h1,inv), qclamp(h2,inv), qclamp(h3,inv));
        if ((t & 7) == 0) g_sa[(t>>3)*BTn + r] = s;
    } else {
        const float* w; int* qo; float* so; int r, nrows;
        if (bid < BTn + C3){ w = w1; qo = g_qw1; so = g_sw1; r = bid - BTn; nrows = C3; }
        else               { w = w2; qo = g_qw2; so = g_sw2; r = bid - BTn - C3; nrows = Cn; }
        float4 wv = *(const float4*)(w + (size_t)r*Cn + c0);
        float m = max8(fmaxf(fmaxf(fabsf(wv.x),fabsf(wv.y)), fmaxf(fabsf(wv.z),fabsf(wv.w))));
        float s = fmaxf(m * (1.0f/QMAXF), 1e-8f);
        float inv = 1.0f / s;
        qo[r*256 + t] = pack4(qclamp(wv.x,inv), qclamp(wv.y,inv), qclamp(wv.z,inv), qclamp(wv.w,inv));
        if ((t & 7) == 0) so[(t>>3)*nrows + r] = s;
    }
}

// ---------------- kernel 3: int8 tensor-core GEMM, 3-stage cp.async pipeline ----------------
__global__ __launch_bounds__(256,2) void gemm_imma(int which){
    const int* Aq; const float* sA; const int* Bq; const float* sB; float* Cm; int N;
    if (which == 0){ Aq=g_qa; sA=g_sa; Bq=g_qw1; sB=g_sw1; Cm=g_qkv;  N=C3; }
    else           { Aq=g_qy; sA=g_sy; Bq=g_qw2; sB=g_sw2; Cm=g_proj; N=Cn; }

    __shared__ __align__(16) int As[3][128][12];
    __shared__ __align__(16) int Bs[3][128][12];
    __shared__ float sAs[3][128];
    __shared__ __align__(8) float sBs[3][128];

    int tid = threadIdx.x, lane = tid & 31, wp = tid >> 5;
    int wM = wp >> 2, wN = wp & 3;
    int bm = blockIdx.y << 7, bn = blockIdx.x << 7;
    int lr = tid >> 1, lw = (tid & 1) << 2;

    #define LOAD_STAGE(st, g) do { \
        cpa16(&As[st][lr][lw], Aq + (bm + lr)*256 + (g)*8 + lw); \
        cpa16(&Bs[st][lr][lw], Bq + (bn + lr)*256 + (g)*8 + lw); \
        if (tid < 128) cpa4(&sAs[st][tid], sA + (g)*BTn + bm + tid); \
        else           cpa4(&sBs[st][tid-128], sB + (g)*N + bn + tid - 128); \
        CP_COMMIT(); \
    } while(0)

    LOAD_STAGE(0, 0);
    LOAD_STAGE(1, 1);

    unsigned long long accp[4][4][2];
#pragma unroll
    for (int i=0;i<4;i++)
#pragma unroll
        for (int j=0;j<4;j++){ accp[i][j][0] = 0ull; accp[i][j][1] = 0ull; }

    const unsigned long long negM = packf2(-12582912.0f, -12582912.0f);
    int a_row = (lane & 15), a_wrd = (lane >> 4) << 2;
    int b_row = ((lane >> 4) << 3) + (lane & 7), b_wrd = ((lane >> 3) & 1) << 2;

    for (int g = 0; g < 32; g++){
        int st = g % 3;
        if (g < 30) CP_WAIT1(); else CP_WAIT0();
        __syncthreads();
        if (g + 2 < 32) LOAD_STAGE((g+2)%3, g+2);

        unsigned a[4][4], bf[2][4];
#pragma unroll
        for (int mc = 0; mc < 4; mc++)
            ldm_x4(a[mc], &As[st][wM*64 + mc*16 + a_row][a_wrd]);
#pragma unroll
        for (int p = 0; p < 2; p++)
            ldm_x4(bf[p], &Bs[st][wN*32 + p*16 + b_row][b_wrd]);

        unsigned long long sa2[8], sb2[4];
#pragma unroll
        for (int mc = 0; mc < 4; mc++){
            float s0 = sAs[st][wM*64 + mc*16 + (lane>>2)];
            float s1 = sAs[st][wM*64 + mc*16 + (lane>>2) + 8];
            sa2[2*mc]   = packf2(s0, s0);
            sa2[2*mc+1] = packf2(s1, s1);
        }
#pragma unroll
        for (int nc = 0; nc < 4; nc++)
            sb2[nc] = *(const unsigned long long*)&sBs[st][wN*32 + nc*8 + ((lane&3)<<1)];

#pragma unroll
        for (int mc = 0; mc < 4; mc++){
#pragma unroll
            for (int nc = 0; nc < 4; nc++){
                int d[4];
                imma16832m(d, a[mc], bf[nc>>1][(nc&1)*2], bf[nc>>1][(nc&1)*2+1]);
                unsigned long long f0 = addf2(pack2i(d[0], d[1]), negM);
                unsigned long long f1 = addf2(pack2i(d[2], d[3]), negM);
                accp[mc][nc][0] = fmaf2(mulf2(f0, sa2[2*mc  ]), sb2[nc], accp[mc][nc][0]);
                accp[mc][nc][1] = fmaf2(mulf2(f1, sa2[2*mc+1]), sb2[nc], accp[mc][nc][1]);
            }
        }
    }
#pragma unroll
    for (int mc = 0; mc < 4; mc++){
#pragma unroll
        for (int nc = 0; nc < 4; nc++){
            int row0 = bm + wM*64 + mc*16 + (lane>>2);
            int col  = bn + wN*32 + nc*8 + ((lane&3)<<1);
            float x0,y0,x1,y1;
            unpackf2(accp[mc][nc][0], x0, y0);
            unpackf2(accp[mc][nc][1], x1, y1);
            *(float2*)(Cm + (size_t)row0*N + col)     = make_float2(x0, y0);
            *(float2*)(Cm + (size_t)(row0+8)*N + col) = make_float2(x1, y1);
        }
    }
    #undef LOAD_STAGE
}

// ---------------- kernel 3.5: K/V -> bf16 hi/lo precompute (V transposed) ----------------
__global__ __launch_bounds__(256) void qkv_convert(){
    __shared__ float Vs[64][65];
    int kt = blockIdx.x, hh = blockIdx.y, b = blockIdx.z;
    int tid = threadIdx.x;
    int ks = kt << 6;
    int bh = b*Hn + hh;
    const float* base = g_qkv + (size_t)(b*Tn)*C3 + hh*HDn;
    unsigned kbase = bh*65536;

#pragma unroll
    for (int it = 0; it < 4; it++){
        int idx = tid + it*256;
        int row = idx >> 4, d4 = (idx & 15) << 2;
        float4 v = *(const float4*)(base + (size_t)(ks+row)*C3 + Cn + d4);
        unsigned h0,l0,h1,l1;
        split2(v.x, v.y, h0, l0);
        split2(v.z, v.w, h1, l1);
        unsigned wd = kbase + (ks+row)*32 + (d4>>1);
        gKH[wd] = h0; gKH[wd+1] = h1;
        gKL[wd] = l0; gKL[wd+1] = l1;
    }
#pragma unroll
    for (int it = 0; it < 4; it++){
        int idx = tid + it*256;
        int row = idx >> 4, d4 = (idx & 15) << 2;
        float4 v = *(const float4*)(base + (size_t)(ks+row)*C3 + 2*Cn + d4);
        Vs[row][d4] = v.x; Vs[row][d4+1] = v.y; Vs[row][d4+2] = v.z; Vs[row][d4+3] = v.w;
    }
    __syncthreads();
#pragma unroll
    for (int it = 0; it < 8; it++){
        int idx = tid + it*256;
        int d = idx >> 5, kwl = idx & 31;
        float v0 = Vs[2*kwl  ][d];
        float v1 = Vs[2*kwl+1][d];
        unsigned h, l;
        split2(v0, v1, h, l);
        unsigned wd = kbase + d*1024 + (ks>>1) + kwl;
        gVH[wd] = h; gVL[wd] = l;
    }
}

// ---------------- kernel 4: flash attention, no-max softmax (deferred normalize) ----------------
__global__ __launch_bounds__(256,2) void attn_kernel(){
    extern __shared__ unsigned sm[];   // 2 stages x STAGEW words

    int qt = (gridDim.x - 1) - blockIdx.x;
    int hh = blockIdx.y, b = blockIdx.z;
    int tid = threadIdx.x, w = tid >> 5, lane = tid & 31;
    int g = lane >> 2, tig = lane & 3;
    int qs = qt << 7, qb = w << 4;
    const float* base = g_qkv + (size_t)(b*Tn)*C3 + hh*HDn;
    int bh = b*Hn + hh;
    unsigned kbase = bh*65536;
    const float SCALE = 0.125f * 1.44269504088896f;
    int r0 = qs + qb + g, r1 = r0 + 8;

    unsigned smem_base = (unsigned)__cvta_generic_to_shared(sm);
    int lm_m = lane >> 3, lm_r = lane & 7;
    unsigned laneB = (unsigned)(((8*(lm_m>>1) + lm_r)*QW + 4*(lm_m&1)) * 4);

    unsigned aqh[4][4], aql[4][4];
#pragma unroll
    for (int dk=0; dk<4; dk++){
        const float* p0 = base + (size_t)r0*C3 + 16*dk + 2*tig;
        const float* p1 = base + (size_t)r1*C3 + 16*dk + 2*tig;
        float2 v00 = *(const float2*)(p0);
        float2 v01 = *(const float2*)(p0 + 8);
        float2 v10 = *(const float2*)(p1);
        float2 v11 = *(const float2*)(p1 + 8);
        split2(v00.x*SCALE, v00.y*SCALE, aqh[dk][0], aql[dk][0]);
        split2(v10.x*SCALE, v10.y*SCALE, aqh[dk][1], aql[dk][1]);
        split2(v01.x*SCALE, v01.y*SCALE, aqh[dk][2], aql[dk][2]);
        split2(v11.x*SCALE, v11.y*SCALE, aqh[dk][3], aql[dk][3]);
    }

    float o[8][4];
#pragma unroll
    for (int n=0;n<8;n++){ o[n][0]=0.f; o[n][1]=0.f; o[n][2]=0.f; o[n][3]=0.f; }
    float l0s = 0.f, l1s = 0.f;

    int ntiles = (qs + 128) >> 5;

    #define TILE_LOAD(stg, kss) do { \
        unsigned* S = sm + (stg)*STAGEW; \
        { int row = tid >> 3, ch = (tid & 7) << 2; \
          cpa16(&S[KH_OFF + row*QW + ch], &gKH[kbase + ((kss)+row)*32 + ch]); \
          cpa16(&S[KL_OFF + row*QW + ch], &gKL[kbase + ((kss)+row)*32 + ch]); } \
        { int row = tid >> 2, ch = (tid & 3) << 2; \
          cpa16(&S[VH_OFF + row*QW + ch], &gVH[kbase + row*1024 + ((kss)>>1) + ch]); \
          cpa16(&S[VL_OFF + row*QW + ch], &gVL[kbase + row*1024 + ((kss)>>1) + ch]); } \
        CP_COMMIT(); \
    } while(0)

    TILE_LOAD(0, 0);

    for (int kt = 0; kt < ntiles; kt++){
        int ks = kt << 5;
        int st = kt & 1;
        if (kt + 1 < ntiles){ TILE_LOAD(st^1, ks + 32); CP_WAIT1(); }
        else                { CP_WAIT0(); }
        __syncthreads();

        unsigned stB = smem_base + (unsigned)(st*STAGEW*4);
        unsigned sKH = stB + KH_OFF*4 + laneB;
        unsigned sKL = stB + KL_OFF*4 + laneB;
        unsigned sVH = stB + VH_OFF*4 + laneB;
        unsigned sVL = stB + VL_OFF*4 + laneB;

        float s[4][4];
#pragma unroll
        for (int n=0;n<4;n++){ s[n][0]=0.f; s[n][1]=0.f; s[n][2]=0.f; s[n][3]=0.f; }
#pragma unroll
        for (int dk = 0; dk < 4; dk++){
#pragma unroll
            for (int np = 0; np < 2; np++){
                unsigned off = (unsigned)(((np<<4)*QW + (dk<<3)) * 4);
                unsigned kh[4], kl[4];
                ldm_x4u(kh, sKH + off);
                ldm_x4u(kl, sKL + off);
                mma16816(s[2*np  ], aqh[dk], kh[0], kh[1]);
                mma16816(s[2*np  ], aql[dk], kh[0], kh[1]);
                mma16816(s[2*np  ], aqh[dk], kl[0], kl[1]);
                mma16816(s[2*np+1], aqh[dk], kh[2], kh[3]);
                mma16816(s[2*np+1], aql[dk], kh[2], kh[3]);
                mma16816(s[2*np+1], aqh[dk], kl[2], kl[3]);
            }
        }
#pragma unroll
        for (int n = 0; n < 4; n++){
            int c0 = ks + 8*n + 2*tig, c1 = c0 + 1;
            if (c0 > r0) s[n][0] = -1e30f;
            if (c1 > r0) s[n][1] = -1e30f;
            if (c0 > r1) s[n][2] = -1e30f;
            if (c1 > r1) s[n][3] = -1e30f;
            s[n][0] = ex2f(s[n][0]);
            s[n][1] = ex2f(s[n][1]);
            s[n][2] = ex2f(s[n][2]);
            s[n][3] = ex2f(s[n][3]);
            l0s += s[n][0] + s[n][1];
            l1s += s[n][2] + s[n][3];
        }
#pragma unroll
        for (int kc = 0; kc < 2; kc++){
            unsigned ph[4], pl[4];
            split2(s[2*kc  ][0], s[2*kc  ][1], ph[0], pl[0]);
            split2(s[2*kc  ][2], s[2*kc  ][3], ph[1], pl[1]);
            split2(s[2*kc+1][0], s[2*kc+1][1], ph[2], pl[2]);
            split2(s[2*kc+1][2], s[2*kc+1][3], ph[3], pl[3]);
#pragma unroll
            for (int ndp = 0; ndp < 4; ndp++){
                unsigned off = (unsigned)(((ndp<<4)*QW + (kc<<3)) * 4);
                unsigned vh[4], vl[4];
                ldm_x4u(vh, sVH + off);
                ldm_x4u(vl, sVL + off);
                mma16816(o[2*ndp  ], ph, vh[0], vh[1]);
                mma16816(o[2*ndp  ], pl, vh[0], vh[1]);
                mma16816(o[2*ndp  ], ph, vl[0], vl[1]);
                mma16816(o[2*ndp+1], ph, vh[2], vh[3]);
                mma16816(o[2*ndp+1], pl, vh[2], vh[3]);
                mma16816(o[2*ndp+1], ph, vl[2], vl[3]);
            }
        }
        __syncthreads();
    }
    #undef TILE_LOAD

    l0s += __shfl_xor_sync(0xffffffffu, l0s, 1);
    l0s += __shfl_xor_sync(0xffffffffu, l0s, 2);
    l1s += __shfl_xor_sync(0xffffffffu, l1s, 1);
    l1s += __shfl_xor_sync(0xffffffffu, l1s, 2);

    float inv0 = 1.0f / l0s, inv1 = 1.0f / l1s;
    float gm00=0.f, gm01=0.f, gm10=0.f, gm11=0.f;
#pragma unroll
    for (int nd = 0; nd < 8; nd++){
        float a0 = fabsf(o[nd][0]*inv0), a1 = fabsf(o[nd][1]*inv0);
        float b0 = fabsf(o[nd][2]*inv1), b1 = fabsf(o[nd][3]*inv1);
        if (nd < 4){ gm00 = fmaxf(gm00, fmaxf(a0,a1)); gm10 = fmaxf(gm10, fmaxf(b0,b1)); }
        else       { gm01 = fmaxf(gm01, fmaxf(a0,a1)); gm11 = fmaxf(gm11, fmaxf(b0,b1)); }
    }
#pragma unroll
    for (int off = 1; off <= 2; off <<= 1){
        gm00 = fmaxf(gm00, __shfl_xor_sync(0xffffffffu, gm00, off));
        gm01 = fmaxf(gm01, __shfl_xor_sync(0xffffffffu, gm01, off));
        gm10 = fmaxf(gm10, __shfl_xor_sync(0xffffffffu, gm10, off));
        gm11 = fmaxf(gm11, __shfl_xor_sync(0xffffffffu, gm11, off));
    }
    float sq00 = fmaxf(gm00*(1.0f/QMAXF), 1e-8f), sq01 = fmaxf(gm01*(1.0f/QMAXF), 1e-8f);
    float sq10 = fmaxf(gm10*(1.0f/QMAXF), 1e-8f), sq11 = fmaxf(gm11*(1.0f/QMAXF), 1e-8f);
    int row0 = b*Tn + r0, row1 = b*Tn + r1;
#pragma unroll
    for (int nd = 0; nd < 8; nd++){
        float is0 = (nd<4) ? 1.0f/sq00 : 1.0f/sq01;
        float is1 = (nd<4) ? 1.0f/sq10 : 1.0f/sq11;
        int q0 = (int)qclamp(o[nd][0]*inv0, is0), q1 = (int)qclamp(o[nd][1]*inv0, is0);
        int q2 = (int)qclamp(o[nd][2]*inv1, is1), q3 = (int)qclamp(o[nd][3]*inv1, is1);
        int sh0 = (q0&0xFF) | ((q1&0xFF)<<8);
        int sh1 = (q2&0xFF) | ((q3&0xFF)<<8);
        int ot0 = __shfl_down_sync(0xffffffffu, sh0, 1);
        int ot1 = __shfl_down_sync(0xffffffffu, sh1, 1);
        if (!(tig & 1)){
            int wi = hh*16 + nd*2 + (tig>>1);
            g_qy[row0*256 + wi] = (sh0&0xFFFF) | (ot0<<16);
            g_qy[row1*256 + wi] = (sh1&0xFFFF) | (ot1<<16);
        }
    }
    if (tig == 0){
        g_sy[(hh*2  )*BTn + row0] = sq00;
        g_sy[(hh*2  )*BTn + row1] = sq10;
    }
    if (tig == 1){
        g_sy[(hh*2+1)*BTn + row0] = sq01;
        g_sy[(hh*2+1)*BTn + row1] = sq11;
    }
}

// ---------------- kernel 5: residual + stats + quant, single-pass ----------------
__global__ void final_kernel(const float* __restrict__ x, float* __restrict__ out, long long osz){
    __shared__ float red[8], redq[8], bc[2];
    int r = blockIdx.x, t = threadIdx.x;
    int c0 = t << 2;
    float4 xv = *(const float4*)(x + (size_t)r*Cn + c0);
    float4 pv = *(const float4*)(g_proj + (size_t)r*Cn + c0);
    float v0 = xv.x + pv.x, v1 = xv.y + pv.y, v2 = xv.z + pv.z, v3 = xv.w + pv.w;

    float sum = (v0 + v1) + (v2 + v3);
    float sq  = v0*v0 + v1*v1 + v2*v2 + v3*v3;
    sum = warp_sum(sum);
    sq  = warp_sum(sq);
    if ((t & 31) == 0){ red[t>>5] = sum; redq[t>>5] = sq; }
    __syncthreads();
    if (t < 32){
        float a = (t < 8) ? red[t]  : 0.f;
        float b = (t < 8) ? redq[t] : 0.f;
#pragma unroll
        for (int o=4;o;o>>=1){ a += __shfl_xor_sync(0xffffffffu, a, o); b += __shfl_xor_sync(0xffffffffu, b, o); }
        if (t == 0){
            float mu = a * (1.0f/Cn);
            float var = b * (1.0f/Cn) - mu*mu;
            bc[0] = mu;
            bc[1] = 1.0f / sqrtf(var + 1e-5f);
        }
    }
    __syncthreads();
    float mu = bc[0], rst = bc[1];

    *(float4*)(out + (size_t)r*Cn + c0) = make_float4(v0, v1, v2, v3);
    float m = max8(fmaxf(fmaxf(fabsf(v0),fabsf(v1)), fmaxf(fabsf(v2),fabsf(v3))));
    float s = fmaxf(m * (1.0f/QMAXF), 1e-8f);
    float inv = 1.0f / s;
    long long oq = (long long)BTn*Cn + (long long)r*Cn + c0;
    if (oq + 3 < osz)
        *(float4*)(out + oq) = make_float4(qclamp(v0,inv), qclamp(v1,inv), qclamp(v2,inv), qclamp(v3,inv));
    if ((t & 7) == 0){
        long long os = 2LL*BTn*Cn + (long long)r*32 + (t>>3);
        if (os < osz) out[os] = s;
    }
    if (t == 0){
        long long om = 2LL*BTn*Cn + 32LL*BTn + r;
        if (om < osz)        out[om]       = mu;
        if (om + BTn < osz)  out[om + BTn] = rst;
    }
}

// ---------------- launch ----------------
extern "C" void kernel_launch(void* const* d_in, const int* in_sizes, int n_in,
                              void* d_out, int out_size){
    const float* x     = (const float*)d_in[0];
    const int*   qx    = (const int*)  d_in[1];
    const float* sx    = (const float*)d_in[2];
    const float* meanp = (const float*)d_in[3];
    const float* rstdp = (const float*)d_in[4];
    const float* lnw   = (const float*)d_in[5];
    const float* w1    = (const float*)d_in[6];
    const float* w2    = (const float*)d_in[7];
    float* out = (float*)d_out;

    const int ATTN_SMEM = 2 * STAGEW * 4;   // 55296 bytes
    cudaFuncSetAttribute(attn_kernel, cudaFuncAttributeMaxDynamicSharedMemorySize, ATTN_SMEM);

    prepass<<<BTn + C3 + Cn, 256>>>(qx, sx, meanp, rstdp, lnw, w1, w2);
    gemm_imma<<<dim3(C3/128, BTn/128), 256>>>(0);
    qkv_convert<<<dim3(Tn/64, Hn, Bn), 256>>>();
    attn_kernel<<<dim3(Tn/128, Hn, Bn), 256, ATTN_SMEM>>>();
    gemm_imma<<<dim3(Cn/128, BTn/128), 256>>>(1);
    final_kernel<<<BTn, 256>>>(x, out, (long long)out_size);
}

// round 16
// speedup vs baseline: 1.1841x; 1.0240x over previous
#include <cuda_runtime.h>
#include <cuda_bf16.h>
#include <math.h>

#define Bn   2
#define Tn   2048
#define Cn   1024
#define Hn   16
#define HDn  64
#define BTn  (Bn*Tn)
#define QMAXF 127.0f
#define C3   3072
#define QW   36
// 64-key stage: KH(64*QW) KL(64*QW) VH(64*QW) VL(64*QW)
#define KH_OFF 0
#define KL_OFF (64*QW)
#define VH_OFF (128*QW)
#define VL_OFF (192*QW)
#define STAGEW (256*QW)     // 9216 words = 36864 B

// ---------------- scratch ----------------
__device__ int   g_qa [BTn*256];
__device__ float g_sa [32*BTn];
__device__ int   g_qw1[3*Cn*256];
__device__ float g_sw1[32*3*Cn];
__device__ int   g_qw2[Cn*256];
__device__ float g_sw2[32*Cn];
__device__ float g_qkv[(size_t)BTn*C3];
__device__ int   g_qy [BTn*256];
__device__ float g_sy [32*BTn];
__device__ float g_proj[(size_t)BTn*Cn];
__device__ unsigned gKH[Bn*Hn*65536], gKL[Bn*Hn*65536];
__device__ unsigned gVH[Bn*Hn*65536], gVL[Bn*Hn*65536];

__device__ __forceinline__ float warp_sum(float v){
#pragma unroll
    for (int o=16;o;o>>=1) v += __shfl_xor_sync(0xffffffffu, v, o);
    return v;
}
__device__ __forceinline__ float max8(float v){
#pragma unroll
    for (int o=4;o;o>>=1) v = fmaxf(v, __shfl_xor_sync(0xffffffffu, v, o));
    return v;
}
__device__ __forceinline__ int pack4(float a, float b, float c, float d){
    int i0=(int)a, i1=(int)b, i2=(int)c, i3=(int)d;
    return (i0&0xFF) | ((i1&0xFF)<<8) | ((i2&0xFF)<<16) | (i3<<24);
}
__device__ __forceinline__ float qclamp(float h, float inv_s){
    float q = rintf(h * inv_s);
    return fminf(fmaxf(q, -QMAXF), QMAXF);
}
__device__ __forceinline__ float ex2f(float x){
    float y; asm("ex2.approx.f32 %0, %1;" : "=f"(y) : "f"(x)); return y;
}
__device__ __forceinline__ unsigned pbf2(float x, float y){
    __nv_bfloat162 h = __floats2bfloat162_rn(x, y);
    return *(unsigned*)&h;
}
__device__ __forceinline__ void split2(float x, float y, unsigned &hi, unsigned &lo){
    unsigned h = pbf2(x, y);
    __nv_bfloat162 hb = *(__nv_bfloat162*)&h;
    hi = h;
    lo = pbf2(x - __bfloat162float(hb.x), y - __bfloat162float(hb.y));
}
__device__ __forceinline__ void mma16816(float* d, const unsigned* a, unsigned b0, unsigned b1){
    asm volatile("mma.sync.aligned.m16n8k16.row.col.f32.bf16.bf16.f32 "
        "{%0,%1,%2,%3},{%4,%5,%6,%7},{%8,%9},{%0,%1,%2,%3};"
        : "+f"(d[0]),"+f"(d[1]),"+f"(d[2]),"+f"(d[3])
        : "r"(a[0]),"r"(a[1]),"r"(a[2]),"r"(a[3]), "r"(b0),"r"(b1));
}
__device__ __forceinline__ void imma16832m(int* d, const unsigned* a, unsigned b0, unsigned b1){
    asm volatile("mma.sync.aligned.m16n8k32.row.col.s32.s8.s8.s32 "
        "{%0,%1,%2,%3},{%4,%5,%6,%7},{%8,%9},{%10,%11,%12,%13};"
        : "=r"(d[0]),"=r"(d[1]),"=r"(d[2]),"=r"(d[3])
        : "r"(a[0]),"r"(a[1]),"r"(a[2]),"r"(a[3]), "r"(b0),"r"(b1),
          "r"(0x4B400000),"r"(0x4B400000),"r"(0x4B400000),"r"(0x4B400000));
}
__device__ __forceinline__ void ldm_x4(unsigned* r, const void* p){
    unsigned ad = (unsigned)__cvta_generic_to_shared(p);
    asm volatile("ldmatrix.sync.aligned.m8n8.x4.shared.b16 {%0,%1,%2,%3}, [%4];"
        : "=r"(r[0]),"=r"(r[1]),"=r"(r[2]),"=r"(r[3]) : "r"(ad));
}
__device__ __forceinline__ void ldm_x4u(unsigned* r, unsigned ad){
    asm volatile("ldmatrix.sync.aligned.m8n8.x4.shared.b16 {%0,%1,%2,%3}, [%4];"
        : "=r"(r[0]),"=r"(r[1]),"=r"(r[2]),"=r"(r[3]) : "r"(ad));
}
__device__ __forceinline__ unsigned long long packf2(float x, float y){
    unsigned long long r; asm("mov.b64 %0, {%1,%2};" : "=l"(r) : "f"(x),"f"(y)); return r;
}
__device__ __forceinline__ unsigned long long pack2i(int x, int y){
    unsigned long long r; asm("mov.b64 %0, {%1,%2};" : "=l"(r) : "r"(x),"r"(y)); return r;
}
__device__ __forceinline__ void unpackf2(unsigned long long v, float &x, float &y){
    asm("mov.b64 {%0,%1}, %2;" : "=f"(x),"=f"(y) : "l"(v));
}
__device__ __forceinline__ unsigned long long addf2(unsigned long long a, unsigned long long b){
    unsigned long long r; asm("add.rn.f32x2 %0, %1, %2;" : "=l"(r) : "l"(a),"l"(b)); return r;
}
__device__ __forceinline__ unsigned long long mulf2(unsigned long long a, unsigned long long b){
    unsigned long long r; asm("mul.rn.f32x2 %0, %1, %2;" : "=l"(r) : "l"(a),"l"(b)); return r;
}
__device__ __forceinline__ unsigned long long fmaf2(unsigned long long a, unsigned long long b, unsigned long long c){
    unsigned long long r; asm("fma.rn.f32x2 %0, %1, %2, %3;" : "=l"(r) : "l"(a),"l"(b),"l"(c)); return r;
}
__device__ __forceinline__ void cpa16(void* dst, const void* src){
    unsigned d = (unsigned)__cvta_generic_to_shared(dst);
    asm volatile("cp.async.cg.shared.global [%0], [%1], 16;" :: "r"(d), "l"(src));
}
__device__ __forceinline__ void cpa4(void* dst, const void* src){
    unsigned d = (unsigned)__cvta_generic_to_shared(dst);
    asm volatile("cp.async.ca.shared.global [%0], [%1], 4;" :: "r"(d), "l"(src));
}
#define CP_COMMIT() asm volatile("cp.async.commit_group;")
#define CP_WAIT0()  asm volatile("cp.async.wait_group 0;")
#define CP_WAIT1()  asm volatile("cp.async.wait_group 1;")

// ---------------- kernel 1: fused prepass ----------------
__global__ void prepass(const int* __restrict__ qx, const float* __restrict__ sx,
                        const float* __restrict__ meanp, const float* __restrict__ rstdp,
                        const float* __restrict__ lnw,
                        const float* __restrict__ w1, const float* __restrict__ w2){
    int bid = blockIdx.x, t = threadIdx.x;
    int c0 = t << 2;
    if (bid < BTn){
        int r = bid;
        int4 qv = *(const int4*)(qx + r*Cn + c0);
        float sxv = sx[r*32 + (c0 >> 5)];
        float mu = meanp[r], rs = rstdp[r];
        float4 wv = *(const float4*)(lnw + c0);
        float h0 = ((float)qv.x * sxv - mu) * rs * wv.x;
        float h1 = ((float)qv.y * sxv - mu) * rs * wv.y;
        float h2 = ((float)qv.z * sxv - mu) * rs * wv.z;
        float h3 = ((float)qv.w * sxv - mu) * rs * wv.w;
        float m = max8(fmaxf(fmaxf(fabsf(h0),fabsf(h1)), fmaxf(fabsf(h2),fabsf(h3))));
        float s = fmaxf(m * (1.0f/QMAXF), 1e-8f);
        float inv = 1.0f / s;
        g_qa[r*256 + t] = pack4(qclamp(h0,inv), qclamp(h1,inv), qclamp(h2,inv), qclamp(h3,inv));
        if ((t & 7) == 0) g_sa[(t>>3)*BTn + r] = s;
    } else {
        const float* w; int* qo; float* so; int r, nrows;
        if (bid < BTn + C3){ w = w1; qo = g_qw1; so = g_sw1; r = bid - BTn; nrows = C3; }
        else               { w = w2; qo = g_qw2; so = g_sw2; r = bid - BTn - C3; nrows = Cn; }
        float4 wv = *(const float4*)(w + (size_t)r*Cn + c0);
        float m = max8(fmaxf(fmaxf(fabsf(wv.x),fabsf(wv.y)), fmaxf(fabsf(wv.z),fabsf(wv.w))));
        float s = fmaxf(m * (1.0f/QMAXF), 1e-8f);
        float inv = 1.0f / s;
        qo[r*256 + t] = pack4(qclamp(wv.x,inv), qclamp(wv.y,inv), qclamp(wv.z,inv), qclamp(wv.w,inv));
        if ((t & 7) == 0) so[(t>>3)*nrows + r] = s;
    }
}

// ---------------- kernel 3: int8 tensor-core GEMM, 3-stage cp.async pipeline ----------------
__global__ __launch_bounds__(256,2) void gemm_imma(int which){
    const int* Aq; const float* sA; const int* Bq; const float* sB; float* Cm; int N;
    if (which == 0){ Aq=g_qa; sA=g_sa; Bq=g_qw1; sB=g_sw1; Cm=g_qkv;  N=C3; }
    else           { Aq=g_qy; sA=g_sy; Bq=g_qw2; sB=g_sw2; Cm=g_proj; N=Cn; }

    __shared__ __align__(16) int As[3][128][12];
    __shared__ __align__(16) int Bs[3][128][12];
    __shared__ float sAs[3][128];
    __shared__ __align__(8) float sBs[3][128];

    int tid = threadIdx.x, lane = tid & 31, wp = tid >> 5;
    int wM = wp >> 2, wN = wp & 3;
    int bm = blockIdx.y << 7, bn = blockIdx.x << 7;
    int lr = tid >> 1, lw = (tid & 1) << 2;

    #define LOAD_STAGE(st, g) do { \
        cpa16(&As[st][lr][lw], Aq + (bm + lr)*256 + (g)*8 + lw); \
        cpa16(&Bs[st][lr][lw], Bq + (bn + lr)*256 + (g)*8 + lw); \
        if (tid < 128) cpa4(&sAs[st][tid], sA + (g)*BTn + bm + tid); \
        else           cpa4(&sBs[st][tid-128], sB + (g)*N + bn + tid - 128); \
        CP_COMMIT(); \
    } while(0)

    LOAD_STAGE(0, 0);
    LOAD_STAGE(1, 1);

    unsigned long long accp[4][4][2];
#pragma unroll
    for (int i=0;i<4;i++)
#pragma unroll
        for (int j=0;j<4;j++){ accp[i][j][0] = 0ull; accp[i][j][1] = 0ull; }

    const unsigned long long negM = packf2(-12582912.0f, -12582912.0f);
    int a_row = (lane & 15), a_wrd = (lane >> 4) << 2;
    int b_row = ((lane >> 4) << 3) + (lane & 7), b_wrd = ((lane >> 3) & 1) << 2;

    for (int g = 0; g < 32; g++){
        int st = g % 3;
        if (g < 30) CP_WAIT1(); else CP_WAIT0();
        __syncthreads();
        if (g + 2 < 32) LOAD_STAGE((g+2)%3, g+2);

        unsigned a[4][4], bf[2][4];
#pragma unroll
        for (int mc = 0; mc < 4; mc++)
            ldm_x4(a[mc], &As[st][wM*64 + mc*16 + a_row][a_wrd]);
#pragma unroll
        for (int p = 0; p < 2; p++)
            ldm_x4(bf[p], &Bs[st][wN*32 + p*16 + b_row][b_wrd]);

        unsigned long long sa2[8], sb2[4];
#pragma unroll
        for (int mc = 0; mc < 4; mc++){
            float s0 = sAs[st][wM*64 + mc*16 + (lane>>2)];
            float s1 = sAs[st][wM*64 + mc*16 + (lane>>2) + 8];
            sa2[2*mc]   = packf2(s0, s0);
            sa2[2*mc+1] = packf2(s1, s1);
        }
#pragma unroll
        for (int nc = 0; nc < 4; nc++)
            sb2[nc] = *(const unsigned long long*)&sBs[st][wN*32 + nc*8 + ((lane&3)<<1)];

#pragma unroll
        for (int mc = 0; mc < 4; mc++){
#pragma unroll
            for (int nc = 0; nc < 4; nc++){
                int d[4];
                imma16832m(d, a[mc], bf[nc>>1][(nc&1)*2], bf[nc>>1][(nc&1)*2+1]);
                unsigned long long f0 = addf2(pack2i(d[0], d[1]), negM);
                unsigned long long f1 = addf2(pack2i(d[2], d[3]), negM);
                accp[mc][nc][0] = fmaf2(mulf2(f0, sa2[2*mc  ]), sb2[nc], accp[mc][nc][0]);
                accp[mc][nc][1] = fmaf2(mulf2(f1, sa2[2*mc+1]), sb2[nc], accp[mc][nc][1]);
            }
        }
    }
#pragma unroll
    for (int mc = 0; mc < 4; mc++){
#pragma unroll
        for (int nc = 0; nc < 4; nc++){
            int row0 = bm + wM*64 + mc*16 + (lane>>2);
            int col  = bn + wN*32 + nc*8 + ((lane&3)<<1);
            float x0,y0,x1,y1;
            unpackf2(accp[mc][nc][0], x0, y0);
            unpackf2(accp[mc][nc][1], x1, y1);
            *(float2*)(Cm + (size_t)row0*N + col)     = make_float2(x0, y0);
            *(float2*)(Cm + (size_t)(row0+8)*N + col) = make_float2(x1, y1);
        }
    }
    #undef LOAD_STAGE
}

// ---------------- kernel 3.5: K/V -> bf16 hi/lo precompute (V transposed) ----------------
__global__ __launch_bounds__(256) void qkv_convert(){
    __shared__ float Vs[64][65];
    int kt = blockIdx.x, hh = blockIdx.y, b = blockIdx.z;
    int tid = threadIdx.x;
    int ks = kt << 6;
    int bh = b*Hn + hh;
    const float* base = g_qkv + (size_t)(b*Tn)*C3 + hh*HDn;
    unsigned kbase = bh*65536;

#pragma unroll
    for (int it = 0; it < 4; it++){
        int idx = tid + it*256;
        int row = idx >> 4, d4 = (idx & 15) << 2;
        float4 v = *(const float4*)(base + (size_t)(ks+row)*C3 + Cn + d4);
        unsigned h0,l0,h1,l1;
        split2(v.x, v.y, h0, l0);
        split2(v.z, v.w, h1, l1);
        unsigned wd = kbase + (ks+row)*32 + (d4>>1);
        gKH[wd] = h0; gKH[wd+1] = h1;
        gKL[wd] = l0; gKL[wd+1] = l1;
    }
#pragma unroll
    for (int it = 0; it < 4; it++){
        int idx = tid + it*256;
        int row = idx >> 4, d4 = (idx & 15) << 2;
        float4 v = *(const float4*)(base + (size_t)(ks+row)*C3 + 2*Cn + d4);
        Vs[row][d4] = v.x; Vs[row][d4+1] = v.y; Vs[row][d4+2] = v.z; Vs[row][d4+3] = v.w;
    }
    __syncthreads();
#pragma unroll
    for (int it = 0; it < 8; it++){
        int idx = tid + it*256;
        int d = idx >> 5, kwl = idx & 31;
        float v0 = Vs[2*kwl  ][d];
        float v1 = Vs[2*kwl+1][d];
        unsigned h, l;
        split2(v0, v1, h, l);
        unsigned wd = kbase + d*1024 + (ks>>1) + kwl;
        gVH[wd] = h; gVL[wd] = l;
    }
}

// ---------------- kernel 4: flash attention, 64-key tiles, single barrier/tile ----------------
__global__ __launch_bounds__(256,2) void attn_kernel(){
    extern __shared__ unsigned sm[];   // 2 stages x STAGEW words (73728 B)

    int qt = (gridDim.x - 1) - blockIdx.x;
    int hh = blockIdx.y, b = blockIdx.z;
    int tid = threadIdx.x, w = tid >> 5, lane = tid & 31;
    int g = lane >> 2, tig = lane & 3;
    int qs = qt << 7, qb = w << 4;
    const float* base = g_qkv + (size_t)(b*Tn)*C3 + hh*HDn;
    int bh = b*Hn + hh;
    unsigned kbase = bh*65536;
    const float SCALE = 0.125f * 1.44269504088896f;
    int r0 = qs + qb + g, r1 = r0 + 8;

    unsigned smem_base = (unsigned)__cvta_generic_to_shared(sm);
    int lm_m = lane >> 3, lm_r = lane & 7;
    unsigned laneB = (unsigned)(((8*(lm_m>>1) + lm_r)*QW + 4*(lm_m&1)) * 4);

    unsigned aqh[4][4], aql[4][4];
#pragma unroll
    for (int dk=0; dk<4; dk++){
        const float* p0 = base + (size_t)r0*C3 + 16*dk + 2*tig;
        const float* p1 = base + (size_t)r1*C3 + 16*dk + 2*tig;
        float2 v00 = *(const float2*)(p0);
        float2 v01 = *(const float2*)(p0 + 8);
        float2 v10 = *(const float2*)(p1);
        float2 v11 = *(const float2*)(p1 + 8);
        split2(v00.x*SCALE, v00.y*SCALE, aqh[dk][0], aql[dk][0]);
        split2(v10.x*SCALE, v10.y*SCALE, aqh[dk][1], aql[dk][1]);
        split2(v01.x*SCALE, v01.y*SCALE, aqh[dk][2], aql[dk][2]);
        split2(v11.x*SCALE, v11.y*SCALE, aqh[dk][3], aql[dk][3]);
    }

    float o[8][4];
#pragma unroll
    for (int n=0;n<8;n++){ o[n][0]=0.f; o[n][1]=0.f; o[n][2]=0.f; o[n][3]=0.f; }
    float l0s = 0.f, l1s = 0.f;

    int ntiles = (qs + 128) >> 6;   // 64-key tiles

    // K: 64 rows x 32 words; V: 64 rows x 32 words -> 2 iters of 256 thr each (16B chunks)
    #define TILE_LOAD(stg, kss) do { \
        unsigned* S = sm + (stg)*STAGEW; \
        _Pragma("unroll") \
        for (int it = 0; it < 2; it++){ \
            int idx = tid + it*256; \
            int row = idx >> 3, ch = (idx & 7) << 2; \
            cpa16(&S[KH_OFF + row*QW + ch], &gKH[kbase + ((kss)+row)*32 + ch]); \
            cpa16(&S[KL_OFF + row*QW + ch], &gKL[kbase + ((kss)+row)*32 + ch]); \
            cpa16(&S[VH_OFF + row*QW + ch], &gVH[kbase + row*1024 + ((kss)>>1) + ch]); \
            cpa16(&S[VL_OFF + row*QW + ch], &gVL[kbase + row*1024 + ((kss)>>1) + ch]); \
        } \
        CP_COMMIT(); \
    } while(0)

    TILE_LOAD(0, 0);

    for (int kt = 0; kt < ntiles; kt++){
        int ks = kt << 6;
        int st = kt & 1;
        CP_WAIT0();
        __syncthreads();            // loads visible + previous compute done
        if (kt + 1 < ntiles) TILE_LOAD(st^1, ks + 64);

        unsigned stB = smem_base + (unsigned)(st*STAGEW*4);
        unsigned sKH = stB + KH_OFF*4 + laneB;
        unsigned sKL = stB + KL_OFF*4 + laneB;
        unsigned sVH = stB + VH_OFF*4 + laneB;
        unsigned sVL = stB + VL_OFF*4 + laneB;

        float s[8][4];
#pragma unroll
        for (int n=0;n<8;n++){ s[n][0]=0.f; s[n][1]=0.f; s[n][2]=0.f; s[n][3]=0.f; }
#pragma unroll
        for (int dk = 0; dk < 4; dk++){
#pragma unroll
            for (int np = 0; np < 4; np++){
                unsigned off = (unsigned)(((np<<4)*QW + (dk<<3)) * 4);
                unsigned kh[4], kl[4];
                ldm_x4u(kh, sKH + off);
                ldm_x4u(kl, sKL + off);
                mma16816(s[2*np  ], aqh[dk], kh[0], kh[1]);
                mma16816(s[2*np  ], aql[dk], kh[0], kh[1]);
                mma16816(s[2*np  ], aqh[dk], kl[0], kl[1]);
                mma16816(s[2*np+1], aqh[dk], kh[2], kh[3]);
                mma16816(s[2*np+1], aql[dk], kh[2], kh[3]);
                mma16816(s[2*np+1], aqh[dk], kl[2], kl[3]);
            }
        }
#pragma unroll
        for (int n = 0; n < 8; n++){
            int c0 = ks + 8*n + 2*tig, c1 = c0 + 1;
            if (c0 > r0) s[n][0] = -1e30f;
            if (c1 > r0) s[n][1] = -1e30f;
            if (c0 > r1) s[n][2] = -1e30f;
            if (c1 > r1) s[n][3] = -1e30f;
            s[n][0] = ex2f(s[n][0]);
            s[n][1] = ex2f(s[n][1]);
            s[n][2] = ex2f(s[n][2]);
            s[n][3] = ex2f(s[n][3]);
            l0s += s[n][0] + s[n][1];
            l1s += s[n][2] + s[n][3];
        }
#pragma unroll
        for (int kc = 0; kc < 4; kc++){
            unsigned ph[4], pl[4];
            split2(s[2*kc  ][0], s[2*kc  ][1], ph[0], pl[0]);
            split2(s[2*kc  ][2], s[2*kc  ][3], ph[1], pl[1]);
            split2(s[2*kc+1][0], s[2*kc+1][1], ph[2], pl[2]);
            split2(s[2*kc+1][2], s[2*kc+1][3], ph[3], pl[3]);
#pragma unroll
            for (int ndp = 0; ndp < 4; ndp++){
                unsigned off = (unsigned)(((ndp<<4)*QW + (kc<<3)) * 4);
                unsigned vh[4], vl[4];
                ldm_x4u(vh, sVH + off);
                ldm_x4u(vl, sVL + off);
                mma16816(o[2*ndp  ], ph, vh[0], vh[1]);
                mma16816(o[2*ndp  ], pl, vh[0], vh[1]);
                mma16816(o[2*ndp  ], ph, vl[0], vl[1]);
                mma16816(o[2*ndp+1], ph, vh[2], vh[3]);
                mma16816(o[2*ndp+1], pl, vh[2], vh[3]);
                mma16816(o[2*ndp+1], ph, vl[2], vl[3]);
            }
        }
    }
    #undef TILE_LOAD

    l0s += __shfl_xor_sync(0xffffffffu, l0s, 1);
    l0s += __shfl_xor_sync(0xffffffffu, l0s, 2);
    l1s += __shfl_xor_sync(0xffffffffu, l1s, 1);
    l1s += __shfl_xor_sync(0xffffffffu, l1s, 2);

    float inv0 = 1.0f / l0s, inv1 = 1.0f / l1s;
    float gm00=0.f, gm01=0.f, gm10=0.f, gm11=0.f;
#pragma unroll
    for (int nd = 0; nd < 8; nd++){
        float a0 = fabsf(o[nd][0]*inv0), a1 = fabsf(o[nd][1]*inv0);
        float b0 = fabsf(o[nd][2]*inv1), b1 = fabsf(o[nd][3]*inv1);
        if (nd < 4){ gm00 = fmaxf(gm00, fmaxf(a0,a1)); gm10 = fmaxf(gm10, fmaxf(b0,b1)); }
        else       { gm01 = fmaxf(gm01, fmaxf(a0,a1)); gm11 = fmaxf(gm11, fmaxf(b0,b1)); }
    }
#pragma unroll
    for (int off = 1; off <= 2; off <<= 1){
        gm00 = fmaxf(gm00, __shfl_xor_sync(0xffffffffu, gm00, off));
        gm01 = fmaxf(gm01, __shfl_xor_sync(0xffffffffu, gm01, off));
        gm10 = fmaxf(gm10, __shfl_xor_sync(0xffffffffu, gm10, off));
        gm11 = fmaxf(gm11, __shfl_xor_sync(0xffffffffu, gm11, off));
    }
    float sq00 = fmaxf(gm00*(1.0f/QMAXF), 1e-8f), sq01 = fmaxf(gm01*(1.0f/QMAXF), 1e-8f);
    float sq10 = fmaxf(gm10*(1.0f/QMAXF), 1e-8f), sq11 = fmaxf(gm11*(1.0f/QMAXF), 1e-8f);
    int row0 = b*Tn + r0, row1 = b*Tn + r1;
#pragma unroll
    for (int nd = 0; nd < 8; nd++){
        float is0 = (nd<4) ? 1.0f/sq00 : 1.0f/sq01;
        float is1 = (nd<4) ? 1.0f/sq10 : 1.0f/sq11;
        int q0 = (int)qclamp(o[nd][0]*inv0, is0), q1 = (int)qclamp(o[nd][1]*inv0, is0);
        int q2 = (int)qclamp(o[nd][2]*inv1, is1), q3 = (int)qclamp(o[nd][3]*inv1, is1);
        int sh0 = (q0&0xFF) | ((q1&0xFF)<<8);
        int sh1 = (q2&0xFF) | ((q3&0xFF)<<8);
        int ot0 = __shfl_down_sync(0xffffffffu, sh0, 1);
        int ot1 = __shfl_down_sync(0xffffffffu, sh1, 1);
        if (!(tig & 1)){
            int wi = hh*16 + nd*2 + (tig>>1);
            g_qy[row0*256 + wi] = (sh0&0xFFFF) | (ot0<<16);
            g_qy[row1*256 + wi] = (sh1&0xFFFF) | (ot1<<16);
        }
    }
    if (tig == 0){
        g_sy[(hh*2  )*BTn + row0] = sq00;
        g_sy[(hh*2  )*BTn + row1] = sq10;
    }
    if (tig == 1){
        g_sy[(hh*2+1)*BTn + row0] = sq01;
        g_sy[(hh*2+1)*BTn + row1] = sq11;
    }
}

// ---------------- kernel 5: residual + stats + quant, single-pass ----------------
__global__ void final_kernel(const float* __restrict__ x, float* __restrict__ out, long long osz){
    __shared__ float red[8], redq[8], bc[2];
    int r = blockIdx.x, t = threadIdx.x;
    int c0 = t << 2;
    float4 xv = *(const float4*)(x + (size_t)r*Cn + c0);
    float4 pv = *(const float4*)(g_proj + (size_t)r*Cn + c0);
    float v0 = xv.x + pv.x, v1 = xv.y + pv.y, v2 = xv.z + pv.z, v3 = xv.w + pv.w;

    float sum = (v0 + v1) + (v2 + v3);
    float sq  = v0*v0 + v1*v1 + v2*v2 + v3*v3;
    sum = warp_sum(sum);
    sq  = warp_sum(sq);
    if ((t & 31) == 0){ red[t>>5] = sum; redq[t>>5] = sq; }
    __syncthreads();
    if (t < 32){
        float a = (t < 8) ? red[t]  : 0.f;
        float b = (t < 8) ? redq[t] : 0.f;
#pragma unroll
        for (int o=4;o;o>>=1){ a += __shfl_xor_sync(0xffffffffu, a, o); b += __shfl_xor_sync(0xffffffffu, b, o); }
        if (t == 0){
            float mu = a * (1.0f/Cn);
            float var = b * (1.0f/Cn) - mu*mu;
            bc[0] = mu;
            bc[1] = 1.0f / sqrtf(var + 1e-5f);
        }
    }
    __syncthreads();
    float mu = bc[0], rst = bc[1];

    *(float4*)(out + (size_t)r*Cn + c0) = make_float4(v0, v1, v2, v3);
    float m = max8(fmaxf(fmaxf(fabsf(v0),fabsf(v1)), fmaxf(fabsf(v2),fabsf(v3))));
    float s = fmaxf(m * (1.0f/QMAXF), 1e-8f);
    float inv = 1.0f / s;
    long long oq = (long long)BTn*Cn + (long long)r*Cn + c0;
    if (oq + 3 < osz)
        *(float4*)(out + oq) = make_float4(qclamp(v0,inv), qclamp(v1,inv), qclamp(v2,inv), qclamp(v3,inv));
    if ((t & 7) == 0){
        long long os = 2LL*BTn*Cn + (long long)r*32 + (t>>3);
        if (os < osz) out[os] = s;
    }
    if (t == 0){
        long long om = 2LL*BTn*Cn + 32LL*BTn + r;
        if (om < osz)        out[om]       = mu;
        if (om + BTn < osz)  out[om + BTn] = rst;
    }
}

// ---------------- launch ----------------
extern "C" void kernel_launch(void* const* d_in, const int* in_sizes, int n_in,
                              void* d_out, int out_size){
    const float* x     = (const float*)d_in[0];
    const int*   qx    = (const int*)  d_in[1];
    const float* sx    = (const float*)d_in[2];
    const float* meanp = (const float*)d_in[3];
    const float* rstdp = (const float*)d_in[4];
    const float* lnw   = (const float*)d_in[5];
    const float* w1    = (const float*)d_in[6];
    const float* w2    = (const float*)d_in[7];
    float* out = (float*)d_out;

    const int ATTN_SMEM = 2 * STAGEW * 4;   // 73728 bytes
    cudaFuncSetAttribute(attn_kernel, cudaFuncAttributeMaxDynamicSharedMemorySize, ATTN_SMEM);

    prepass<<<BTn + C3 + Cn, 256>>>(qx, sx, meanp, rstdp, lnw, w1, w2);
    gemm_imma<<<dim3(C3/128, BTn/128), 256>>>(0);
    qkv_convert<<<dim3(Tn/64, Hn, Bn), 256>>>();
    attn_kernel<<<dim3(Tn/128, Hn, Bn), 256, ATTN_SMEM>>>();
    gemm_imma<<<dim3(Cn/128, BTn/128), 256>>>(1);
    final_kernel<<<BTn, 256>>>(x, out, (long long)out_size);
}